// round 6
// baseline (speedup 1.0000x reference)
#include <cuda_runtime.h>
#include <cuda_bf16.h>
#include <cstdint>
#include <math.h>

#define NR 32768
#define NH 8
#define DD 128
#define HD 1024     // NH * DD
#define KC2 64      // split-K chunks for ktv (512 rows each)

// ---------------- scratch (static device memory; no allocations) ----------------
__device__ __nv_bfloat16 g_Wqh[DD * HD], g_Wql[DD * HD];   // [h*128+o][i] K-major
__device__ __nv_bfloat16 g_Wkh[DD * HD], g_Wkl[DD * HD];
__device__ __nv_bfloat16 g_Wvh[DD * HD], g_Wvl[DD * HD];
__device__ float g_Wvm[DD * DD];                           // mean_h Wv_w -> [d][i]
__device__ __nv_bfloat16 g_WfTh[DD * DD], g_WfTl[DD * DD]; // fused vss weight [o][i]
__device__ float g_cfuse[DD];
__device__ float g_bufA[(size_t)NR * HD];   // phi_qs (fp32, for combine denominator)
__device__ float g_bufB[(size_t)NR * HD];   // num
__device__ float g_att[(size_t)NR * DD];    // fused vss mean
__device__ __nv_bfloat16 g_Xsh[(size_t)NR * DD], g_Xsl[(size_t)NR * DD];  // xs split
__device__ __nv_bfloat16 g_Xqh[(size_t)NR * DD], g_Xql[(size_t)NR * DD];  // xq split
__device__ __nv_bfloat16 g_Kh[(size_t)NR * HD], g_Kl[(size_t)NR * HD];    // phi_ks split
__device__ __nv_bfloat16 g_Vh[(size_t)NR * HD], g_Vl[(size_t)NR * HD];    // v split
__device__ __nv_bfloat16 g_Qh[(size_t)NR * HD], g_Ql[(size_t)NR * HD];    // phi_qs split
__device__ __nv_bfloat16 g_ktvTh[NH * DD * DD], g_ktvTl[NH * DD * DD];    // [h][d][m]
__device__ float g_ksum[NH * DD];
__device__ float g_ktvp[(size_t)KC2 * NH * DD * DD];
__device__ float g_ksump[KC2 * NH * DD];

// ---------------- helpers ----------------
__device__ __forceinline__ uint32_t smem_u32(const void* p) {
    uint32_t a;
    asm("{ .reg .u64 t; cvta.to.shared.u64 t, %1; cvt.u32.u64 %0, t; }" : "=r"(a) : "l"(p));
    return a;
}
__device__ __forceinline__ uint32_t pack_bf2(__nv_bfloat16 a, __nv_bfloat16 b) {
    __nv_bfloat162 t; t.x = a; t.y = b;
    return *reinterpret_cast<uint32_t*>(&t);
}
__device__ __forceinline__ void split_bf(float x, __nv_bfloat16& h, __nv_bfloat16& l) {
    h = __float2bfloat16_rn(x);
    l = __float2bfloat16_rn(x - __bfloat162float(h));
}
#define SWZ(o)  ((o) ^ ((((o) >> 8) & 7) << 4))
#define SWZ1(o) ((o) ^ ((((o) >> 7) & 7) << 4))

__device__ __forceinline__ void ldsm_x4(uint32_t& r0, uint32_t& r1, uint32_t& r2,
                                        uint32_t& r3, uint32_t addr) {
    asm volatile("ldmatrix.sync.aligned.m8n8.x4.shared.b16 {%0,%1,%2,%3}, [%4];"
                 : "=r"(r0), "=r"(r1), "=r"(r2), "=r"(r3) : "r"(addr));
}
__device__ __forceinline__ void ldsm_x4_t(uint32_t& r0, uint32_t& r1, uint32_t& r2,
                                          uint32_t& r3, uint32_t addr) {
    asm volatile("ldmatrix.sync.aligned.m8n8.x4.trans.shared.b16 {%0,%1,%2,%3}, [%4];"
                 : "=r"(r0), "=r"(r1), "=r"(r2), "=r"(r3) : "r"(addr));
}
__device__ __forceinline__ void mma_bf16(float* c, uint32_t a0, uint32_t a1,
                                         uint32_t a2, uint32_t a3,
                                         uint32_t b0, uint32_t b1) {
    asm volatile("mma.sync.aligned.m16n8k16.row.col.f32.bf16.bf16.f32 "
                 "{%0,%1,%2,%3}, {%4,%5,%6,%7}, {%8,%9}, {%0,%1,%2,%3};"
                 : "+f"(c[0]), "+f"(c[1]), "+f"(c[2]), "+f"(c[3])
                 : "r"(a0), "r"(a1), "r"(a2), "r"(a3), "r"(b0), "r"(b1));
}
__device__ __forceinline__ void cp16(uint32_t saddr, const void* g) {
    asm volatile("cp.async.cg.shared.global [%0], [%1], 16;" :: "r"(saddr), "l"(g));
}
#define CP_COMMIT() asm volatile("cp.async.commit_group;" ::: "memory")
#define CP_WAIT0()  asm volatile("cp.async.wait_group 0;" ::: "memory")

// ---------------- input split: fp32 -> bf16 hi/lo ----------------
__global__ void split_x_kernel(const float* __restrict__ xs, const float* __restrict__ xq) {
    int idx = blockIdx.x * blockDim.x + threadIdx.x;
    if (idx >= NR * DD / 4) return;
    float4 s = *(const float4*)(xs + (size_t)idx * 4);
    float4 q = *(const float4*)(xq + (size_t)idx * 4);
    __nv_bfloat16 h0, h1, h2, h3, l0, l1, l2, l3;
    split_bf(s.x, h0, l0); split_bf(s.y, h1, l1);
    split_bf(s.z, h2, l2); split_bf(s.w, h3, l3);
    uint2 hv = { pack_bf2(h0, h1), pack_bf2(h2, h3) };
    uint2 lv = { pack_bf2(l0, l1), pack_bf2(l2, l3) };
    *(uint2*)(g_Xsh + (size_t)idx * 4) = hv;
    *(uint2*)(g_Xsl + (size_t)idx * 4) = lv;
    split_bf(q.x, h0, l0); split_bf(q.y, h1, l1);
    split_bf(q.z, h2, l2); split_bf(q.w, h3, l3);
    hv.x = pack_bf2(h0, h1); hv.y = pack_bf2(h2, h3);
    lv.x = pack_bf2(l0, l1); lv.y = pack_bf2(l2, l3);
    *(uint2*)(g_Xqh + (size_t)idx * 4) = hv;
    *(uint2*)(g_Xql + (size_t)idx * 4) = lv;
}

// ---------------- weight prep ----------------
__global__ void prep_kernel(const float* __restrict__ Wq,
                            const float* __restrict__ Wk,
                            const float* __restrict__ Wv) {
    int idx = blockIdx.x * blockDim.x + threadIdx.x;
    if (idx < 3 * 131072) {
        int which = idx / 131072;
        int e = idx % 131072;
        const float* src = (which == 0) ? Wq : (which == 1) ? Wk : Wv;
        __nv_bfloat16 h, l;
        split_bf(src[e], h, l);
        if (which == 0)      { g_Wqh[e] = h; g_Wql[e] = l; }
        else if (which == 1) { g_Wkh[e] = h; g_Wkl[e] = l; }
        else                 { g_Wvh[e] = h; g_Wvl[e] = l; }
    } else if (idx < 3 * 131072 + DD * DD) {
        int e = idx - 3 * 131072;
        int i = e & 127, d = e >> 7;
        float s = 0.f;
        #pragma unroll
        for (int h = 0; h < NH; h++) s += Wv[((size_t)(h * DD + d)) * DD + i];
        g_Wvm[d * DD + i] = s * 0.125f;
    }
}

__global__ void wfuse_kernel(const float* __restrict__ Wv_b,
                             const float* __restrict__ vmw,
                             const float* __restrict__ vmb) {
    int idx = blockIdx.x * blockDim.x + threadIdx.x;
    if (idx >= DD * DD) return;
    int o = idx & 127, i = idx >> 7;
    float acc = 0.f;
    for (int d = 0; d < DD; d++) acc += g_Wvm[d * DD + i] * vmw[o * DD + d];
    __nv_bfloat16 h, l;
    split_bf(acc, h, l);
    g_WfTh[o * DD + i] = h;
    g_WfTl[o * DD + i] = l;
    if (idx < DD) {
        float c = 0.f;
        for (int d = 0; d < DD; d++) {
            float bm = 0.f;
            #pragma unroll
            for (int hh = 0; hh < NH; hh++) bm += Wv_b[hh * DD + d];
            c += 0.125f * bm * vmw[idx * DD + d];
        }
        g_cfuse[idx] = c + vmb[idx];
    }
}

// ---------------- mma.sync bf16-pair GEMM: 4 warps, 64x64 warp tiles ----------------
#define S_AH 0
#define S_AL 16384
#define S_BH 32768
#define S_BL 49152
#define C_LD 132
#define MM_SMEM (128 * C_LD * 4)   // 67584 (covers the 65536 staging panels)

__global__ void __launch_bounds__(128, 2) mm_gemm(
    const __nv_bfloat16* __restrict__ Ah, const __nv_bfloat16* __restrict__ Al,
    int lda, int per_head,
    const __nv_bfloat16* __restrict__ Bh, const __nv_bfloat16* __restrict__ Bl,
    const float* __restrict__ bias, float* __restrict__ Cf, int ldc,
    const float* __restrict__ nsc,
    __nv_bfloat16* __restrict__ OutH, __nv_bfloat16* __restrict__ OutL) {
    extern __shared__ __align__(16) char smem[];
    const uint32_t sb = smem_u32(smem);
    float* Cs = (float*)smem;
    const int tid = threadIdx.x;
    const int lane = tid & 31, warp = tid >> 5;   // 4 warps
    const int wm = warp >> 1, wn = warp & 1;      // 64x64 warp tile
    const int row0 = blockIdx.x * 128;
    const int colb = blockIdx.y * 128;
    const int aoff = per_head ? colb : 0;
    Bh += (size_t)colb * DD;
    Bl += (size_t)colb * DD;

    float acc[4][8][4];
    #pragma unroll
    for (int i = 0; i < 4; i++)
        #pragma unroll
        for (int j = 0; j < 8; j++)
            #pragma unroll
            for (int e = 0; e < 4; e++) acc[i][j][e] = 0.f;

    const uint32_t a_row = wm * 64 + (lane & 15);
    const uint32_t a_cb  = (lane >> 4) * 16;
    const uint32_t b_row = wn * 64 + (lane & 7) + ((lane >> 4) & 1) * 8;
    const uint32_t b_cb  = ((lane >> 3) & 1) * 16;

    #pragma unroll
    for (int kc = 0; kc < 2; kc++) {
        // stage 4 panels of 128x64 bf16 via cp.async (16B granules, SW1 rows)
        #pragma unroll
        for (int it = 0; it < 8; it++) {
            int idx = it * 128 + tid;
            int r = idx >> 3, c8 = idx & 7;
            size_t ga = (size_t)(row0 + r) * lda + aoff + kc * 64 + c8 * 8;
            size_t gb = (size_t)r * DD + kc * 64 + c8 * 8;
            uint32_t off = SWZ1((uint32_t)(r * 128 + c8 * 16));
            cp16(sb + S_AH + off, Ah + ga);
            cp16(sb + S_AL + off, Al + ga);
            cp16(sb + S_BH + off, Bh + gb);
            cp16(sb + S_BL + off, Bl + gb);
        }
        CP_COMMIT();
        CP_WAIT0();
        __syncthreads();

        #pragma unroll
        for (int k = 0; k < 4; k++) {
            const uint32_t kb = k * 32;
            uint32_t ah[4][4], al[4][4], b[4][4];
            #pragma unroll
            for (int mi = 0; mi < 4; mi++) {
                uint32_t ra = SWZ1((a_row + mi * 16) * 128 + kb + a_cb);
                ldsm_x4(ah[mi][0], ah[mi][1], ah[mi][2], ah[mi][3], sb + S_AH + ra);
                ldsm_x4(al[mi][0], al[mi][1], al[mi][2], al[mi][3], sb + S_AL + ra);
            }
            #pragma unroll
            for (int nj = 0; nj < 4; nj++)
                ldsm_x4(b[nj][0], b[nj][1], b[nj][2], b[nj][3],
                        sb + S_BH + SWZ1((b_row + nj * 16) * 128 + kb + b_cb));
            #pragma unroll
            for (int mi = 0; mi < 4; mi++)
                #pragma unroll
                for (int nb = 0; nb < 8; nb++) {
                    mma_bf16(acc[mi][nb], ah[mi][0], ah[mi][1], ah[mi][2], ah[mi][3],
                             b[nb >> 1][(nb & 1) * 2], b[nb >> 1][(nb & 1) * 2 + 1]);
                    mma_bf16(acc[mi][nb], al[mi][0], al[mi][1], al[mi][2], al[mi][3],
                             b[nb >> 1][(nb & 1) * 2], b[nb >> 1][(nb & 1) * 2 + 1]);
                }
            #pragma unroll
            for (int nj = 0; nj < 4; nj++)
                ldsm_x4(b[nj][0], b[nj][1], b[nj][2], b[nj][3],
                        sb + S_BL + SWZ1((b_row + nj * 16) * 128 + kb + b_cb));
            #pragma unroll
            for (int mi = 0; mi < 4; mi++)
                #pragma unroll
                for (int nb = 0; nb < 8; nb++)
                    mma_bf16(acc[mi][nb], ah[mi][0], ah[mi][1], ah[mi][2], ah[mi][3],
                             b[nb >> 1][(nb & 1) * 2], b[nb >> 1][(nb & 1) * 2 + 1]);
        }
        __syncthreads();
    }

    const int rr = wm * 64 + (lane >> 2);
    const int cc = wn * 64 + 2 * (lane & 3);

    if (nsc) {
        // ---- phi epilogue: stage C in smem for full-row norm ----
        #pragma unroll
        for (int mi = 0; mi < 4; mi++)
            #pragma unroll
            for (int nb = 0; nb < 8; nb++) {
                int r = rr + mi * 16;
                int c = cc + (nb >> 1) * 16 + (nb & 1) * 8;
                *(float2*)&Cs[r * C_LD + c]       = *(float2*)&acc[mi][nb][0];
                *(float2*)&Cs[(r + 8) * C_LD + c] = *(float2*)&acc[mi][nb][2];
            }
        __syncthreads();
        float inv = 1.f / (fabsf(*nsc) + 1e-6f);
        const float4 bv = *(const float4*)(bias + colb + lane * 4);
        #pragma unroll 2
        for (int i = 0; i < 32; i++) {
            int r = warp * 32 + i;
            float4 x = *(float4*)&Cs[r * C_LD + lane * 4];
            float y0 = (fmaxf(x.x + bv.x, 0.f) + 1e-6f) * inv;
            float y1 = (fmaxf(x.y + bv.y, 0.f) + 1e-6f) * inv;
            float y2 = (fmaxf(x.z + bv.z, 0.f) + 1e-6f) * inv;
            float y3 = (fmaxf(x.w + bv.w, 0.f) + 1e-6f) * inv;
            float q0 = y0 * y0, q1 = y1 * y1, q2 = y2 * y2, q3 = y3 * y3;
            float s2 = q0 + q1 + q2 + q3;
            float s4 = q0 * q0 + q1 * q1 + q2 * q2 + q3 * q3;
            #pragma unroll
            for (int off = 16; off; off >>= 1) {
                s2 += __shfl_xor_sync(0xffffffffu, s2, off);
                s4 += __shfl_xor_sync(0xffffffffu, s4, off);
            }
            float rsc = sqrtf(s2) / (sqrtf(s4) + 1e-8f);
            float4 o;
            o.x = rsc * q0; o.y = rsc * q1; o.z = rsc * q2; o.w = rsc * q3;
            size_t base = (size_t)(row0 + r) * ldc + colb + lane * 4;
            if (Cf) *(float4*)(Cf + base) = o;
            if (OutH) {
                __nv_bfloat16 h0, h1, h2, h3, l0, l1, l2, l3;
                split_bf(o.x, h0, l0); split_bf(o.y, h1, l1);
                split_bf(o.z, h2, l2); split_bf(o.w, h3, l3);
                uint2 hv = { pack_bf2(h0, h1), pack_bf2(h2, h3) };
                uint2 lv = { pack_bf2(l0, l1), pack_bf2(l2, l3) };
                *(uint2*)(OutH + base) = hv;
                *(uint2*)(OutL + base) = lv;
            }
        }
    } else {
        // ---- direct register epilogue ----
        float bb0[8], bb1[8];
        #pragma unroll
        for (int nb = 0; nb < 8; nb++) {
            int c = cc + (nb >> 1) * 16 + (nb & 1) * 8;
            bb0[nb] = bias ? bias[colb + c] : 0.f;
            bb1[nb] = bias ? bias[colb + c + 1] : 0.f;
        }
        #pragma unroll
        for (int mi = 0; mi < 4; mi++)
            #pragma unroll
            for (int nb = 0; nb < 8; nb++) {
                int r = rr + mi * 16;
                int c = cc + (nb >> 1) * 16 + (nb & 1) * 8;
                float2 v0 = { acc[mi][nb][0] + bb0[nb], acc[mi][nb][1] + bb1[nb] };
                float2 v1 = { acc[mi][nb][2] + bb0[nb], acc[mi][nb][3] + bb1[nb] };
                size_t base0 = (size_t)(row0 + r) * ldc + colb + c;
                size_t base1 = (size_t)(row0 + r + 8) * ldc + colb + c;
                if (Cf) {
                    *(float2*)(Cf + base0) = v0;
                    *(float2*)(Cf + base1) = v1;
                }
                if (OutH) {
                    __nv_bfloat16 h0, h1, l0, l1;
                    split_bf(v0.x, h0, l0); split_bf(v0.y, h1, l1);
                    *(uint32_t*)(OutH + base0) = pack_bf2(h0, h1);
                    *(uint32_t*)(OutL + base0) = pack_bf2(l0, l1);
                    split_bf(v1.x, h0, l0); split_bf(v1.y, h1, l1);
                    *(uint32_t*)(OutH + base1) = pack_bf2(h0, h1);
                    *(uint32_t*)(OutL + base1) = pack_bf2(l0, l1);
                }
            }
    }
}

// ---------------- ktv via mma: C[m][d] = sum_n P[n][m] * V[n][d], per head ----------------
#define T_PH 0
#define T_PL 16384
#define T_VH 32768
#define T_VL 49152
#define KTV_SMEM 65536

__global__ void __launch_bounds__(256, 2) ktv_mma() {
    extern __shared__ __align__(16) char smem[];
    const uint32_t sb = smem_u32(smem);
    const int h = blockIdx.x;
    const int chunk = blockIdx.y;
    const int tid = threadIdx.x;
    const int lane = tid & 31, warp = tid >> 5;
    const int wm = warp >> 2, wn = warp & 3;
    const int n0 = chunk * (NR / KC2);

    float acc[4][4][4];
    #pragma unroll
    for (int i = 0; i < 4; i++)
        #pragma unroll
        for (int j = 0; j < 4; j++)
            #pragma unroll
            for (int e = 0; e < 4; e++) acc[i][j][e] = 0.f;
    float ks = 0.f;

    const uint32_t a_kr = (lane & 7) + ((lane >> 4) & 1) * 8;
    const uint32_t a_cl = wm * 64 + ((lane >> 3) & 1) * 8;
    const uint32_t b_kr = (lane & 7) + ((lane >> 3) & 1) * 8;
    const uint32_t b_cl = wn * 32 + ((lane >> 4) & 1) * 8;

    for (int s = 0; s < (NR / KC2) / 64; s++) {
        const int nb = n0 + s * 64;
        #pragma unroll 2
        for (int it = 0; it < 4; it++) {
            int idx = it * 256 + tid;
            int r = idx >> 4, c16 = idx & 15;
            size_t gb = (size_t)(nb + r) * HD + h * DD + c16 * 8;
            uint32_t off = SWZ((uint32_t)(r * 256 + c16 * 16));
            *(uint4*)(smem + T_PH + off) = *(const uint4*)(g_Kh + gb);
            *(uint4*)(smem + T_PL + off) = *(const uint4*)(g_Kl + gb);
            *(uint4*)(smem + T_VH + off) = *(const uint4*)(g_Vh + gb);
            *(uint4*)(smem + T_VL + off) = *(const uint4*)(g_Vl + gb);
        }
        __syncthreads();

        #pragma unroll
        for (int pass = 0; pass < 3; pass++) {
            const uint32_t Ap = sb + ((pass == 2) ? T_PL : T_PH);
            const uint32_t Bp = sb + ((pass == 1) ? T_VL : T_VH);
            #pragma unroll
            for (int kk = 0; kk < 4; kk++) {
                uint32_t a[4][4];
                #pragma unroll
                for (int mi = 0; mi < 4; mi++)
                    ldsm_x4_t(a[mi][0], a[mi][1], a[mi][2], a[mi][3],
                              Ap + SWZ((kk * 16 + a_kr) * 256 + (a_cl + mi * 16) * 2));
                uint32_t b[2][4];
                #pragma unroll
                for (int nj = 0; nj < 2; nj++)
                    ldsm_x4_t(b[nj][0], b[nj][1], b[nj][2], b[nj][3],
                              Bp + SWZ((kk * 16 + b_kr) * 256 + (b_cl + nj * 16) * 2));
                #pragma unroll
                for (int mi = 0; mi < 4; mi++)
                    #pragma unroll
                    for (int nbt = 0; nbt < 4; nbt++)
                        mma_bf16(acc[mi][nbt], a[mi][0], a[mi][1], a[mi][2], a[mi][3],
                                 b[nbt >> 1][(nbt & 1) * 2], b[nbt >> 1][(nbt & 1) * 2 + 1]);
            }
        }
        if (tid < 128) {
            #pragma unroll 4
            for (int r = 0; r < 64; r++) {
                uint32_t off = SWZ((uint32_t)(r * 256 + tid * 2));
                ks += __bfloat162float(*(const __nv_bfloat16*)(smem + T_PH + off))
                    + __bfloat162float(*(const __nv_bfloat16*)(smem + T_PL + off));
            }
        }
        __syncthreads();
    }

    float* out = g_ktvp + ((size_t)chunk * NH + h) * (DD * DD);
    const int rr = wm * 64 + (lane >> 2);
    const int cc = wn * 32 + 2 * (lane & 3);
    #pragma unroll
    for (int mi = 0; mi < 4; mi++)
        #pragma unroll
        for (int nbt = 0; nbt < 4; nbt++) {
            int r = rr + mi * 16;
            int c = cc + (nbt >> 1) * 16 + (nbt & 1) * 8;
            *(float2*)&out[r * DD + c]       = *(float2*)&acc[mi][nbt][0];
            *(float2*)&out[(r + 8) * DD + c] = *(float2*)&acc[mi][nbt][2];
        }
    if (tid < 128) g_ksump[(chunk * NH + h) * DD + tid] = ks;
}

// reduce partials; write ktv^T bf16-split for the numerator GEMM
__global__ void ktv_reduce_kernel() {
    int idx = blockIdx.x * blockDim.x + threadIdx.x;
    if (idx < NH * DD * DD) {
        float s = 0.f;
        #pragma unroll 8
        for (int c = 0; c < KC2; c++) s += g_ktvp[(size_t)c * NH * DD * DD + idx];
        int h = idx >> 14, m = (idx >> 7) & 127, d = idx & 127;
        __nv_bfloat16 hi, lo;
        split_bf(s, hi, lo);
        g_ktvTh[(h << 14) + (d << 7) + m] = hi;
        g_ktvTl[(h << 14) + (d << 7) + m] = lo;
    }
    if (idx < NH * DD) {
        float s = 0.f;
        #pragma unroll 8
        for (int c = 0; c < KC2; c++) s += g_ksump[c * NH * DD + idx];
        g_ksum[idx] = s;
    }
}

// ---------------- combine: one warp per row -> out[n][129] ----------------
__global__ void combine_kernel(float* __restrict__ out) {
    int n = blockIdx.x * 8 + (threadIdx.x >> 5);
    int lane = threadIdx.x & 31;
    const float* phiq = g_bufA + (size_t)n * HD;
    const float* num  = g_bufB + (size_t)n * HD;

    float dinv[NH];
    #pragma unroll
    for (int h = 0; h < NH; h++) {
        float4 q = *((const float4*)(phiq + h * DD) + lane);
        float4 s = *((const float4*)(g_ksum + h * DD) + lane);
        float d = q.x * s.x + q.y * s.y + q.z * s.z + q.w * s.w;
        #pragma unroll
        for (int off = 16; off; off >>= 1) d += __shfl_xor_sync(0xffffffffu, d, off);
        dinv[h] = 1.f / (d + 1e-6f);
    }

    float vals[4];
    float ssum = 0.f;
    #pragma unroll
    for (int c = 0; c < 4; c++) {
        int dcol = c * 32 + lane;
        float acc = 0.f;
        #pragma unroll
        for (int h = 0; h < NH; h++) acc += num[h * DD + dcol] * dinv[h];
        acc = acc * 0.125f + g_att[(size_t)n * DD + dcol];
        vals[c] = acc;
        ssum += acc * acc;
    }
    #pragma unroll
    for (int off = 16; off; off >>= 1) ssum += __shfl_xor_sync(0xffffffffu, ssum, off);
    float t = sqrtf(ssum + 1.0f);

    float* op = out + (size_t)n * 129;
    if (lane == 0) op[0] = t;
    #pragma unroll
    for (int c = 0; c < 4; c++) op[1 + c * 32 + lane] = vals[c];
}

// ---------------- launch ----------------
extern "C" void kernel_launch(void* const* d_in, const int* in_sizes, int n_in,
                              void* d_out, int out_size) {
    const float* xq   = (const float*)d_in[0];
    const float* xs   = (const float*)d_in[1];
    const float* Wq_w = (const float*)d_in[2];
    const float* Wq_b = (const float*)d_in[3];
    const float* Wk_w = (const float*)d_in[4];
    const float* Wk_b = (const float*)d_in[5];
    const float* Wv_w = (const float*)d_in[6];
    const float* Wv_b = (const float*)d_in[7];
    const float* vmw  = (const float*)d_in[8];
    const float* vmb  = (const float*)d_in[9];
    const float* nsc  = (const float*)d_in[10];
    float* out = (float*)d_out;

    float *pcfuse, *pbufA, *pbufB, *patt;
    __nv_bfloat16 *pWqh, *pWql, *pWkh, *pWkl, *pWvh, *pWvl, *pWfh, *pWfl, *pKTh, *pKTl;
    __nv_bfloat16 *pKh, *pKl, *pVh, *pVl, *pQh, *pQl, *pXsh, *pXsl, *pXqh, *pXql;
    cudaGetSymbolAddress((void**)&pcfuse, g_cfuse);
    cudaGetSymbolAddress((void**)&pbufA, g_bufA);
    cudaGetSymbolAddress((void**)&pbufB, g_bufB);
    cudaGetSymbolAddress((void**)&patt, g_att);
    cudaGetSymbolAddress((void**)&pWqh, g_Wqh);
    cudaGetSymbolAddress((void**)&pWql, g_Wql);
    cudaGetSymbolAddress((void**)&pWkh, g_Wkh);
    cudaGetSymbolAddress((void**)&pWkl, g_Wkl);
    cudaGetSymbolAddress((void**)&pWvh, g_Wvh);
    cudaGetSymbolAddress((void**)&pWvl, g_Wvl);
    cudaGetSymbolAddress((void**)&pWfh, g_WfTh);
    cudaGetSymbolAddress((void**)&pWfl, g_WfTl);
    cudaGetSymbolAddress((void**)&pKTh, g_ktvTh);
    cudaGetSymbolAddress((void**)&pKTl, g_ktvTl);
    cudaGetSymbolAddress((void**)&pKh, g_Kh);
    cudaGetSymbolAddress((void**)&pKl, g_Kl);
    cudaGetSymbolAddress((void**)&pVh, g_Vh);
    cudaGetSymbolAddress((void**)&pVl, g_Vl);
    cudaGetSymbolAddress((void**)&pQh, g_Qh);
    cudaGetSymbolAddress((void**)&pQl, g_Ql);
    cudaGetSymbolAddress((void**)&pXsh, g_Xsh);
    cudaGetSymbolAddress((void**)&pXsl, g_Xsl);
    cudaGetSymbolAddress((void**)&pXqh, g_Xqh);
    cudaGetSymbolAddress((void**)&pXql, g_Xql);

    cudaFuncSetAttribute(mm_gemm, cudaFuncAttributeMaxDynamicSharedMemorySize, MM_SMEM);
    cudaFuncSetAttribute(ktv_mma, cudaFuncAttributeMaxDynamicSharedMemorySize, KTV_SMEM);

    split_x_kernel<<<(NR * DD / 4 + 255) / 256, 256>>>(xs, xq);
    prep_kernel<<<(3 * 131072 + DD * DD + 255) / 256, 256>>>(Wq_w, Wk_w, Wv_w);
    wfuse_kernel<<<(DD * DD + 255) / 256, 256>>>(Wv_b, vmw, vmb);

    dim3 gproj(NR / 128, NH);
    // K projection + fused phi -> bf16 split
    mm_gemm<<<gproj, 128, MM_SMEM>>>(pXsh, pXsl, DD, 0, pWkh, pWkl, Wk_b,
                                     nullptr, HD, nsc, pKh, pKl);
    // V projection -> bf16 split (direct epilogue)
    mm_gemm<<<gproj, 128, MM_SMEM>>>(pXsh, pXsl, DD, 0, pWvh, pWvl, Wv_b,
                                     nullptr, HD, nullptr, pVh, pVl);
    // ktv + ksum on tensor cores
    ktv_mma<<<dim3(NH, KC2), 256, KTV_SMEM>>>();
    ktv_reduce_kernel<<<(NH * DD * DD + 255) / 256, 256>>>();
    // Q projection + fused phi -> fp32 bufA AND bf16 split
    mm_gemm<<<gproj, 128, MM_SMEM>>>(pXqh, pXql, DD, 0, pWqh, pWql, Wq_b,
                                     pbufA, HD, nsc, pQh, pQl);
    // numerator: per-head phi_qs @ ktv[h] -> bufB (direct epilogue)
    mm_gemm<<<gproj, 128, MM_SMEM>>>(pQh, pQl, HD, 1, pKTh, pKTl, nullptr,
                                     pbufB, HD, nullptr, nullptr, nullptr);
    // fused vss: xs @ WfuseT -> att (direct epilogue)
    mm_gemm<<<dim3(NR / 128, 1), 128, MM_SMEM>>>(pXsh, pXsl, DD, 0, pWfh, pWfl, pcfuse,
                                                 patt, DD, nullptr, nullptr, nullptr);
    // combine + time coordinate
    combine_kernel<<<NR / 8, 256>>>(out);
}

// round 7
// speedup vs baseline: 1.1152x; 1.1152x over previous
#include <cuda_runtime.h>
#include <cuda_bf16.h>
#include <cstdint>
#include <math.h>

#define NR 32768
#define NH 8
#define DD 128
#define HD 1024     // NH * DD
#define KC2 64      // split-K chunks for ktv (512 rows each)

// ---------------- scratch (static device memory; no allocations) ----------------
__device__ __nv_bfloat16 g_Wqh[DD * HD], g_Wql[DD * HD];   // [h*128+o][i] K-major
__device__ __nv_bfloat16 g_Wkh[DD * HD], g_Wkl[DD * HD];
__device__ __nv_bfloat16 g_Wvh[DD * HD], g_Wvl[DD * HD];
__device__ float g_Wvm[DD * DD];                           // mean_h Wv_w -> [d][i]
__device__ __nv_bfloat16 g_WfTh[DD * DD], g_WfTl[DD * DD]; // fused vss weight [o][i]
__device__ float g_cfuse[DD];
__device__ float g_att[(size_t)NR * DD];    // fused vss mean
__device__ __nv_bfloat16 g_Xsh[(size_t)NR * DD], g_Xsl[(size_t)NR * DD];  // xs split
__device__ __nv_bfloat16 g_Xqh[(size_t)NR * DD], g_Xql[(size_t)NR * DD];  // xq split
__device__ __nv_bfloat16 g_Kh[(size_t)NR * HD], g_Kl[(size_t)NR * HD];    // phi_ks split
__device__ __nv_bfloat16 g_Vh[(size_t)NR * HD], g_Vl[(size_t)NR * HD];    // v split
__device__ __nv_bfloat16 g_Qh[(size_t)NR * HD], g_Ql[(size_t)NR * HD];    // phi_qs * dinv
__device__ __nv_bfloat16 g_ktvTh[NH * DD * DD], g_ktvTl[NH * DD * DD];    // [h][d][m]
__device__ float g_ksum[NH * DD];
__device__ float g_ktvp[(size_t)KC2 * NH * DD * DD];
__device__ float g_ksump[KC2 * NH * DD];

// ---------------- helpers ----------------
__device__ __forceinline__ uint32_t smem_u32(const void* p) {
    uint32_t a;
    asm("{ .reg .u64 t; cvta.to.shared.u64 t, %1; cvt.u32.u64 %0, t; }" : "=r"(a) : "l"(p));
    return a;
}
__device__ __forceinline__ uint32_t pack_bf2(__nv_bfloat16 a, __nv_bfloat16 b) {
    __nv_bfloat162 t; t.x = a; t.y = b;
    return *reinterpret_cast<uint32_t*>(&t);
}
__device__ __forceinline__ void split_bf(float x, __nv_bfloat16& h, __nv_bfloat16& l) {
    h = __float2bfloat16_rn(x);
    l = __float2bfloat16_rn(x - __bfloat162float(h));
}
#define SWZ(o)  ((o) ^ ((((o) >> 8) & 7) << 4))
#define SWZ1(o) ((o) ^ ((((o) >> 7) & 7) << 4))

__device__ __forceinline__ void ldsm_x4(uint32_t& r0, uint32_t& r1, uint32_t& r2,
                                        uint32_t& r3, uint32_t addr) {
    asm volatile("ldmatrix.sync.aligned.m8n8.x4.shared.b16 {%0,%1,%2,%3}, [%4];"
                 : "=r"(r0), "=r"(r1), "=r"(r2), "=r"(r3) : "r"(addr));
}
__device__ __forceinline__ void ldsm_x4_t(uint32_t& r0, uint32_t& r1, uint32_t& r2,
                                          uint32_t& r3, uint32_t addr) {
    asm volatile("ldmatrix.sync.aligned.m8n8.x4.trans.shared.b16 {%0,%1,%2,%3}, [%4];"
                 : "=r"(r0), "=r"(r1), "=r"(r2), "=r"(r3) : "r"(addr));
}
__device__ __forceinline__ void mma_bf16(float* c, uint32_t a0, uint32_t a1,
                                         uint32_t a2, uint32_t a3,
                                         uint32_t b0, uint32_t b1) {
    asm volatile("mma.sync.aligned.m16n8k16.row.col.f32.bf16.bf16.f32 "
                 "{%0,%1,%2,%3}, {%4,%5,%6,%7}, {%8,%9}, {%0,%1,%2,%3};"
                 : "+f"(c[0]), "+f"(c[1]), "+f"(c[2]), "+f"(c[3])
                 : "r"(a0), "r"(a1), "r"(a2), "r"(a3), "r"(b0), "r"(b1));
}
__device__ __forceinline__ void cp16(uint32_t saddr, const void* g) {
    asm volatile("cp.async.cg.shared.global [%0], [%1], 16;" :: "r"(saddr), "l"(g));
}
#define CP_COMMIT() asm volatile("cp.async.commit_group;" ::: "memory")
#define CP_WAIT0()  asm volatile("cp.async.wait_group 0;" ::: "memory")

// ---------------- input split: fp32 -> bf16 hi/lo ----------------
__global__ void split_x_kernel(const float* __restrict__ xs, const float* __restrict__ xq) {
    int idx = blockIdx.x * blockDim.x + threadIdx.x;
    if (idx >= NR * DD / 4) return;
    float4 s = *(const float4*)(xs + (size_t)idx * 4);
    float4 q = *(const float4*)(xq + (size_t)idx * 4);
    __nv_bfloat16 h0, h1, h2, h3, l0, l1, l2, l3;
    split_bf(s.x, h0, l0); split_bf(s.y, h1, l1);
    split_bf(s.z, h2, l2); split_bf(s.w, h3, l3);
    uint2 hv = { pack_bf2(h0, h1), pack_bf2(h2, h3) };
    uint2 lv = { pack_bf2(l0, l1), pack_bf2(l2, l3) };
    *(uint2*)(g_Xsh + (size_t)idx * 4) = hv;
    *(uint2*)(g_Xsl + (size_t)idx * 4) = lv;
    split_bf(q.x, h0, l0); split_bf(q.y, h1, l1);
    split_bf(q.z, h2, l2); split_bf(q.w, h3, l3);
    hv.x = pack_bf2(h0, h1); hv.y = pack_bf2(h2, h3);
    lv.x = pack_bf2(l0, l1); lv.y = pack_bf2(l2, l3);
    *(uint2*)(g_Xqh + (size_t)idx * 4) = hv;
    *(uint2*)(g_Xql + (size_t)idx * 4) = lv;
}

// ---------------- weight prep ----------------
__global__ void prep_kernel(const float* __restrict__ Wq,
                            const float* __restrict__ Wk,
                            const float* __restrict__ Wv) {
    int idx = blockIdx.x * blockDim.x + threadIdx.x;
    if (idx < 3 * 131072) {
        int which = idx / 131072;
        int e = idx % 131072;
        const float* src = (which == 0) ? Wq : (which == 1) ? Wk : Wv;
        __nv_bfloat16 h, l;
        split_bf(src[e], h, l);
        if (which == 0)      { g_Wqh[e] = h; g_Wql[e] = l; }
        else if (which == 1) { g_Wkh[e] = h; g_Wkl[e] = l; }
        else                 { g_Wvh[e] = h; g_Wvl[e] = l; }
    } else if (idx < 3 * 131072 + DD * DD) {
        int e = idx - 3 * 131072;
        int i = e & 127, d = e >> 7;
        float s = 0.f;
        #pragma unroll
        for (int h = 0; h < NH; h++) s += Wv[((size_t)(h * DD + d)) * DD + i];
        g_Wvm[d * DD + i] = s * 0.125f;
    }
}

__global__ void wfuse_kernel(const float* __restrict__ Wv_b,
                             const float* __restrict__ vmw,
                             const float* __restrict__ vmb) {
    int idx = blockIdx.x * blockDim.x + threadIdx.x;
    if (idx >= DD * DD) return;
    int o = idx & 127, i = idx >> 7;
    float acc = 0.f;
    for (int d = 0; d < DD; d++) acc += g_Wvm[d * DD + i] * vmw[o * DD + d];
    __nv_bfloat16 h, l;
    split_bf(acc, h, l);
    g_WfTh[o * DD + i] = h;
    g_WfTl[o * DD + i] = l;
    if (idx < DD) {
        float c = 0.f;
        for (int d = 0; d < DD; d++) {
            float bm = 0.f;
            #pragma unroll
            for (int hh = 0; hh < NH; hh++) bm += Wv_b[hh * DD + d];
            c += 0.125f * bm * vmw[idx * DD + d];
        }
        g_cfuse[idx] = c + vmb[idx];
    }
}

// ---------------- mma.sync bf16-pair GEMM (R5 geometry: 8 warps, 64x32 tiles) ----------------
// modes: nsc -> phi epilogue (ksum!=0 adds dinv scaling); else direct epilogue
#define S_AH 0
#define S_AL 16384
#define S_BH 32768
#define S_BL 49152
#define C_LD 132
#define MM_SMEM (128 * C_LD * 4)   // 67584

__global__ void __launch_bounds__(256, 2) mm_gemm(
    const __nv_bfloat16* __restrict__ Ah, const __nv_bfloat16* __restrict__ Al,
    int lda,
    const __nv_bfloat16* __restrict__ Bh, const __nv_bfloat16* __restrict__ Bl,
    const float* __restrict__ bias, float* __restrict__ Cf, int ldc,
    const float* __restrict__ nsc, const float* __restrict__ ksum,
    __nv_bfloat16* __restrict__ OutH, __nv_bfloat16* __restrict__ OutL) {
    extern __shared__ __align__(16) char smem[];
    const uint32_t sb = smem_u32(smem);
    float* Cs = (float*)smem;
    const int tid = threadIdx.x;
    const int lane = tid & 31, warp = tid >> 5;
    const int wm = warp >> 2, wn = warp & 3;
    const int row0 = blockIdx.x * 128;
    const int colb = blockIdx.y * 128;
    Bh += (size_t)colb * DD;
    Bl += (size_t)colb * DD;

    float acc[4][4][4];
    #pragma unroll
    for (int i = 0; i < 4; i++)
        #pragma unroll
        for (int j = 0; j < 4; j++)
            #pragma unroll
            for (int e = 0; e < 4; e++) acc[i][j][e] = 0.f;

    const uint32_t a_row = wm * 64 + (lane & 15);
    const uint32_t a_cb  = (lane >> 4) * 16;
    const uint32_t b_row = wn * 32 + (lane & 7) + ((lane >> 4) & 1) * 8;
    const uint32_t b_cb  = ((lane >> 3) & 1) * 16;

    #pragma unroll
    for (int kc = 0; kc < 2; kc++) {
        #pragma unroll
        for (int it = 0; it < 4; it++) {
            int idx = it * 256 + tid;
            int r = idx >> 3, c8 = idx & 7;
            size_t ga = (size_t)(row0 + r) * lda + kc * 64 + c8 * 8;
            size_t gb = (size_t)r * DD + kc * 64 + c8 * 8;
            uint32_t off = SWZ1((uint32_t)(r * 128 + c8 * 16));
            cp16(sb + S_AH + off, Ah + ga);
            cp16(sb + S_AL + off, Al + ga);
            cp16(sb + S_BH + off, Bh + gb);
            cp16(sb + S_BL + off, Bl + gb);
        }
        CP_COMMIT();
        CP_WAIT0();
        __syncthreads();

        #pragma unroll
        for (int k = 0; k < 4; k++) {
            const uint32_t kb = k * 32;
            uint32_t ah[4][4], al[4][4], b[2][4];
            #pragma unroll
            for (int mi = 0; mi < 4; mi++) {
                uint32_t ra = SWZ1((a_row + mi * 16) * 128 + kb + a_cb);
                ldsm_x4(ah[mi][0], ah[mi][1], ah[mi][2], ah[mi][3], sb + S_AH + ra);
                ldsm_x4(al[mi][0], al[mi][1], al[mi][2], al[mi][3], sb + S_AL + ra);
            }
            #pragma unroll
            for (int nj = 0; nj < 2; nj++)
                ldsm_x4(b[nj][0], b[nj][1], b[nj][2], b[nj][3],
                        sb + S_BH + SWZ1((b_row + nj * 16) * 128 + kb + b_cb));
            #pragma unroll
            for (int mi = 0; mi < 4; mi++)
                #pragma unroll
                for (int nb = 0; nb < 4; nb++) {
                    mma_bf16(acc[mi][nb], ah[mi][0], ah[mi][1], ah[mi][2], ah[mi][3],
                             b[nb >> 1][(nb & 1) * 2], b[nb >> 1][(nb & 1) * 2 + 1]);
                    mma_bf16(acc[mi][nb], al[mi][0], al[mi][1], al[mi][2], al[mi][3],
                             b[nb >> 1][(nb & 1) * 2], b[nb >> 1][(nb & 1) * 2 + 1]);
                }
            #pragma unroll
            for (int nj = 0; nj < 2; nj++)
                ldsm_x4(b[nj][0], b[nj][1], b[nj][2], b[nj][3],
                        sb + S_BL + SWZ1((b_row + nj * 16) * 128 + kb + b_cb));
            #pragma unroll
            for (int mi = 0; mi < 4; mi++)
                #pragma unroll
                for (int nb = 0; nb < 4; nb++)
                    mma_bf16(acc[mi][nb], ah[mi][0], ah[mi][1], ah[mi][2], ah[mi][3],
                             b[nb >> 1][(nb & 1) * 2], b[nb >> 1][(nb & 1) * 2 + 1]);
        }
        __syncthreads();
    }

    const int rr = wm * 64 + (lane >> 2);
    const int cc = wn * 32 + 2 * (lane & 3);

    if (nsc) {
        // phi (+ optional dinv) epilogue: stage C in smem for full-row norm
        #pragma unroll
        for (int mi = 0; mi < 4; mi++)
            #pragma unroll
            for (int nb = 0; nb < 4; nb++) {
                int r = rr + mi * 16;
                int c = cc + (nb >> 1) * 16 + (nb & 1) * 8;
                *(float2*)&Cs[r * C_LD + c]       = *(float2*)&acc[mi][nb][0];
                *(float2*)&Cs[(r + 8) * C_LD + c] = *(float2*)&acc[mi][nb][2];
            }
        __syncthreads();
        float inv = 1.f / (fabsf(*nsc) + 1e-6f);
        const float4 bv = *(const float4*)(bias + colb + lane * 4);
        float4 ks4 = { 0.f, 0.f, 0.f, 0.f };
        if (ksum) ks4 = *(const float4*)(ksum + colb + lane * 4);
        #pragma unroll 2
        for (int i = 0; i < 16; i++) {
            int r = warp * 16 + i;
            float4 x = *(float4*)&Cs[r * C_LD + lane * 4];
            float y0 = (fmaxf(x.x + bv.x, 0.f) + 1e-6f) * inv;
            float y1 = (fmaxf(x.y + bv.y, 0.f) + 1e-6f) * inv;
            float y2 = (fmaxf(x.z + bv.z, 0.f) + 1e-6f) * inv;
            float y3 = (fmaxf(x.w + bv.w, 0.f) + 1e-6f) * inv;
            float q0 = y0 * y0, q1 = y1 * y1, q2 = y2 * y2, q3 = y3 * y3;
            float s2 = q0 + q1 + q2 + q3;
            float s4 = q0 * q0 + q1 * q1 + q2 * q2 + q3 * q3;
            #pragma unroll
            for (int off = 16; off; off >>= 1) {
                s2 += __shfl_xor_sync(0xffffffffu, s2, off);
                s4 += __shfl_xor_sync(0xffffffffu, s4, off);
            }
            float rsc = sqrtf(s2) / (sqrtf(s4) + 1e-8f);
            float4 o;
            o.x = rsc * q0; o.y = rsc * q1; o.z = rsc * q2; o.w = rsc * q3;
            if (ksum) {
                float dd = o.x * ks4.x + o.y * ks4.y + o.z * ks4.z + o.w * ks4.w;
                #pragma unroll
                for (int off = 16; off; off >>= 1) dd += __shfl_xor_sync(0xffffffffu, dd, off);
                float dinv = 1.f / (dd + 1e-6f);
                o.x *= dinv; o.y *= dinv; o.z *= dinv; o.w *= dinv;
            }
            size_t base = (size_t)(row0 + r) * ldc + colb + lane * 4;
            __nv_bfloat16 h0, h1, h2, h3, l0, l1, l2, l3;
            split_bf(o.x, h0, l0); split_bf(o.y, h1, l1);
            split_bf(o.z, h2, l2); split_bf(o.w, h3, l3);
            uint2 hv = { pack_bf2(h0, h1), pack_bf2(h2, h3) };
            uint2 lv = { pack_bf2(l0, l1), pack_bf2(l2, l3) };
            *(uint2*)(OutH + base) = hv;
            *(uint2*)(OutL + base) = lv;
        }
    } else {
        // direct register epilogue
        #pragma unroll
        for (int mi = 0; mi < 4; mi++)
            #pragma unroll
            for (int nb = 0; nb < 4; nb++) {
                int r = rr + mi * 16;
                int c = cc + (nb >> 1) * 16 + (nb & 1) * 8;
                float b0 = bias ? bias[colb + c] : 0.f;
                float b1 = bias ? bias[colb + c + 1] : 0.f;
                float2 v0 = { acc[mi][nb][0] + b0, acc[mi][nb][1] + b1 };
                float2 v1 = { acc[mi][nb][2] + b0, acc[mi][nb][3] + b1 };
                size_t base0 = (size_t)(row0 + r) * ldc + colb + c;
                size_t base1 = (size_t)(row0 + r + 8) * ldc + colb + c;
                if (Cf) {
                    *(float2*)(Cf + base0) = v0;
                    *(float2*)(Cf + base1) = v1;
                }
                if (OutH) {
                    __nv_bfloat16 h0, h1, l0, l1;
                    split_bf(v0.x, h0, l0); split_bf(v0.y, h1, l1);
                    *(uint32_t*)(OutH + base0) = pack_bf2(h0, h1);
                    *(uint32_t*)(OutL + base0) = pack_bf2(l0, l1);
                    split_bf(v1.x, h0, l0); split_bf(v1.y, h1, l1);
                    *(uint32_t*)(OutH + base1) = pack_bf2(h0, h1);
                    *(uint32_t*)(OutL + base1) = pack_bf2(l0, l1);
                }
            }
    }
}

// ---------------- fused numerator + combine: out[n][129] ----------------
// A = scaled phi_q (Qh/Ql) [NR][1024]; B = ktvT concat over heads; K = 1024.
__global__ void __launch_bounds__(256, 2) attn_out(const float* __restrict__ att,
                                                   float* __restrict__ out) {
    extern __shared__ __align__(16) char smem[];
    const uint32_t sb = smem_u32(smem);
    float* Cs = (float*)smem;
    const int tid = threadIdx.x;
    const int lane = tid & 31, warp = tid >> 5;
    const int wm = warp >> 2, wn = warp & 3;
    const int row0 = blockIdx.x * 128;

    float acc[4][4][4];
    #pragma unroll
    for (int i = 0; i < 4; i++)
        #pragma unroll
        for (int j = 0; j < 4; j++)
            #pragma unroll
            for (int e = 0; e < 4; e++) acc[i][j][e] = 0.f;

    const uint32_t a_row = wm * 64 + (lane & 15);
    const uint32_t a_cb  = (lane >> 4) * 16;
    const uint32_t b_row = wn * 32 + (lane & 7) + ((lane >> 4) & 1) * 8;
    const uint32_t b_cb  = ((lane >> 3) & 1) * 16;

    for (int kc = 0; kc < 16; kc++) {
        const int h = kc >> 1;
        const __nv_bfloat16* Bh = g_ktvTh + h * (DD * DD) + (kc & 1) * 64;
        const __nv_bfloat16* Bl = g_ktvTl + h * (DD * DD) + (kc & 1) * 64;
        #pragma unroll
        for (int it = 0; it < 4; it++) {
            int idx = it * 256 + tid;
            int r = idx >> 3, c8 = idx & 7;
            size_t ga = (size_t)(row0 + r) * HD + kc * 64 + c8 * 8;
            size_t gb = (size_t)r * DD + c8 * 8;
            uint32_t off = SWZ1((uint32_t)(r * 128 + c8 * 16));
            cp16(sb + S_AH + off, g_Qh + ga);
            cp16(sb + S_AL + off, g_Ql + ga);
            cp16(sb + S_BH + off, Bh + gb);
            cp16(sb + S_BL + off, Bl + gb);
        }
        CP_COMMIT();
        CP_WAIT0();
        __syncthreads();

        #pragma unroll
        for (int k = 0; k < 4; k++) {
            const uint32_t kb = k * 32;
            uint32_t ah[4][4], al[4][4], b[2][4];
            #pragma unroll
            for (int mi = 0; mi < 4; mi++) {
                uint32_t ra = SWZ1((a_row + mi * 16) * 128 + kb + a_cb);
                ldsm_x4(ah[mi][0], ah[mi][1], ah[mi][2], ah[mi][3], sb + S_AH + ra);
                ldsm_x4(al[mi][0], al[mi][1], al[mi][2], al[mi][3], sb + S_AL + ra);
            }
            #pragma unroll
            for (int nj = 0; nj < 2; nj++)
                ldsm_x4(b[nj][0], b[nj][1], b[nj][2], b[nj][3],
                        sb + S_BH + SWZ1((b_row + nj * 16) * 128 + kb + b_cb));
            #pragma unroll
            for (int mi = 0; mi < 4; mi++)
                #pragma unroll
                for (int nb = 0; nb < 4; nb++) {
                    mma_bf16(acc[mi][nb], ah[mi][0], ah[mi][1], ah[mi][2], ah[mi][3],
                             b[nb >> 1][(nb & 1) * 2], b[nb >> 1][(nb & 1) * 2 + 1]);
                    mma_bf16(acc[mi][nb], al[mi][0], al[mi][1], al[mi][2], al[mi][3],
                             b[nb >> 1][(nb & 1) * 2], b[nb >> 1][(nb & 1) * 2 + 1]);
                }
            #pragma unroll
            for (int nj = 0; nj < 2; nj++)
                ldsm_x4(b[nj][0], b[nj][1], b[nj][2], b[nj][3],
                        sb + S_BL + SWZ1((b_row + nj * 16) * 128 + kb + b_cb));
            #pragma unroll
            for (int mi = 0; mi < 4; mi++)
                #pragma unroll
                for (int nb = 0; nb < 4; nb++)
                    mma_bf16(acc[mi][nb], ah[mi][0], ah[mi][1], ah[mi][2], ah[mi][3],
                             b[nb >> 1][(nb & 1) * 2], b[nb >> 1][(nb & 1) * 2 + 1]);
        }
        __syncthreads();
    }

    // dump acc, then final epilogue: mean + att + time coordinate
    {
        const int rr = wm * 64 + (lane >> 2);
        const int cc = wn * 32 + 2 * (lane & 3);
        #pragma unroll
        for (int mi = 0; mi < 4; mi++)
            #pragma unroll
            for (int nb = 0; nb < 4; nb++) {
                int r = rr + mi * 16;
                int c = cc + (nb >> 1) * 16 + (nb & 1) * 8;
                *(float2*)&Cs[r * C_LD + c]       = *(float2*)&acc[mi][nb][0];
                *(float2*)&Cs[(r + 8) * C_LD + c] = *(float2*)&acc[mi][nb][2];
            }
    }
    __syncthreads();
    #pragma unroll 2
    for (int i = 0; i < 16; i++) {
        int r = warp * 16 + i;
        int n = row0 + r;
        float4 x = *(float4*)&Cs[r * C_LD + lane * 4];
        float4 a4 = *(const float4*)(att + (size_t)n * DD + lane * 4);
        float v0 = x.x * 0.125f + a4.x;
        float v1 = x.y * 0.125f + a4.y;
        float v2 = x.z * 0.125f + a4.z;
        float v3 = x.w * 0.125f + a4.w;
        float ssum = v0 * v0 + v1 * v1 + v2 * v2 + v3 * v3;
        #pragma unroll
        for (int off = 16; off; off >>= 1) ssum += __shfl_xor_sync(0xffffffffu, ssum, off);
        float t = sqrtf(ssum + 1.0f);
        float* op = out + (size_t)n * 129;
        if (lane == 0) op[0] = t;
        op[1 + lane * 4 + 0] = v0;
        op[1 + lane * 4 + 1] = v1;
        op[1 + lane * 4 + 2] = v2;
        op[1 + lane * 4 + 3] = v3;
    }
}

// ---------------- ktv via mma (unchanged) ----------------
#define T_PH 0
#define T_PL 16384
#define T_VH 32768
#define T_VL 49152
#define KTV_SMEM 65536

__global__ void __launch_bounds__(256, 2) ktv_mma() {
    extern __shared__ __align__(16) char smem[];
    const uint32_t sb = smem_u32(smem);
    const int h = blockIdx.x;
    const int chunk = blockIdx.y;
    const int tid = threadIdx.x;
    const int lane = tid & 31, warp = tid >> 5;
    const int wm = warp >> 2, wn = warp & 3;
    const int n0 = chunk * (NR / KC2);

    float acc[4][4][4];
    #pragma unroll
    for (int i = 0; i < 4; i++)
        #pragma unroll
        for (int j = 0; j < 4; j++)
            #pragma unroll
            for (int e = 0; e < 4; e++) acc[i][j][e] = 0.f;
    float ks = 0.f;

    const uint32_t a_kr = (lane & 7) + ((lane >> 4) & 1) * 8;
    const uint32_t a_cl = wm * 64 + ((lane >> 3) & 1) * 8;
    const uint32_t b_kr = (lane & 7) + ((lane >> 3) & 1) * 8;
    const uint32_t b_cl = wn * 32 + ((lane >> 4) & 1) * 8;

    for (int s = 0; s < (NR / KC2) / 64; s++) {
        const int nb = n0 + s * 64;
        #pragma unroll 2
        for (int it = 0; it < 4; it++) {
            int idx = it * 256 + tid;
            int r = idx >> 4, c16 = idx & 15;
            size_t gb = (size_t)(nb + r) * HD + h * DD + c16 * 8;
            uint32_t off = SWZ((uint32_t)(r * 256 + c16 * 16));
            *(uint4*)(smem + T_PH + off) = *(const uint4*)(g_Kh + gb);
            *(uint4*)(smem + T_PL + off) = *(const uint4*)(g_Kl + gb);
            *(uint4*)(smem + T_VH + off) = *(const uint4*)(g_Vh + gb);
            *(uint4*)(smem + T_VL + off) = *(const uint4*)(g_Vl + gb);
        }
        __syncthreads();

        #pragma unroll
        for (int pass = 0; pass < 3; pass++) {
            const uint32_t Ap = sb + ((pass == 2) ? T_PL : T_PH);
            const uint32_t Bp = sb + ((pass == 1) ? T_VL : T_VH);
            #pragma unroll
            for (int kk = 0; kk < 4; kk++) {
                uint32_t a[4][4];
                #pragma unroll
                for (int mi = 0; mi < 4; mi++)
                    ldsm_x4_t(a[mi][0], a[mi][1], a[mi][2], a[mi][3],
                              Ap + SWZ((kk * 16 + a_kr) * 256 + (a_cl + mi * 16) * 2));
                uint32_t b[2][4];
                #pragma unroll
                for (int nj = 0; nj < 2; nj++)
                    ldsm_x4_t(b[nj][0], b[nj][1], b[nj][2], b[nj][3],
                              Bp + SWZ((kk * 16 + b_kr) * 256 + (b_cl + nj * 16) * 2));
                #pragma unroll
                for (int mi = 0; mi < 4; mi++)
                    #pragma unroll
                    for (int nbt = 0; nbt < 4; nbt++)
                        mma_bf16(acc[mi][nbt], a[mi][0], a[mi][1], a[mi][2], a[mi][3],
                                 b[nbt >> 1][(nbt & 1) * 2], b[nbt >> 1][(nbt & 1) * 2 + 1]);
            }
        }
        if (tid < 128) {
            #pragma unroll 4
            for (int r = 0; r < 64; r++) {
                uint32_t off = SWZ((uint32_t)(r * 256 + tid * 2));
                ks += __bfloat162float(*(const __nv_bfloat16*)(smem + T_PH + off))
                    + __bfloat162float(*(const __nv_bfloat16*)(smem + T_PL + off));
            }
        }
        __syncthreads();
    }

    float* outp = g_ktvp + ((size_t)chunk * NH + h) * (DD * DD);
    const int rr = wm * 64 + (lane >> 2);
    const int cc = wn * 32 + 2 * (lane & 3);
    #pragma unroll
    for (int mi = 0; mi < 4; mi++)
        #pragma unroll
        for (int nbt = 0; nbt < 4; nbt++) {
            int r = rr + mi * 16;
            int c = cc + (nbt >> 1) * 16 + (nbt & 1) * 8;
            *(float2*)&outp[r * DD + c]       = *(float2*)&acc[mi][nbt][0];
            *(float2*)&outp[(r + 8) * DD + c] = *(float2*)&acc[mi][nbt][2];
        }
    if (tid < 128) g_ksump[(chunk * NH + h) * DD + tid] = ks;
}

__global__ void ktv_reduce_kernel() {
    int idx = blockIdx.x * blockDim.x + threadIdx.x;
    if (idx < NH * DD * DD) {
        float s = 0.f;
        #pragma unroll 8
        for (int c = 0; c < KC2; c++) s += g_ktvp[(size_t)c * NH * DD * DD + idx];
        int h = idx >> 14, m = (idx >> 7) & 127, d = idx & 127;
        __nv_bfloat16 hi, lo;
        split_bf(s, hi, lo);
        g_ktvTh[(h << 14) + (d << 7) + m] = hi;
        g_ktvTl[(h << 14) + (d << 7) + m] = lo;
    }
    if (idx < NH * DD) {
        float s = 0.f;
        #pragma unroll 8
        for (int c = 0; c < KC2; c++) s += g_ksump[c * NH * DD + idx];
        g_ksum[idx] = s;
    }
}

// ---------------- launch ----------------
extern "C" void kernel_launch(void* const* d_in, const int* in_sizes, int n_in,
                              void* d_out, int out_size) {
    const float* xq   = (const float*)d_in[0];
    const float* xs   = (const float*)d_in[1];
    const float* Wq_w = (const float*)d_in[2];
    const float* Wq_b = (const float*)d_in[3];
    const float* Wk_w = (const float*)d_in[4];
    const float* Wk_b = (const float*)d_in[5];
    const float* Wv_w = (const float*)d_in[6];
    const float* Wv_b = (const float*)d_in[7];
    const float* vmw  = (const float*)d_in[8];
    const float* vmb  = (const float*)d_in[9];
    const float* nsc  = (const float*)d_in[10];
    float* out = (float*)d_out;

    float *pcfuse, *patt, *pksum;
    __nv_bfloat16 *pWqh, *pWql, *pWkh, *pWkl, *pWvh, *pWvl, *pWfh, *pWfl;
    __nv_bfloat16 *pKh, *pKl, *pVh, *pVl, *pQh, *pQl, *pXsh, *pXsl, *pXqh, *pXql;
    cudaGetSymbolAddress((void**)&pcfuse, g_cfuse);
    cudaGetSymbolAddress((void**)&patt, g_att);
    cudaGetSymbolAddress((void**)&pksum, g_ksum);
    cudaGetSymbolAddress((void**)&pWqh, g_Wqh);
    cudaGetSymbolAddress((void**)&pWql, g_Wql);
    cudaGetSymbolAddress((void**)&pWkh, g_Wkh);
    cudaGetSymbolAddress((void**)&pWkl, g_Wkl);
    cudaGetSymbolAddress((void**)&pWvh, g_Wvh);
    cudaGetSymbolAddress((void**)&pWvl, g_Wvl);
    cudaGetSymbolAddress((void**)&pWfh, g_WfTh);
    cudaGetSymbolAddress((void**)&pWfl, g_WfTl);
    cudaGetSymbolAddress((void**)&pKh, g_Kh);
    cudaGetSymbolAddress((void**)&pKl, g_Kl);
    cudaGetSymbolAddress((void**)&pVh, g_Vh);
    cudaGetSymbolAddress((void**)&pVl, g_Vl);
    cudaGetSymbolAddress((void**)&pQh, g_Qh);
    cudaGetSymbolAddress((void**)&pQl, g_Ql);
    cudaGetSymbolAddress((void**)&pXsh, g_Xsh);
    cudaGetSymbolAddress((void**)&pXsl, g_Xsl);
    cudaGetSymbolAddress((void**)&pXqh, g_Xqh);
    cudaGetSymbolAddress((void**)&pXql, g_Xql);

    cudaFuncSetAttribute(mm_gemm, cudaFuncAttributeMaxDynamicSharedMemorySize, MM_SMEM);
    cudaFuncSetAttribute(attn_out, cudaFuncAttributeMaxDynamicSharedMemorySize, MM_SMEM);
    cudaFuncSetAttribute(ktv_mma, cudaFuncAttributeMaxDynamicSharedMemorySize, KTV_SMEM);

    split_x_kernel<<<(NR * DD / 4 + 255) / 256, 256>>>(xs, xq);
    prep_kernel<<<(3 * 131072 + DD * DD + 255) / 256, 256>>>(Wq_w, Wk_w, Wv_w);
    wfuse_kernel<<<(DD * DD + 255) / 256, 256>>>(Wv_b, vmw, vmb);

    dim3 gproj(NR / 128, NH);
    // K projection + fused phi -> Kh/Kl
    mm_gemm<<<gproj, 256, MM_SMEM>>>(pXsh, pXsl, DD, pWkh, pWkl, Wk_b,
                                     nullptr, HD, nsc, nullptr, pKh, pKl);
    // V projection -> Vh/Vl
    mm_gemm<<<gproj, 256, MM_SMEM>>>(pXsh, pXsl, DD, pWvh, pWvl, Wv_b,
                                     nullptr, HD, nullptr, nullptr, pVh, pVl);
    // ktv + ksum on tensor cores
    ktv_mma<<<dim3(NH, KC2), 256, KTV_SMEM>>>();
    ktv_reduce_kernel<<<(NH * DD * DD + 255) / 256, 256>>>();
    // fused vss: xs @ WfuseT -> att
    mm_gemm<<<dim3(NR / 128, 1), 256, MM_SMEM>>>(pXsh, pXsl, DD, pWfh, pWfl, pcfuse,
                                                 patt, DD, nullptr, nullptr, nullptr, nullptr);
    // Q projection + phi + dinv scaling -> Qh/Ql (pre-scaled by denominator)
    mm_gemm<<<gproj, 256, MM_SMEM>>>(pXqh, pXql, DD, pWqh, pWql, Wq_b,
                                     nullptr, HD, nsc, pksum, pQh, pQl);
    // fused numerator + combine + time coordinate -> out [NR][129]
    attn_out<<<NR / 128, 256, MM_SMEM>>>(patt, out);
}

// round 8
// speedup vs baseline: 1.4356x; 1.2874x over previous
#include <cuda_runtime.h>
#include <cuda_bf16.h>
#include <cuda_fp16.h>
#include <cstdint>
#include <math.h>

#define NR 32768
#define NH 8
#define DD 128
#define HD 1024     // NH * DD
#define KC2 64      // split-K chunks for ktv (512 rows each)
#define QSCALE 1048576.f          // 2^20 pre-scale for Q*dinv (fp16 range guard)
#define OSCALE (0.125f / 1048576.f)

// ---------------- scratch (static device memory; no allocations) ----------------
__device__ __nv_bfloat16 g_Wqh[DD * HD], g_Wql[DD * HD];   // bf16 pair, K-major
__device__ __nv_bfloat16 g_Wkh[DD * HD], g_Wkl[DD * HD];
__device__ __half        g_Wvf[DD * HD];                   // Wv fp16 single
__device__ float g_Wvm[DD * DD];
__device__ __nv_bfloat16 g_WfTh[DD * DD], g_WfTl[DD * DD]; // fused vss weight
__device__ float g_cfuse[DD];
__device__ float g_att[(size_t)NR * DD];
__device__ __nv_bfloat16 g_Xsh[(size_t)NR * DD], g_Xsl[(size_t)NR * DD];  // xs bf16 pair
__device__ __nv_bfloat16 g_Xqh[(size_t)NR * DD], g_Xql[(size_t)NR * DD];  // xq bf16 pair
__device__ __half g_Xfh[(size_t)NR * DD], g_Xfl[(size_t)NR * DD];         // xs fp16 pair
__device__ __half g_Kfh[(size_t)NR * HD], g_Kfl[(size_t)NR * HD];         // phi_ks fp16 pair
__device__ __half g_Vf[(size_t)NR * HD];                                  // v fp16 single
__device__ __half g_Qfh[(size_t)NR * HD], g_Qfl[(size_t)NR * HD];         // Q*dinv*2^20 pair
__device__ __half g_ktvTf[NH * DD * DD];                                  // [h][d][m] fp16
__device__ float g_ksum[NH * DD];
__device__ float g_ktvp[(size_t)KC2 * NH * DD * DD];
__device__ float g_ksump[KC2 * NH * DD];

// ---------------- helpers ----------------
__device__ __forceinline__ uint32_t smem_u32(const void* p) {
    uint32_t a;
    asm("{ .reg .u64 t; cvta.to.shared.u64 t, %1; cvt.u32.u64 %0, t; }" : "=r"(a) : "l"(p));
    return a;
}
__device__ __forceinline__ uint32_t pack_bf2(__nv_bfloat16 a, __nv_bfloat16 b) {
    __nv_bfloat162 t; t.x = a; t.y = b;
    return *reinterpret_cast<uint32_t*>(&t);
}
__device__ __forceinline__ uint32_t pack_h2(__half a, __half b) {
    __half2 t; t.x = a; t.y = b;
    return *reinterpret_cast<uint32_t*>(&t);
}
__device__ __forceinline__ void split_bf(float x, __nv_bfloat16& h, __nv_bfloat16& l) {
    h = __float2bfloat16_rn(x);
    l = __float2bfloat16_rn(x - __bfloat162float(h));
}
__device__ __forceinline__ void split_h(float x, __half& h, __half& l) {
    h = __float2half_rn(x);
    l = __float2half_rn(x - __half2float(h));
}
#define SWZ(o)  ((o) ^ ((((o) >> 8) & 7) << 4))
#define SWZ1(o) ((o) ^ ((((o) >> 7) & 7) << 4))

__device__ __forceinline__ void ldsm_x4(uint32_t& r0, uint32_t& r1, uint32_t& r2,
                                        uint32_t& r3, uint32_t addr) {
    asm volatile("ldmatrix.sync.aligned.m8n8.x4.shared.b16 {%0,%1,%2,%3}, [%4];"
                 : "=r"(r0), "=r"(r1), "=r"(r2), "=r"(r3) : "r"(addr));
}
__device__ __forceinline__ void ldsm_x4_t(uint32_t& r0, uint32_t& r1, uint32_t& r2,
                                          uint32_t& r3, uint32_t addr) {
    asm volatile("ldmatrix.sync.aligned.m8n8.x4.trans.shared.b16 {%0,%1,%2,%3}, [%4];"
                 : "=r"(r0), "=r"(r1), "=r"(r2), "=r"(r3) : "r"(addr));
}
__device__ __forceinline__ void mma_bf16(float* c, uint32_t a0, uint32_t a1,
                                         uint32_t a2, uint32_t a3,
                                         uint32_t b0, uint32_t b1) {
    asm volatile("mma.sync.aligned.m16n8k16.row.col.f32.bf16.bf16.f32 "
                 "{%0,%1,%2,%3}, {%4,%5,%6,%7}, {%8,%9}, {%0,%1,%2,%3};"
                 : "+f"(c[0]), "+f"(c[1]), "+f"(c[2]), "+f"(c[3])
                 : "r"(a0), "r"(a1), "r"(a2), "r"(a3), "r"(b0), "r"(b1));
}
__device__ __forceinline__ void mma_f16(float* c, uint32_t a0, uint32_t a1,
                                        uint32_t a2, uint32_t a3,
                                        uint32_t b0, uint32_t b1) {
    asm volatile("mma.sync.aligned.m16n8k16.row.col.f32.f16.f16.f32 "
                 "{%0,%1,%2,%3}, {%4,%5,%6,%7}, {%8,%9}, {%0,%1,%2,%3};"
                 : "+f"(c[0]), "+f"(c[1]), "+f"(c[2]), "+f"(c[3])
                 : "r"(a0), "r"(a1), "r"(a2), "r"(a3), "r"(b0), "r"(b1));
}
__device__ __forceinline__ void cp16(uint32_t saddr, const void* g) {
    asm volatile("cp.async.cg.shared.global [%0], [%1], 16;" :: "r"(saddr), "l"(g));
}
#define CP_COMMIT() asm volatile("cp.async.commit_group;" ::: "memory")
#define CP_WAIT0()  asm volatile("cp.async.wait_group 0;" ::: "memory")

// ---------------- input split ----------------
__global__ void split_x_kernel(const float* __restrict__ xs, const float* __restrict__ xq) {
    int idx = blockIdx.x * blockDim.x + threadIdx.x;
    if (idx >= NR * DD / 4) return;
    float4 s = *(const float4*)(xs + (size_t)idx * 4);
    float4 q = *(const float4*)(xq + (size_t)idx * 4);
    {   // xs bf16 pair
        __nv_bfloat16 h0, h1, h2, h3, l0, l1, l2, l3;
        split_bf(s.x, h0, l0); split_bf(s.y, h1, l1);
        split_bf(s.z, h2, l2); split_bf(s.w, h3, l3);
        uint2 hv = { pack_bf2(h0, h1), pack_bf2(h2, h3) };
        uint2 lv = { pack_bf2(l0, l1), pack_bf2(l2, l3) };
        *(uint2*)(g_Xsh + (size_t)idx * 4) = hv;
        *(uint2*)(g_Xsl + (size_t)idx * 4) = lv;
    }
    {   // xs fp16 pair (V-proj)
        __half h0, h1, h2, h3, l0, l1, l2, l3;
        split_h(s.x, h0, l0); split_h(s.y, h1, l1);
        split_h(s.z, h2, l2); split_h(s.w, h3, l3);
        uint2 hv = { pack_h2(h0, h1), pack_h2(h2, h3) };
        uint2 lv = { pack_h2(l0, l1), pack_h2(l2, l3) };
        *(uint2*)(g_Xfh + (size_t)idx * 4) = hv;
        *(uint2*)(g_Xfl + (size_t)idx * 4) = lv;
    }
    {   // xq bf16 pair
        __nv_bfloat16 h0, h1, h2, h3, l0, l1, l2, l3;
        split_bf(q.x, h0, l0); split_bf(q.y, h1, l1);
        split_bf(q.z, h2, l2); split_bf(q.w, h3, l3);
        uint2 hv = { pack_bf2(h0, h1), pack_bf2(h2, h3) };
        uint2 lv = { pack_bf2(l0, l1), pack_bf2(l2, l3) };
        *(uint2*)(g_Xqh + (size_t)idx * 4) = hv;
        *(uint2*)(g_Xql + (size_t)idx * 4) = lv;
    }
}

// ---------------- weight prep ----------------
__global__ void prep_kernel(const float* __restrict__ Wq,
                            const float* __restrict__ Wk,
                            const float* __restrict__ Wv) {
    int idx = blockIdx.x * blockDim.x + threadIdx.x;
    if (idx < 3 * 131072) {
        int which = idx / 131072;
        int e = idx % 131072;
        if (which == 0) {
            __nv_bfloat16 h, l; split_bf(Wq[e], h, l);
            g_Wqh[e] = h; g_Wql[e] = l;
        } else if (which == 1) {
            __nv_bfloat16 h, l; split_bf(Wk[e], h, l);
            g_Wkh[e] = h; g_Wkl[e] = l;
        } else {
            g_Wvf[e] = __float2half_rn(Wv[e]);
        }
    } else if (idx < 3 * 131072 + DD * DD) {
        int e = idx - 3 * 131072;
        int i = e & 127, d = e >> 7;
        float s = 0.f;
        #pragma unroll
        for (int h = 0; h < NH; h++) s += Wv[((size_t)(h * DD + d)) * DD + i];
        g_Wvm[d * DD + i] = s * 0.125f;
    }
}

__global__ void wfuse_kernel(const float* __restrict__ Wv_b,
                             const float* __restrict__ vmw,
                             const float* __restrict__ vmb) {
    int idx = blockIdx.x * blockDim.x + threadIdx.x;
    if (idx >= DD * DD) return;
    int o = idx & 127, i = idx >> 7;
    float acc = 0.f;
    for (int d = 0; d < DD; d++) acc += g_Wvm[d * DD + i] * vmw[o * DD + d];
    __nv_bfloat16 h, l;
    split_bf(acc, h, l);
    g_WfTh[o * DD + i] = h;
    g_WfTl[o * DD + i] = l;
    if (idx < DD) {
        float c = 0.f;
        for (int d = 0; d < DD; d++) {
            float bm = 0.f;
            #pragma unroll
            for (int hh = 0; hh < NH; hh++) bm += Wv_b[hh * DD + d];
            c += 0.125f * bm * vmw[idx * DD + d];
        }
        g_cfuse[idx] = c + vmb[idx];
    }
}

// ---------------- bf16 3-pass GEMM (K-proj / Q-proj / vss) ----------------
#define S_AH 0
#define S_AL 16384
#define S_BH 32768
#define S_BL 49152
#define C_LD 132
#define MM_SMEM (128 * C_LD * 4)   // 67584

__global__ void __launch_bounds__(256, 2) mm_gemm(
    const __nv_bfloat16* __restrict__ Ah, const __nv_bfloat16* __restrict__ Al,
    const __nv_bfloat16* __restrict__ Bh, const __nv_bfloat16* __restrict__ Bl,
    const float* __restrict__ bias, float* __restrict__ Cf, int ldc,
    const float* __restrict__ nsc, const float* __restrict__ ksum,
    __half* __restrict__ OutH, __half* __restrict__ OutL) {
    extern __shared__ __align__(16) char smem[];
    const uint32_t sb = smem_u32(smem);
    float* Cs = (float*)smem;
    const int tid = threadIdx.x;
    const int lane = tid & 31, warp = tid >> 5;
    const int wm = warp >> 2, wn = warp & 3;
    const int row0 = blockIdx.x * 128;
    const int colb = blockIdx.y * 128;
    Bh += (size_t)colb * DD;
    Bl += (size_t)colb * DD;

    float acc[4][4][4];
    #pragma unroll
    for (int i = 0; i < 4; i++)
        #pragma unroll
        for (int j = 0; j < 4; j++)
            #pragma unroll
            for (int e = 0; e < 4; e++) acc[i][j][e] = 0.f;

    const uint32_t a_row = wm * 64 + (lane & 15);
    const uint32_t a_cb  = (lane >> 4) * 16;
    const uint32_t b_row = wn * 32 + (lane & 7) + ((lane >> 4) & 1) * 8;
    const uint32_t b_cb  = ((lane >> 3) & 1) * 16;

    #pragma unroll
    for (int kc = 0; kc < 2; kc++) {
        #pragma unroll
        for (int it = 0; it < 4; it++) {
            int idx = it * 256 + tid;
            int r = idx >> 3, c8 = idx & 7;
            size_t ga = (size_t)(row0 + r) * DD + kc * 64 + c8 * 8;
            size_t gb = (size_t)r * DD + kc * 64 + c8 * 8;
            uint32_t off = SWZ1((uint32_t)(r * 128 + c8 * 16));
            cp16(sb + S_AH + off, Ah + ga);
            cp16(sb + S_AL + off, Al + ga);
            cp16(sb + S_BH + off, Bh + gb);
            cp16(sb + S_BL + off, Bl + gb);
        }
        CP_COMMIT();
        CP_WAIT0();
        __syncthreads();

        #pragma unroll
        for (int k = 0; k < 4; k++) {
            const uint32_t kb = k * 32;
            uint32_t ah[4][4], al[4][4], b[2][4];
            #pragma unroll
            for (int mi = 0; mi < 4; mi++) {
                uint32_t ra = SWZ1((a_row + mi * 16) * 128 + kb + a_cb);
                ldsm_x4(ah[mi][0], ah[mi][1], ah[mi][2], ah[mi][3], sb + S_AH + ra);
                ldsm_x4(al[mi][0], al[mi][1], al[mi][2], al[mi][3], sb + S_AL + ra);
            }
            #pragma unroll
            for (int nj = 0; nj < 2; nj++)
                ldsm_x4(b[nj][0], b[nj][1], b[nj][2], b[nj][3],
                        sb + S_BH + SWZ1((b_row + nj * 16) * 128 + kb + b_cb));
            #pragma unroll
            for (int mi = 0; mi < 4; mi++)
                #pragma unroll
                for (int nb = 0; nb < 4; nb++) {
                    mma_bf16(acc[mi][nb], ah[mi][0], ah[mi][1], ah[mi][2], ah[mi][3],
                             b[nb >> 1][(nb & 1) * 2], b[nb >> 1][(nb & 1) * 2 + 1]);
                    mma_bf16(acc[mi][nb], al[mi][0], al[mi][1], al[mi][2], al[mi][3],
                             b[nb >> 1][(nb & 1) * 2], b[nb >> 1][(nb & 1) * 2 + 1]);
                }
            #pragma unroll
            for (int nj = 0; nj < 2; nj++)
                ldsm_x4(b[nj][0], b[nj][1], b[nj][2], b[nj][3],
                        sb + S_BL + SWZ1((b_row + nj * 16) * 128 + kb + b_cb));
            #pragma unroll
            for (int mi = 0; mi < 4; mi++)
                #pragma unroll
                for (int nb = 0; nb < 4; nb++)
                    mma_bf16(acc[mi][nb], ah[mi][0], ah[mi][1], ah[mi][2], ah[mi][3],
                             b[nb >> 1][(nb & 1) * 2], b[nb >> 1][(nb & 1) * 2 + 1]);
        }
        __syncthreads();
    }

    const int rr = wm * 64 + (lane >> 2);
    const int cc = wn * 32 + 2 * (lane & 3);

    if (nsc) {
        // phi (+ optional dinv*QSCALE) epilogue -> fp16 pair
        #pragma unroll
        for (int mi = 0; mi < 4; mi++)
            #pragma unroll
            for (int nb = 0; nb < 4; nb++) {
                int r = rr + mi * 16;
                int c = cc + (nb >> 1) * 16 + (nb & 1) * 8;
                *(float2*)&Cs[r * C_LD + c]       = *(float2*)&acc[mi][nb][0];
                *(float2*)&Cs[(r + 8) * C_LD + c] = *(float2*)&acc[mi][nb][2];
            }
        __syncthreads();
        float inv = 1.f / (fabsf(*nsc) + 1e-6f);
        const float4 bv = *(const float4*)(bias + colb + lane * 4);
        float4 ks4 = { 0.f, 0.f, 0.f, 0.f };
        if (ksum) ks4 = *(const float4*)(ksum + colb + lane * 4);
        #pragma unroll 2
        for (int i = 0; i < 16; i++) {
            int r = warp * 16 + i;
            float4 x = *(float4*)&Cs[r * C_LD + lane * 4];
            float y0 = (fmaxf(x.x + bv.x, 0.f) + 1e-6f) * inv;
            float y1 = (fmaxf(x.y + bv.y, 0.f) + 1e-6f) * inv;
            float y2 = (fmaxf(x.z + bv.z, 0.f) + 1e-6f) * inv;
            float y3 = (fmaxf(x.w + bv.w, 0.f) + 1e-6f) * inv;
            float q0 = y0 * y0, q1 = y1 * y1, q2 = y2 * y2, q3 = y3 * y3;
            float s2 = q0 + q1 + q2 + q3;
            float s4 = q0 * q0 + q1 * q1 + q2 * q2 + q3 * q3;
            #pragma unroll
            for (int off = 16; off; off >>= 1) {
                s2 += __shfl_xor_sync(0xffffffffu, s2, off);
                s4 += __shfl_xor_sync(0xffffffffu, s4, off);
            }
            float rsc = sqrtf(s2) / (sqrtf(s4) + 1e-8f);
            float4 o;
            o.x = rsc * q0; o.y = rsc * q1; o.z = rsc * q2; o.w = rsc * q3;
            if (ksum) {
                float dd = o.x * ks4.x + o.y * ks4.y + o.z * ks4.z + o.w * ks4.w;
                #pragma unroll
                for (int off = 16; off; off >>= 1) dd += __shfl_xor_sync(0xffffffffu, dd, off);
                float sc = QSCALE / (dd + 1e-6f);
                o.x *= sc; o.y *= sc; o.z *= sc; o.w *= sc;
            }
            size_t base = (size_t)(row0 + r) * ldc + colb + lane * 4;
            __half h0, h1, h2, h3, l0, l1, l2, l3;
            split_h(o.x, h0, l0); split_h(o.y, h1, l1);
            split_h(o.z, h2, l2); split_h(o.w, h3, l3);
            uint2 hv = { pack_h2(h0, h1), pack_h2(h2, h3) };
            uint2 lv = { pack_h2(l0, l1), pack_h2(l2, l3) };
            *(uint2*)(OutH + base) = hv;
            *(uint2*)(OutL + base) = lv;
        }
    } else {
        // direct fp32 epilogue (vss)
        #pragma unroll
        for (int mi = 0; mi < 4; mi++)
            #pragma unroll
            for (int nb = 0; nb < 4; nb++) {
                int r = rr + mi * 16;
                int c = cc + (nb >> 1) * 16 + (nb & 1) * 8;
                float b0 = bias ? bias[colb + c] : 0.f;
                float b1 = bias ? bias[colb + c + 1] : 0.f;
                float2 v0 = { acc[mi][nb][0] + b0, acc[mi][nb][1] + b1 };
                float2 v1 = { acc[mi][nb][2] + b0, acc[mi][nb][3] + b1 };
                *(float2*)(Cf + (size_t)(row0 + r) * ldc + colb + c) = v0;
                *(float2*)(Cf + (size_t)(row0 + r + 8) * ldc + colb + c) = v1;
            }
    }
}

// ---------------- fp16 2-pass V projection ----------------
#define F_AH 0
#define F_AL 16384
#define F_B  32768
#define VP_SMEM 49152

__global__ void __launch_bounds__(256, 2) vproj_f16(const float* __restrict__ bias) {
    extern __shared__ __align__(16) char smem[];
    const uint32_t sb = smem_u32(smem);
    const int tid = threadIdx.x;
    const int lane = tid & 31, warp = tid >> 5;
    const int wm = warp >> 2, wn = warp & 3;
    const int row0 = blockIdx.x * 128;
    const int colb = blockIdx.y * 128;
    const __half* B = g_Wvf + (size_t)colb * DD;

    float acc[4][4][4];
    #pragma unroll
    for (int i = 0; i < 4; i++)
        #pragma unroll
        for (int j = 0; j < 4; j++)
            #pragma unroll
            for (int e = 0; e < 4; e++) acc[i][j][e] = 0.f;

    const uint32_t a_row = wm * 64 + (lane & 15);
    const uint32_t a_cb  = (lane >> 4) * 16;
    const uint32_t b_row = wn * 32 + (lane & 7) + ((lane >> 4) & 1) * 8;
    const uint32_t b_cb  = ((lane >> 3) & 1) * 16;

    #pragma unroll
    for (int kc = 0; kc < 2; kc++) {
        #pragma unroll
        for (int it = 0; it < 4; it++) {
            int idx = it * 256 + tid;
            int r = idx >> 3, c8 = idx & 7;
            size_t ga = (size_t)(row0 + r) * DD + kc * 64 + c8 * 8;
            size_t gb = (size_t)r * DD + kc * 64 + c8 * 8;
            uint32_t off = SWZ1((uint32_t)(r * 128 + c8 * 16));
            cp16(sb + F_AH + off, g_Xfh + ga);
            cp16(sb + F_AL + off, g_Xfl + ga);
            cp16(sb + F_B + off, B + gb);
        }
        CP_COMMIT();
        CP_WAIT0();
        __syncthreads();

        #pragma unroll
        for (int k = 0; k < 4; k++) {
            const uint32_t kb = k * 32;
            uint32_t a[4][4], b[2][4];
            #pragma unroll
            for (int nj = 0; nj < 2; nj++)
                ldsm_x4(b[nj][0], b[nj][1], b[nj][2], b[nj][3],
                        sb + F_B + SWZ1((b_row + nj * 16) * 128 + kb + b_cb));
            #pragma unroll
            for (int mi = 0; mi < 4; mi++)
                ldsm_x4(a[mi][0], a[mi][1], a[mi][2], a[mi][3],
                        sb + F_AH + SWZ1((a_row + mi * 16) * 128 + kb + a_cb));
            #pragma unroll
            for (int mi = 0; mi < 4; mi++)
                #pragma unroll
                for (int nb = 0; nb < 4; nb++)
                    mma_f16(acc[mi][nb], a[mi][0], a[mi][1], a[mi][2], a[mi][3],
                            b[nb >> 1][(nb & 1) * 2], b[nb >> 1][(nb & 1) * 2 + 1]);
            #pragma unroll
            for (int mi = 0; mi < 4; mi++)
                ldsm_x4(a[mi][0], a[mi][1], a[mi][2], a[mi][3],
                        sb + F_AL + SWZ1((a_row + mi * 16) * 128 + kb + a_cb));
            #pragma unroll
            for (int mi = 0; mi < 4; mi++)
                #pragma unroll
                for (int nb = 0; nb < 4; nb++)
                    mma_f16(acc[mi][nb], a[mi][0], a[mi][1], a[mi][2], a[mi][3],
                            b[nb >> 1][(nb & 1) * 2], b[nb >> 1][(nb & 1) * 2 + 1]);
        }
        __syncthreads();
    }

    const int rr = wm * 64 + (lane >> 2);
    const int cc = wn * 32 + 2 * (lane & 3);
    #pragma unroll
    for (int mi = 0; mi < 4; mi++)
        #pragma unroll
        for (int nb = 0; nb < 4; nb++) {
            int r = rr + mi * 16;
            int c = cc + (nb >> 1) * 16 + (nb & 1) * 8;
            float b0 = bias[colb + c];
            float b1 = bias[colb + c + 1];
            *(uint32_t*)(g_Vf + (size_t)(row0 + r) * HD + colb + c) =
                pack_h2(__float2half_rn(acc[mi][nb][0] + b0),
                        __float2half_rn(acc[mi][nb][1] + b1));
            *(uint32_t*)(g_Vf + (size_t)(row0 + r + 8) * HD + colb + c) =
                pack_h2(__float2half_rn(acc[mi][nb][2] + b0),
                        __float2half_rn(acc[mi][nb][3] + b1));
        }
}

// ---------------- ktv via fp16 2-pass mma ----------------
#define T_PH 0
#define T_PL 16384
#define T_VH 32768
#define KTV_SMEM 49152

__global__ void __launch_bounds__(256, 2) ktv_mma() {
    extern __shared__ __align__(16) char smem[];
    const uint32_t sb = smem_u32(smem);
    const int h = blockIdx.x;
    const int chunk = blockIdx.y;
    const int tid = threadIdx.x;
    const int lane = tid & 31, warp = tid >> 5;
    const int wm = warp >> 2, wn = warp & 3;
    const int n0 = chunk * (NR / KC2);

    float acc[4][4][4];
    #pragma unroll
    for (int i = 0; i < 4; i++)
        #pragma unroll
        for (int j = 0; j < 4; j++)
            #pragma unroll
            for (int e = 0; e < 4; e++) acc[i][j][e] = 0.f;
    float ks = 0.f;

    const uint32_t a_kr = (lane & 7) + ((lane >> 4) & 1) * 8;
    const uint32_t a_cl = wm * 64 + ((lane >> 3) & 1) * 8;
    const uint32_t b_kr = (lane & 7) + ((lane >> 3) & 1) * 8;
    const uint32_t b_cl = wn * 32 + ((lane >> 4) & 1) * 8;

    for (int s = 0; s < (NR / KC2) / 64; s++) {
        const int nb = n0 + s * 64;
        #pragma unroll 2
        for (int it = 0; it < 4; it++) {
            int idx = it * 256 + tid;
            int r = idx >> 4, c16 = idx & 15;
            size_t gb = (size_t)(nb + r) * HD + h * DD + c16 * 8;
            uint32_t off = SWZ((uint32_t)(r * 256 + c16 * 16));
            *(uint4*)(smem + T_PH + off) = *(const uint4*)(g_Kfh + gb);
            *(uint4*)(smem + T_PL + off) = *(const uint4*)(g_Kfl + gb);
            *(uint4*)(smem + T_VH + off) = *(const uint4*)(g_Vf + gb);
        }
        __syncthreads();

        #pragma unroll
        for (int kk = 0; kk < 4; kk++) {
            uint32_t a[4][4], b[2][4];
            #pragma unroll
            for (int nj = 0; nj < 2; nj++)
                ldsm_x4_t(b[nj][0], b[nj][1], b[nj][2], b[nj][3],
                          sb + T_VH + SWZ((kk * 16 + b_kr) * 256 + (b_cl + nj * 16) * 2));
            #pragma unroll
            for (int mi = 0; mi < 4; mi++)
                ldsm_x4_t(a[mi][0], a[mi][1], a[mi][2], a[mi][3],
                          sb + T_PH + SWZ((kk * 16 + a_kr) * 256 + (a_cl + mi * 16) * 2));
            #pragma unroll
            for (int mi = 0; mi < 4; mi++)
                #pragma unroll
                for (int nbt = 0; nbt < 4; nbt++)
                    mma_f16(acc[mi][nbt], a[mi][0], a[mi][1], a[mi][2], a[mi][3],
                            b[nbt >> 1][(nbt & 1) * 2], b[nbt >> 1][(nbt & 1) * 2 + 1]);
            #pragma unroll
            for (int mi = 0; mi < 4; mi++)
                ldsm_x4_t(a[mi][0], a[mi][1], a[mi][2], a[mi][3],
                          sb + T_PL + SWZ((kk * 16 + a_kr) * 256 + (a_cl + mi * 16) * 2));
            #pragma unroll
            for (int mi = 0; mi < 4; mi++)
                #pragma unroll
                for (int nbt = 0; nbt < 4; nbt++)
                    mma_f16(acc[mi][nbt], a[mi][0], a[mi][1], a[mi][2], a[mi][3],
                            b[nbt >> 1][(nbt & 1) * 2], b[nbt >> 1][(nbt & 1) * 2 + 1]);
        }
        if (tid < 128) {
            #pragma unroll 4
            for (int r = 0; r < 64; r++) {
                uint32_t off = SWZ((uint32_t)(r * 256 + tid * 2));
                ks += __half2float(*(const __half*)(smem + T_PH + off))
                    + __half2float(*(const __half*)(smem + T_PL + off));
            }
        }
        __syncthreads();
    }

    float* outp = g_ktvp + ((size_t)chunk * NH + h) * (DD * DD);
    const int rr = wm * 64 + (lane >> 2);
    const int cc = wn * 32 + 2 * (lane & 3);
    #pragma unroll
    for (int mi = 0; mi < 4; mi++)
        #pragma unroll
        for (int nbt = 0; nbt < 4; nbt++) {
            int r = rr + mi * 16;
            int c = cc + (nbt >> 1) * 16 + (nbt & 1) * 8;
            *(float2*)&outp[r * DD + c]       = *(float2*)&acc[mi][nbt][0];
            *(float2*)&outp[(r + 8) * DD + c] = *(float2*)&acc[mi][nbt][2];
        }
    if (tid < 128) g_ksump[(chunk * NH + h) * DD + tid] = ks;
}

__global__ void ktv_reduce_kernel() {
    int idx = blockIdx.x * blockDim.x + threadIdx.x;
    if (idx < NH * DD * DD) {
        float s = 0.f;
        #pragma unroll 8
        for (int c = 0; c < KC2; c++) s += g_ktvp[(size_t)c * NH * DD * DD + idx];
        int h = idx >> 14, m = (idx >> 7) & 127, d = idx & 127;
        g_ktvTf[(h << 14) + (d << 7) + m] = __float2half_rn(s);
    }
    if (idx < NH * DD) {
        float s = 0.f;
        #pragma unroll 8
        for (int c = 0; c < KC2; c++) s += g_ksump[c * NH * DD + idx];
        g_ksum[idx] = s;
    }
}

// ---------------- fused numerator + combine (fp16 2-pass): out[n][129] ----------------
__global__ void __launch_bounds__(256, 2) attn_out(const float* __restrict__ att,
                                                   float* __restrict__ out) {
    extern __shared__ __align__(16) char smem[];
    const uint32_t sb = smem_u32(smem);
    float* Cs = (float*)smem;
    const int tid = threadIdx.x;
    const int lane = tid & 31, warp = tid >> 5;
    const int wm = warp >> 2, wn = warp & 3;
    const int row0 = blockIdx.x * 128;

    float acc[4][4][4];
    #pragma unroll
    for (int i = 0; i < 4; i++)
        #pragma unroll
        for (int j = 0; j < 4; j++)
            #pragma unroll
            for (int e = 0; e < 4; e++) acc[i][j][e] = 0.f;

    const uint32_t a_row = wm * 64 + (lane & 15);
    const uint32_t a_cb  = (lane >> 4) * 16;
    const uint32_t b_row = wn * 32 + (lane & 7) + ((lane >> 4) & 1) * 8;
    const uint32_t b_cb  = ((lane >> 3) & 1) * 16;

    for (int kc = 0; kc < 16; kc++) {
        const int h = kc >> 1;
        const __half* B = g_ktvTf + h * (DD * DD) + (kc & 1) * 64;
        #pragma unroll
        for (int it = 0; it < 4; it++) {
            int idx = it * 256 + tid;
            int r = idx >> 3, c8 = idx & 7;
            size_t ga = (size_t)(row0 + r) * HD + kc * 64 + c8 * 8;
            size_t gb = (size_t)r * DD + c8 * 8;
            uint32_t off = SWZ1((uint32_t)(r * 128 + c8 * 16));
            cp16(sb + F_AH + off, g_Qfh + ga);
            cp16(sb + F_AL + off, g_Qfl + ga);
            cp16(sb + F_B + off, B + gb);
        }
        CP_COMMIT();
        CP_WAIT0();
        __syncthreads();

        #pragma unroll
        for (int k = 0; k < 4; k++) {
            const uint32_t kb = k * 32;
            uint32_t a[4][4], b[2][4];
            #pragma unroll
            for (int nj = 0; nj < 2; nj++)
                ldsm_x4(b[nj][0], b[nj][1], b[nj][2], b[nj][3],
                        sb + F_B + SWZ1((b_row + nj * 16) * 128 + kb + b_cb));
            #pragma unroll
            for (int mi = 0; mi < 4; mi++)
                ldsm_x4(a[mi][0], a[mi][1], a[mi][2], a[mi][3],
                        sb + F_AH + SWZ1((a_row + mi * 16) * 128 + kb + a_cb));
            #pragma unroll
            for (int mi = 0; mi < 4; mi++)
                #pragma unroll
                for (int nb = 0; nb < 4; nb++)
                    mma_f16(acc[mi][nb], a[mi][0], a[mi][1], a[mi][2], a[mi][3],
                            b[nb >> 1][(nb & 1) * 2], b[nb >> 1][(nb & 1) * 2 + 1]);
            #pragma unroll
            for (int mi = 0; mi < 4; mi++)
                ldsm_x4(a[mi][0], a[mi][1], a[mi][2], a[mi][3],
                        sb + F_AL + SWZ1((a_row + mi * 16) * 128 + kb + a_cb));
            #pragma unroll
            for (int mi = 0; mi < 4; mi++)
                #pragma unroll
                for (int nb = 0; nb < 4; nb++)
                    mma_f16(acc[mi][nb], a[mi][0], a[mi][1], a[mi][2], a[mi][3],
                            b[nb >> 1][(nb & 1) * 2], b[nb >> 1][(nb & 1) * 2 + 1]);
        }
        __syncthreads();
    }

    // dump acc, then final epilogue: mean + att + time coordinate
    {
        const int rr = wm * 64 + (lane >> 2);
        const int cc = wn * 32 + 2 * (lane & 3);
        #pragma unroll
        for (int mi = 0; mi < 4; mi++)
            #pragma unroll
            for (int nb = 0; nb < 4; nb++) {
                int r = rr + mi * 16;
                int c = cc + (nb >> 1) * 16 + (nb & 1) * 8;
                *(float2*)&Cs[r * C_LD + c]       = *(float2*)&acc[mi][nb][0];
                *(float2*)&Cs[(r + 8) * C_LD + c] = *(float2*)&acc[mi][nb][2];
            }
    }
    __syncthreads();
    #pragma unroll 2
    for (int i = 0; i < 16; i++) {
        int r = warp * 16 + i;
        int n = row0 + r;
        float4 x = *(float4*)&Cs[r * C_LD + lane * 4];
        float4 a4 = *(const float4*)(att + (size_t)n * DD + lane * 4);
        float v0 = x.x * OSCALE + a4.x;
        float v1 = x.y * OSCALE + a4.y;
        float v2 = x.z * OSCALE + a4.z;
        float v3 = x.w * OSCALE + a4.w;
        float ssum = v0 * v0 + v1 * v1 + v2 * v2 + v3 * v3;
        #pragma unroll
        for (int off = 16; off; off >>= 1) ssum += __shfl_xor_sync(0xffffffffu, ssum, off);
        float t = sqrtf(ssum + 1.0f);
        float* op = out + (size_t)n * 129;
        if (lane == 0) op[0] = t;
        op[1 + lane * 4 + 0] = v0;
        op[1 + lane * 4 + 1] = v1;
        op[1 + lane * 4 + 2] = v2;
        op[1 + lane * 4 + 3] = v3;
    }
}

// ---------------- launch ----------------
extern "C" void kernel_launch(void* const* d_in, const int* in_sizes, int n_in,
                              void* d_out, int out_size) {
    const float* xq   = (const float*)d_in[0];
    const float* xs   = (const float*)d_in[1];
    const float* Wq_w = (const float*)d_in[2];
    const float* Wq_b = (const float*)d_in[3];
    const float* Wk_w = (const float*)d_in[4];
    const float* Wk_b = (const float*)d_in[5];
    const float* Wv_w = (const float*)d_in[6];
    const float* Wv_b = (const float*)d_in[7];
    const float* vmw  = (const float*)d_in[8];
    const float* vmb  = (const float*)d_in[9];
    const float* nsc  = (const float*)d_in[10];
    float* out = (float*)d_out;

    float *pcfuse, *patt, *pksum;
    __nv_bfloat16 *pWqh, *pWql, *pWkh, *pWkl, *pWfh, *pWfl;
    __nv_bfloat16 *pXsh, *pXsl, *pXqh, *pXql;
    __half *pKfh, *pKfl, *pQfh, *pQfl;
    cudaGetSymbolAddress((void**)&pcfuse, g_cfuse);
    cudaGetSymbolAddress((void**)&patt, g_att);
    cudaGetSymbolAddress((void**)&pksum, g_ksum);
    cudaGetSymbolAddress((void**)&pWqh, g_Wqh);
    cudaGetSymbolAddress((void**)&pWql, g_Wql);
    cudaGetSymbolAddress((void**)&pWkh, g_Wkh);
    cudaGetSymbolAddress((void**)&pWkl, g_Wkl);
    cudaGetSymbolAddress((void**)&pWfh, g_WfTh);
    cudaGetSymbolAddress((void**)&pWfl, g_WfTl);
    cudaGetSymbolAddress((void**)&pXsh, g_Xsh);
    cudaGetSymbolAddress((void**)&pXsl, g_Xsl);
    cudaGetSymbolAddress((void**)&pXqh, g_Xqh);
    cudaGetSymbolAddress((void**)&pXql, g_Xql);
    cudaGetSymbolAddress((void**)&pKfh, g_Kfh);
    cudaGetSymbolAddress((void**)&pKfl, g_Kfl);
    cudaGetSymbolAddress((void**)&pQfh, g_Qfh);
    cudaGetSymbolAddress((void**)&pQfl, g_Qfl);

    cudaFuncSetAttribute(mm_gemm, cudaFuncAttributeMaxDynamicSharedMemorySize, MM_SMEM);
    cudaFuncSetAttribute(vproj_f16, cudaFuncAttributeMaxDynamicSharedMemorySize, VP_SMEM);
    cudaFuncSetAttribute(ktv_mma, cudaFuncAttributeMaxDynamicSharedMemorySize, KTV_SMEM);
    cudaFuncSetAttribute(attn_out, cudaFuncAttributeMaxDynamicSharedMemorySize, MM_SMEM);

    split_x_kernel<<<(NR * DD / 4 + 255) / 256, 256>>>(xs, xq);
    prep_kernel<<<(3 * 131072 + DD * DD + 255) / 256, 256>>>(Wq_w, Wk_w, Wv_w);
    wfuse_kernel<<<(DD * DD + 255) / 256, 256>>>(Wv_b, vmw, vmb);

    dim3 gproj(NR / 128, NH);
    // K projection + fused phi -> fp16 pair (bf16 3-pass core)
    mm_gemm<<<gproj, 256, MM_SMEM>>>(pXsh, pXsl, pWkh, pWkl, Wk_b,
                                     nullptr, HD, nsc, nullptr, pKfh, pKfl);
    // V projection (fp16 2-pass) -> fp16 single
    vproj_f16<<<gproj, 256, VP_SMEM>>>(Wv_b);
    // ktv + ksum (fp16 2-pass)
    ktv_mma<<<dim3(NH, KC2), 256, KTV_SMEM>>>();
    ktv_reduce_kernel<<<(NH * DD * DD + 255) / 256, 256>>>();
    // fused vss: xs @ WfuseT -> att (bf16 3-pass, fp32 out)
    mm_gemm<<<dim3(NR / 128, 1), 256, MM_SMEM>>>(pXsh, pXsl, pWfh, pWfl, pcfuse,
                                                 patt, DD, nullptr, nullptr, nullptr, nullptr);
    // Q projection + phi + dinv*2^20 -> fp16 pair (bf16 3-pass core)
    mm_gemm<<<gproj, 256, MM_SMEM>>>(pXqh, pXql, pWqh, pWql, Wq_b,
                                     nullptr, HD, nsc, pksum, pQfh, pQfl);
    // fused numerator + combine + time coordinate -> out [NR][129]
    attn_out<<<NR / 128, 256, MM_SMEM>>>(patt, out);
}

// round 9
// speedup vs baseline: 1.7621x; 1.2274x over previous
#include <cuda_runtime.h>
#include <cuda_bf16.h>
#include <cuda_fp16.h>
#include <cstdint>
#include <math.h>

#define NR 32768
#define NH 8
#define DD 128
#define HD 1024     // NH * DD
#define KC2 64      // split-K chunks for ktv (512 rows each)
#define QSCALE 1048576.f          // 2^20 pre-scale for Q*dinv (fp16 range guard)
#define OSCALE (0.125f / 1048576.f)

// ---------------- scratch (static device memory; no allocations) ----------------
__device__ __half g_Wqf[DD * HD], g_Wkf[DD * HD], g_Wvf[DD * HD];  // fp16 single, K-major
__device__ float g_Wvm[DD * DD];
__device__ __nv_bfloat16 g_WfTh[DD * DD], g_WfTl[DD * DD];         // fused vss weight
__device__ float g_cfuse[DD];
__device__ float g_att[(size_t)NR * DD];
__device__ __nv_bfloat16 g_Xsh[(size_t)NR * DD], g_Xsl[(size_t)NR * DD];  // xs bf16 pair (vss)
__device__ __half g_Xfh[(size_t)NR * DD], g_Xfl[(size_t)NR * DD];         // xs fp16 pair
__device__ __half g_Xqfh[(size_t)NR * DD], g_Xqfl[(size_t)NR * DD];       // xq fp16 pair
__device__ __half g_Kf[(size_t)NR * HD];                                  // phi_ks fp16 single
__device__ __half g_Vf[(size_t)NR * HD];                                  // v fp16 single
__device__ __half g_Qf[(size_t)NR * HD];                                  // Q*dinv*2^20 single
__device__ __half g_ktvTf[NH * DD * DD];                                  // [h][d][m] fp16
__device__ float g_ksum[NH * DD];
__device__ float g_ktvp[(size_t)KC2 * NH * DD * DD];
__device__ float g_ksump[KC2 * NH * DD];

// ---------------- helpers ----------------
__device__ __forceinline__ uint32_t smem_u32(const void* p) {
    uint32_t a;
    asm("{ .reg .u64 t; cvta.to.shared.u64 t, %1; cvt.u32.u64 %0, t; }" : "=r"(a) : "l"(p));
    return a;
}
__device__ __forceinline__ uint32_t pack_bf2(__nv_bfloat16 a, __nv_bfloat16 b) {
    __nv_bfloat162 t; t.x = a; t.y = b;
    return *reinterpret_cast<uint32_t*>(&t);
}
__device__ __forceinline__ uint32_t pack_h2(__half a, __half b) {
    __half2 t; t.x = a; t.y = b;
    return *reinterpret_cast<uint32_t*>(&t);
}
__device__ __forceinline__ void split_bf(float x, __nv_bfloat16& h, __nv_bfloat16& l) {
    h = __float2bfloat16_rn(x);
    l = __float2bfloat16_rn(x - __bfloat162float(h));
}
__device__ __forceinline__ void split_h(float x, __half& h, __half& l) {
    h = __float2half_rn(x);
    l = __float2half_rn(x - __half2float(h));
}
#define SWZ(o)  ((o) ^ ((((o) >> 8) & 7) << 4))
#define SWZ1(o) ((o) ^ ((((o) >> 7) & 7) << 4))

__device__ __forceinline__ void ldsm_x4(uint32_t& r0, uint32_t& r1, uint32_t& r2,
                                        uint32_t& r3, uint32_t addr) {
    asm volatile("ldmatrix.sync.aligned.m8n8.x4.shared.b16 {%0,%1,%2,%3}, [%4];"
                 : "=r"(r0), "=r"(r1), "=r"(r2), "=r"(r3) : "r"(addr));
}
__device__ __forceinline__ void ldsm_x4_t(uint32_t& r0, uint32_t& r1, uint32_t& r2,
                                          uint32_t& r3, uint32_t addr) {
    asm volatile("ldmatrix.sync.aligned.m8n8.x4.trans.shared.b16 {%0,%1,%2,%3}, [%4];"
                 : "=r"(r0), "=r"(r1), "=r"(r2), "=r"(r3) : "r"(addr));
}
__device__ __forceinline__ void mma_bf16(float* c, uint32_t a0, uint32_t a1,
                                         uint32_t a2, uint32_t a3,
                                         uint32_t b0, uint32_t b1) {
    asm volatile("mma.sync.aligned.m16n8k16.row.col.f32.bf16.bf16.f32 "
                 "{%0,%1,%2,%3}, {%4,%5,%6,%7}, {%8,%9}, {%0,%1,%2,%3};"
                 : "+f"(c[0]), "+f"(c[1]), "+f"(c[2]), "+f"(c[3])
                 : "r"(a0), "r"(a1), "r"(a2), "r"(a3), "r"(b0), "r"(b1));
}
__device__ __forceinline__ void mma_f16(float* c, uint32_t a0, uint32_t a1,
                                        uint32_t a2, uint32_t a3,
                                        uint32_t b0, uint32_t b1) {
    asm volatile("mma.sync.aligned.m16n8k16.row.col.f32.f16.f16.f32 "
                 "{%0,%1,%2,%3}, {%4,%5,%6,%7}, {%8,%9}, {%0,%1,%2,%3};"
                 : "+f"(c[0]), "+f"(c[1]), "+f"(c[2]), "+f"(c[3])
                 : "r"(a0), "r"(a1), "r"(a2), "r"(a3), "r"(b0), "r"(b1));
}
__device__ __forceinline__ void cp16(uint32_t saddr, const void* g) {
    asm volatile("cp.async.cg.shared.global [%0], [%1], 16;" :: "r"(saddr), "l"(g));
}
#define CP_COMMIT() asm volatile("cp.async.commit_group;" ::: "memory")
#define CP_WAIT0()  asm volatile("cp.async.wait_group 0;" ::: "memory")

// ---------------- input split ----------------
__global__ void split_x_kernel(const float* __restrict__ xs, const float* __restrict__ xq) {
    int idx = blockIdx.x * blockDim.x + threadIdx.x;
    if (idx >= NR * DD / 4) return;
    float4 s = *(const float4*)(xs + (size_t)idx * 4);
    float4 q = *(const float4*)(xq + (size_t)idx * 4);
    {   // xs bf16 pair (vss)
        __nv_bfloat16 h0, h1, h2, h3, l0, l1, l2, l3;
        split_bf(s.x, h0, l0); split_bf(s.y, h1, l1);
        split_bf(s.z, h2, l2); split_bf(s.w, h3, l3);
        uint2 hv = { pack_bf2(h0, h1), pack_bf2(h2, h3) };
        uint2 lv = { pack_bf2(l0, l1), pack_bf2(l2, l3) };
        *(uint2*)(g_Xsh + (size_t)idx * 4) = hv;
        *(uint2*)(g_Xsl + (size_t)idx * 4) = lv;
    }
    {   // xs fp16 pair
        __half h0, h1, h2, h3, l0, l1, l2, l3;
        split_h(s.x, h0, l0); split_h(s.y, h1, l1);
        split_h(s.z, h2, l2); split_h(s.w, h3, l3);
        uint2 hv = { pack_h2(h0, h1), pack_h2(h2, h3) };
        uint2 lv = { pack_h2(l0, l1), pack_h2(l2, l3) };
        *(uint2*)(g_Xfh + (size_t)idx * 4) = hv;
        *(uint2*)(g_Xfl + (size_t)idx * 4) = lv;
    }
    {   // xq fp16 pair
        __half h0, h1, h2, h3, l0, l1, l2, l3;
        split_h(q.x, h0, l0); split_h(q.y, h1, l1);
        split_h(q.z, h2, l2); split_h(q.w, h3, l3);
        uint2 hv = { pack_h2(h0, h1), pack_h2(h2, h3) };
        uint2 lv = { pack_h2(l0, l1), pack_h2(l2, l3) };
        *(uint2*)(g_Xqfh + (size_t)idx * 4) = hv;
        *(uint2*)(g_Xqfl + (size_t)idx * 4) = lv;
    }
}

// ---------------- weight prep ----------------
__global__ void prep_kernel(const float* __restrict__ Wq,
                            const float* __restrict__ Wk,
                            const float* __restrict__ Wv) {
    int idx = blockIdx.x * blockDim.x + threadIdx.x;
    if (idx < 3 * 131072) {
        int which = idx / 131072;
        int e = idx % 131072;
        if (which == 0)      g_Wqf[e] = __float2half_rn(Wq[e]);
        else if (which == 1) g_Wkf[e] = __float2half_rn(Wk[e]);
        else                 g_Wvf[e] = __float2half_rn(Wv[e]);
    } else if (idx < 3 * 131072 + DD * DD) {
        int e = idx - 3 * 131072;
        int i = e & 127, d = e >> 7;
        float s = 0.f;
        #pragma unroll
        for (int h = 0; h < NH; h++) s += Wv[((size_t)(h * DD + d)) * DD + i];
        g_Wvm[d * DD + i] = s * 0.125f;
    }
}

__global__ void wfuse_kernel(const float* __restrict__ Wv_b,
                             const float* __restrict__ vmw,
                             const float* __restrict__ vmb) {
    int idx = blockIdx.x * blockDim.x + threadIdx.x;
    if (idx >= DD * DD) return;
    int o = idx & 127, i = idx >> 7;
    float acc = 0.f;
    for (int d = 0; d < DD; d++) acc += g_Wvm[d * DD + i] * vmw[o * DD + d];
    __nv_bfloat16 h, l;
    split_bf(acc, h, l);
    g_WfTh[o * DD + i] = h;
    g_WfTl[o * DD + i] = l;
    if (idx < DD) {
        float c = 0.f;
        for (int d = 0; d < DD; d++) {
            float bm = 0.f;
            #pragma unroll
            for (int hh = 0; hh < NH; hh++) bm += Wv_b[hh * DD + d];
            c += 0.125f * bm * vmw[idx * DD + d];
        }
        g_cfuse[idx] = c + vmb[idx];
    }
}

// ---------------- fp16 2-pass projection (A pair, B single) ----------------
#define F_AH 0
#define F_AL 16384
#define F_B  32768
#define C_LD 132
#define PJ_SMEM (128 * C_LD * 4)   // 67584 (covers 49152 panels + C staging)

__global__ void __launch_bounds__(256, 2) proj_f16(
    const __half* __restrict__ Ah, const __half* __restrict__ Al,
    const __half* __restrict__ B_, const float* __restrict__ bias,
    const float* __restrict__ nsc, const float* __restrict__ ksum,
    __half* __restrict__ OutF) {
    extern __shared__ __align__(16) char smem[];
    const uint32_t sb = smem_u32(smem);
    float* Cs = (float*)smem;
    const int tid = threadIdx.x;
    const int lane = tid & 31, warp = tid >> 5;
    const int wm = warp >> 2, wn = warp & 3;
    const int row0 = blockIdx.x * 128;
    const int colb = blockIdx.y * 128;
    const __half* B = B_ + (size_t)colb * DD;

    float acc[4][4][4];
    #pragma unroll
    for (int i = 0; i < 4; i++)
        #pragma unroll
        for (int j = 0; j < 4; j++)
            #pragma unroll
            for (int e = 0; e < 4; e++) acc[i][j][e] = 0.f;

    const uint32_t a_row = wm * 64 + (lane & 15);
    const uint32_t a_cb  = (lane >> 4) * 16;
    const uint32_t b_row = wn * 32 + (lane & 7) + ((lane >> 4) & 1) * 8;
    const uint32_t b_cb  = ((lane >> 3) & 1) * 16;

    #pragma unroll
    for (int kc = 0; kc < 2; kc++) {
        #pragma unroll
        for (int it = 0; it < 4; it++) {
            int idx = it * 256 + tid;
            int r = idx >> 3, c8 = idx & 7;
            size_t ga = (size_t)(row0 + r) * DD + kc * 64 + c8 * 8;
            size_t gb = (size_t)r * DD + kc * 64 + c8 * 8;
            uint32_t off = SWZ1((uint32_t)(r * 128 + c8 * 16));
            cp16(sb + F_AH + off, Ah + ga);
            cp16(sb + F_AL + off, Al + ga);
            cp16(sb + F_B + off, B + gb);
        }
        CP_COMMIT();
        CP_WAIT0();
        __syncthreads();

        #pragma unroll
        for (int k = 0; k < 4; k++) {
            const uint32_t kb = k * 32;
            uint32_t a[4][4], b[2][4];
            #pragma unroll
            for (int nj = 0; nj < 2; nj++)
                ldsm_x4(b[nj][0], b[nj][1], b[nj][2], b[nj][3],
                        sb + F_B + SWZ1((b_row + nj * 16) * 128 + kb + b_cb));
            #pragma unroll
            for (int mi = 0; mi < 4; mi++)
                ldsm_x4(a[mi][0], a[mi][1], a[mi][2], a[mi][3],
                        sb + F_AH + SWZ1((a_row + mi * 16) * 128 + kb + a_cb));
            #pragma unroll
            for (int mi = 0; mi < 4; mi++)
                #pragma unroll
                for (int nb = 0; nb < 4; nb++)
                    mma_f16(acc[mi][nb], a[mi][0], a[mi][1], a[mi][2], a[mi][3],
                            b[nb >> 1][(nb & 1) * 2], b[nb >> 1][(nb & 1) * 2 + 1]);
            #pragma unroll
            for (int mi = 0; mi < 4; mi++)
                ldsm_x4(a[mi][0], a[mi][1], a[mi][2], a[mi][3],
                        sb + F_AL + SWZ1((a_row + mi * 16) * 128 + kb + a_cb));
            #pragma unroll
            for (int mi = 0; mi < 4; mi++)
                #pragma unroll
                for (int nb = 0; nb < 4; nb++)
                    mma_f16(acc[mi][nb], a[mi][0], a[mi][1], a[mi][2], a[mi][3],
                            b[nb >> 1][(nb & 1) * 2], b[nb >> 1][(nb & 1) * 2 + 1]);
        }
        __syncthreads();
    }

    const int rr = wm * 64 + (lane >> 2);
    const int cc = wn * 32 + 2 * (lane & 3);

    if (nsc) {
        // phi (+ optional dinv*QSCALE) epilogue -> fp16 single
        #pragma unroll
        for (int mi = 0; mi < 4; mi++)
            #pragma unroll
            for (int nb = 0; nb < 4; nb++) {
                int r = rr + mi * 16;
                int c = cc + (nb >> 1) * 16 + (nb & 1) * 8;
                *(float2*)&Cs[r * C_LD + c]       = *(float2*)&acc[mi][nb][0];
                *(float2*)&Cs[(r + 8) * C_LD + c] = *(float2*)&acc[mi][nb][2];
            }
        __syncthreads();
        float inv = 1.f / (fabsf(*nsc) + 1e-6f);
        const float4 bv = *(const float4*)(bias + colb + lane * 4);
        float4 ks4 = { 0.f, 0.f, 0.f, 0.f };
        if (ksum) ks4 = *(const float4*)(ksum + colb + lane * 4);
        #pragma unroll 2
        for (int i = 0; i < 16; i++) {
            int r = warp * 16 + i;
            float4 x = *(float4*)&Cs[r * C_LD + lane * 4];
            float y0 = (fmaxf(x.x + bv.x, 0.f) + 1e-6f) * inv;
            float y1 = (fmaxf(x.y + bv.y, 0.f) + 1e-6f) * inv;
            float y2 = (fmaxf(x.z + bv.z, 0.f) + 1e-6f) * inv;
            float y3 = (fmaxf(x.w + bv.w, 0.f) + 1e-6f) * inv;
            float q0 = y0 * y0, q1 = y1 * y1, q2 = y2 * y2, q3 = y3 * y3;
            float s2 = q0 + q1 + q2 + q3;
            float s4 = q0 * q0 + q1 * q1 + q2 * q2 + q3 * q3;
            #pragma unroll
            for (int off = 16; off; off >>= 1) {
                s2 += __shfl_xor_sync(0xffffffffu, s2, off);
                s4 += __shfl_xor_sync(0xffffffffu, s4, off);
            }
            float rsc = sqrtf(s2) / (sqrtf(s4) + 1e-8f);
            float4 o;
            o.x = rsc * q0; o.y = rsc * q1; o.z = rsc * q2; o.w = rsc * q3;
            if (ksum) {
                float dd = o.x * ks4.x + o.y * ks4.y + o.z * ks4.z + o.w * ks4.w;
                #pragma unroll
                for (int off = 16; off; off >>= 1) dd += __shfl_xor_sync(0xffffffffu, dd, off);
                float sc = QSCALE / (dd + 1e-6f);
                o.x *= sc; o.y *= sc; o.z *= sc; o.w *= sc;
            }
            size_t base = (size_t)(row0 + r) * HD + colb + lane * 4;
            uint2 hv = { pack_h2(__float2half_rn(o.x), __float2half_rn(o.y)),
                         pack_h2(__float2half_rn(o.z), __float2half_rn(o.w)) };
            *(uint2*)(OutF + base) = hv;
        }
    } else {
        // direct epilogue (V projection)
        #pragma unroll
        for (int mi = 0; mi < 4; mi++)
            #pragma unroll
            for (int nb = 0; nb < 4; nb++) {
                int r = rr + mi * 16;
                int c = cc + (nb >> 1) * 16 + (nb & 1) * 8;
                float b0 = bias[colb + c];
                float b1 = bias[colb + c + 1];
                *(uint32_t*)(OutF + (size_t)(row0 + r) * HD + colb + c) =
                    pack_h2(__float2half_rn(acc[mi][nb][0] + b0),
                            __float2half_rn(acc[mi][nb][1] + b1));
                *(uint32_t*)(OutF + (size_t)(row0 + r + 8) * HD + colb + c) =
                    pack_h2(__float2half_rn(acc[mi][nb][2] + b0),
                            __float2half_rn(acc[mi][nb][3] + b1));
            }
    }
}

// ---------------- bf16 3-pass GEMM (vss only) ----------------
#define S_AH 0
#define S_AL 16384
#define S_BH 32768
#define S_BL 49152
#define MM_SMEM 65536

__global__ void __launch_bounds__(256, 2) mm_gemm_vss(
    const __nv_bfloat16* __restrict__ Ah, const __nv_bfloat16* __restrict__ Al,
    const __nv_bfloat16* __restrict__ Bh, const __nv_bfloat16* __restrict__ Bl,
    const float* __restrict__ bias, float* __restrict__ Cf) {
    extern __shared__ __align__(16) char smem[];
    const uint32_t sb = smem_u32(smem);
    const int tid = threadIdx.x;
    const int lane = tid & 31, warp = tid >> 5;
    const int wm = warp >> 2, wn = warp & 3;
    const int row0 = blockIdx.x * 128;

    float acc[4][4][4];
    #pragma unroll
    for (int i = 0; i < 4; i++)
        #pragma unroll
        for (int j = 0; j < 4; j++)
            #pragma unroll
            for (int e = 0; e < 4; e++) acc[i][j][e] = 0.f;

    const uint32_t a_row = wm * 64 + (lane & 15);
    const uint32_t a_cb  = (lane >> 4) * 16;
    const uint32_t b_row = wn * 32 + (lane & 7) + ((lane >> 4) & 1) * 8;
    const uint32_t b_cb  = ((lane >> 3) & 1) * 16;

    #pragma unroll
    for (int kc = 0; kc < 2; kc++) {
        #pragma unroll
        for (int it = 0; it < 4; it++) {
            int idx = it * 256 + tid;
            int r = idx >> 3, c8 = idx & 7;
            size_t ga = (size_t)(row0 + r) * DD + kc * 64 + c8 * 8;
            size_t gb = (size_t)r * DD + kc * 64 + c8 * 8;
            uint32_t off = SWZ1((uint32_t)(r * 128 + c8 * 16));
            cp16(sb + S_AH + off, Ah + ga);
            cp16(sb + S_AL + off, Al + ga);
            cp16(sb + S_BH + off, Bh + gb);
            cp16(sb + S_BL + off, Bl + gb);
        }
        CP_COMMIT();
        CP_WAIT0();
        __syncthreads();

        #pragma unroll
        for (int k = 0; k < 4; k++) {
            const uint32_t kb = k * 32;
            uint32_t ah[4][4], al[4][4], b[2][4];
            #pragma unroll
            for (int mi = 0; mi < 4; mi++) {
                uint32_t ra = SWZ1((a_row + mi * 16) * 128 + kb + a_cb);
                ldsm_x4(ah[mi][0], ah[mi][1], ah[mi][2], ah[mi][3], sb + S_AH + ra);
                ldsm_x4(al[mi][0], al[mi][1], al[mi][2], al[mi][3], sb + S_AL + ra);
            }
            #pragma unroll
            for (int nj = 0; nj < 2; nj++)
                ldsm_x4(b[nj][0], b[nj][1], b[nj][2], b[nj][3],
                        sb + S_BH + SWZ1((b_row + nj * 16) * 128 + kb + b_cb));
            #pragma unroll
            for (int mi = 0; mi < 4; mi++)
                #pragma unroll
                for (int nb = 0; nb < 4; nb++) {
                    mma_bf16(acc[mi][nb], ah[mi][0], ah[mi][1], ah[mi][2], ah[mi][3],
                             b[nb >> 1][(nb & 1) * 2], b[nb >> 1][(nb & 1) * 2 + 1]);
                    mma_bf16(acc[mi][nb], al[mi][0], al[mi][1], al[mi][2], al[mi][3],
                             b[nb >> 1][(nb & 1) * 2], b[nb >> 1][(nb & 1) * 2 + 1]);
                }
            #pragma unroll
            for (int nj = 0; nj < 2; nj++)
                ldsm_x4(b[nj][0], b[nj][1], b[nj][2], b[nj][3],
                        sb + S_BL + SWZ1((b_row + nj * 16) * 128 + kb + b_cb));
            #pragma unroll
            for (int mi = 0; mi < 4; mi++)
                #pragma unroll
                for (int nb = 0; nb < 4; nb++)
                    mma_bf16(acc[mi][nb], ah[mi][0], ah[mi][1], ah[mi][2], ah[mi][3],
                             b[nb >> 1][(nb & 1) * 2], b[nb >> 1][(nb & 1) * 2 + 1]);
        }
        __syncthreads();
    }

    const int rr = wm * 64 + (lane >> 2);
    const int cc = wn * 32 + 2 * (lane & 3);
    #pragma unroll
    for (int mi = 0; mi < 4; mi++)
        #pragma unroll
        for (int nb = 0; nb < 4; nb++) {
            int r = rr + mi * 16;
            int c = cc + (nb >> 1) * 16 + (nb & 1) * 8;
            float b0 = bias[c], b1 = bias[c + 1];
            float2 v0 = { acc[mi][nb][0] + b0, acc[mi][nb][1] + b1 };
            float2 v1 = { acc[mi][nb][2] + b0, acc[mi][nb][3] + b1 };
            *(float2*)(Cf + (size_t)(row0 + r) * DD + c) = v0;
            *(float2*)(Cf + (size_t)(row0 + r + 8) * DD + c) = v1;
        }
}

// ---------------- ktv via fp16 1-pass mma ----------------
#define T_P 0
#define T_V 16384
#define KTV_SMEM 32768

__global__ void __launch_bounds__(256, 2) ktv_mma() {
    extern __shared__ __align__(16) char smem[];
    const uint32_t sb = smem_u32(smem);
    const int h = blockIdx.x;
    const int chunk = blockIdx.y;
    const int tid = threadIdx.x;
    const int lane = tid & 31, warp = tid >> 5;
    const int wm = warp >> 2, wn = warp & 3;
    const int n0 = chunk * (NR / KC2);

    float acc[4][4][4];
    #pragma unroll
    for (int i = 0; i < 4; i++)
        #pragma unroll
        for (int j = 0; j < 4; j++)
            #pragma unroll
            for (int e = 0; e < 4; e++) acc[i][j][e] = 0.f;
    float ks = 0.f;

    const uint32_t a_kr = (lane & 7) + ((lane >> 4) & 1) * 8;
    const uint32_t a_cl = wm * 64 + ((lane >> 3) & 1) * 8;
    const uint32_t b_kr = (lane & 7) + ((lane >> 3) & 1) * 8;
    const uint32_t b_cl = wn * 32 + ((lane >> 4) & 1) * 8;

    for (int s = 0; s < (NR / KC2) / 64; s++) {
        const int nb = n0 + s * 64;
        #pragma unroll
        for (int it = 0; it < 4; it++) {
            int idx = it * 256 + tid;
            int r = idx >> 4, c16 = idx & 15;
            size_t gb = (size_t)(nb + r) * HD + h * DD + c16 * 8;
            uint32_t off = SWZ((uint32_t)(r * 256 + c16 * 16));
            cp16(sb + T_P + off, g_Kf + gb);
            cp16(sb + T_V + off, g_Vf + gb);
        }
        CP_COMMIT();
        CP_WAIT0();
        __syncthreads();

        #pragma unroll
        for (int kk = 0; kk < 4; kk++) {
            uint32_t a[4][4], b[2][4];
            #pragma unroll
            for (int nj = 0; nj < 2; nj++)
                ldsm_x4_t(b[nj][0], b[nj][1], b[nj][2], b[nj][3],
                          sb + T_V + SWZ((kk * 16 + b_kr) * 256 + (b_cl + nj * 16) * 2));
            #pragma unroll
            for (int mi = 0; mi < 4; mi++)
                ldsm_x4_t(a[mi][0], a[mi][1], a[mi][2], a[mi][3],
                          sb + T_P + SWZ((kk * 16 + a_kr) * 256 + (a_cl + mi * 16) * 2));
            #pragma unroll
            for (int mi = 0; mi < 4; mi++)
                #pragma unroll
                for (int nbt = 0; nbt < 4; nbt++)
                    mma_f16(acc[mi][nbt], a[mi][0], a[mi][1], a[mi][2], a[mi][3],
                            b[nbt >> 1][(nbt & 1) * 2], b[nbt >> 1][(nbt & 1) * 2 + 1]);
        }
        if (tid < 128) {
            #pragma unroll 4
            for (int r = 0; r < 64; r++) {
                uint32_t off = SWZ((uint32_t)(r * 256 + tid * 2));
                ks += __half2float(*(const __half*)(smem + T_P + off));
            }
        }
        __syncthreads();
    }

    float* outp = g_ktvp + ((size_t)chunk * NH + h) * (DD * DD);
    const int rr = wm * 64 + (lane >> 2);
    const int cc = wn * 32 + 2 * (lane & 3);
    #pragma unroll
    for (int mi = 0; mi < 4; mi++)
        #pragma unroll
        for (int nbt = 0; nbt < 4; nbt++) {
            int r = rr + mi * 16;
            int c = cc + (nbt >> 1) * 16 + (nbt & 1) * 8;
            *(float2*)&outp[r * DD + c]       = *(float2*)&acc[mi][nbt][0];
            *(float2*)&outp[(r + 8) * DD + c] = *(float2*)&acc[mi][nbt][2];
        }
    if (tid < 128) g_ksump[(chunk * NH + h) * DD + tid] = ks;
}

__global__ void ktv_reduce_kernel() {
    int idx = blockIdx.x * blockDim.x + threadIdx.x;
    if (idx < NH * DD * DD) {
        float s = 0.f;
        #pragma unroll 8
        for (int c = 0; c < KC2; c++) s += g_ktvp[(size_t)c * NH * DD * DD + idx];
        int h = idx >> 14, m = (idx >> 7) & 127, d = idx & 127;
        g_ktvTf[(h << 14) + (d << 7) + m] = __float2half_rn(s);
    }
    if (idx < NH * DD) {
        float s = 0.f;
        #pragma unroll 8
        for (int c = 0; c < KC2; c++) s += g_ksump[c * NH * DD + idx];
        g_ksum[idx] = s;
    }
}

// ---------------- fused numerator + combine (fp16 1-pass): out[n][129] ----------------
#define A_A 0
#define A_B 16384
#define AT_SMEM (128 * C_LD * 4)   // 67584

__global__ void __launch_bounds__(256, 2) attn_out(const float* __restrict__ att,
                                                   float* __restrict__ out) {
    extern __shared__ __align__(16) char smem[];
    const uint32_t sb = smem_u32(smem);
    float* Cs = (float*)smem;
    const int tid = threadIdx.x;
    const int lane = tid & 31, warp = tid >> 5;
    const int wm = warp >> 2, wn = warp & 3;
    const int row0 = blockIdx.x * 128;

    float acc[4][4][4];
    #pragma unroll
    for (int i = 0; i < 4; i++)
        #pragma unroll
        for (int j = 0; j < 4; j++)
            #pragma unroll
            for (int e = 0; e < 4; e++) acc[i][j][e] = 0.f;

    const uint32_t a_row = wm * 64 + (lane & 15);
    const uint32_t a_cb  = (lane >> 4) * 16;
    const uint32_t b_row = wn * 32 + (lane & 7) + ((lane >> 4) & 1) * 8;
    const uint32_t b_cb  = ((lane >> 3) & 1) * 16;

    for (int kc = 0; kc < 16; kc++) {
        const int h = kc >> 1;
        const __half* B = g_ktvTf + h * (DD * DD) + (kc & 1) * 64;
        #pragma unroll
        for (int it = 0; it < 4; it++) {
            int idx = it * 256 + tid;
            int r = idx >> 3, c8 = idx & 7;
            size_t ga = (size_t)(row0 + r) * HD + kc * 64 + c8 * 8;
            size_t gb = (size_t)r * DD + c8 * 8;
            uint32_t off = SWZ1((uint32_t)(r * 128 + c8 * 16));
            cp16(sb + A_A + off, g_Qf + ga);
            cp16(sb + A_B + off, B + gb);
        }
        CP_COMMIT();
        CP_WAIT0();
        __syncthreads();

        #pragma unroll
        for (int k = 0; k < 4; k++) {
            const uint32_t kb = k * 32;
            uint32_t a[4][4], b[2][4];
            #pragma unroll
            for (int nj = 0; nj < 2; nj++)
                ldsm_x4(b[nj][0], b[nj][1], b[nj][2], b[nj][3],
                        sb + A_B + SWZ1((b_row + nj * 16) * 128 + kb + b_cb));
            #pragma unroll
            for (int mi = 0; mi < 4; mi++)
                ldsm_x4(a[mi][0], a[mi][1], a[mi][2], a[mi][3],
                        sb + A_A + SWZ1((a_row + mi * 16) * 128 + kb + a_cb));
            #pragma unroll
            for (int mi = 0; mi < 4; mi++)
                #pragma unroll
                for (int nb = 0; nb < 4; nb++)
                    mma_f16(acc[mi][nb], a[mi][0], a[mi][1], a[mi][2], a[mi][3],
                            b[nb >> 1][(nb & 1) * 2], b[nb >> 1][(nb & 1) * 2 + 1]);
        }
        __syncthreads();
    }

    // dump acc, then final epilogue: mean + att + time coordinate
    {
        const int rr = wm * 64 + (lane >> 2);
        const int cc = wn * 32 + 2 * (lane & 3);
        #pragma unroll
        for (int mi = 0; mi < 4; mi++)
            #pragma unroll
            for (int nb = 0; nb < 4; nb++) {
                int r = rr + mi * 16;
                int c = cc + (nb >> 1) * 16 + (nb & 1) * 8;
                *(float2*)&Cs[r * C_LD + c]       = *(float2*)&acc[mi][nb][0];
                *(float2*)&Cs[(r + 8) * C_LD + c] = *(float2*)&acc[mi][nb][2];
            }
    }
    __syncthreads();
    #pragma unroll 2
    for (int i = 0; i < 16; i++) {
        int r = warp * 16 + i;
        int n = row0 + r;
        float4 x = *(float4*)&Cs[r * C_LD + lane * 4];
        float4 a4 = *(const float4*)(att + (size_t)n * DD + lane * 4);
        float v0 = x.x * OSCALE + a4.x;
        float v1 = x.y * OSCALE + a4.y;
        float v2 = x.z * OSCALE + a4.z;
        float v3 = x.w * OSCALE + a4.w;
        float ssum = v0 * v0 + v1 * v1 + v2 * v2 + v3 * v3;
        #pragma unroll
        for (int off = 16; off; off >>= 1) ssum += __shfl_xor_sync(0xffffffffu, ssum, off);
        float t = sqrtf(ssum + 1.0f);
        float* op = out + (size_t)n * 129;
        if (lane == 0) op[0] = t;
        op[1 + lane * 4 + 0] = v0;
        op[1 + lane * 4 + 1] = v1;
        op[1 + lane * 4 + 2] = v2;
        op[1 + lane * 4 + 3] = v3;
    }
}

// ---------------- launch ----------------
extern "C" void kernel_launch(void* const* d_in, const int* in_sizes, int n_in,
                              void* d_out, int out_size) {
    const float* xq   = (const float*)d_in[0];
    const float* xs   = (const float*)d_in[1];
    const float* Wq_w = (const float*)d_in[2];
    const float* Wq_b = (const float*)d_in[3];
    const float* Wk_w = (const float*)d_in[4];
    const float* Wk_b = (const float*)d_in[5];
    const float* Wv_w = (const float*)d_in[6];
    const float* Wv_b = (const float*)d_in[7];
    const float* vmw  = (const float*)d_in[8];
    const float* vmb  = (const float*)d_in[9];
    const float* nsc  = (const float*)d_in[10];
    float* out = (float*)d_out;

    float *pcfuse, *patt, *pksum;
    __nv_bfloat16 *pWfh, *pWfl, *pXsh, *pXsl;
    __half *pWqf, *pWkf, *pWvf, *pXfh, *pXfl, *pXqfh, *pXqfl, *pKf, *pVf, *pQf;
    cudaGetSymbolAddress((void**)&pcfuse, g_cfuse);
    cudaGetSymbolAddress((void**)&patt, g_att);
    cudaGetSymbolAddress((void**)&pksum, g_ksum);
    cudaGetSymbolAddress((void**)&pWfh, g_WfTh);
    cudaGetSymbolAddress((void**)&pWfl, g_WfTl);
    cudaGetSymbolAddress((void**)&pXsh, g_Xsh);
    cudaGetSymbolAddress((void**)&pXsl, g_Xsl);
    cudaGetSymbolAddress((void**)&pWqf, g_Wqf);
    cudaGetSymbolAddress((void**)&pWkf, g_Wkf);
    cudaGetSymbolAddress((void**)&pWvf, g_Wvf);
    cudaGetSymbolAddress((void**)&pXfh, g_Xfh);
    cudaGetSymbolAddress((void**)&pXfl, g_Xfl);
    cudaGetSymbolAddress((void**)&pXqfh, g_Xqfh);
    cudaGetSymbolAddress((void**)&pXqfl, g_Xqfl);
    cudaGetSymbolAddress((void**)&pKf, g_Kf);
    cudaGetSymbolAddress((void**)&pVf, g_Vf);
    cudaGetSymbolAddress((void**)&pQf, g_Qf);

    cudaFuncSetAttribute(proj_f16, cudaFuncAttributeMaxDynamicSharedMemorySize, PJ_SMEM);
    cudaFuncSetAttribute(mm_gemm_vss, cudaFuncAttributeMaxDynamicSharedMemorySize, MM_SMEM);
    cudaFuncSetAttribute(ktv_mma, cudaFuncAttributeMaxDynamicSharedMemorySize, KTV_SMEM);
    cudaFuncSetAttribute(attn_out, cudaFuncAttributeMaxDynamicSharedMemorySize, AT_SMEM);

    split_x_kernel<<<(NR * DD / 4 + 255) / 256, 256>>>(xs, xq);
    prep_kernel<<<(3 * 131072 + DD * DD + 255) / 256, 256>>>(Wq_w, Wk_w, Wv_w);
    wfuse_kernel<<<(DD * DD + 255) / 256, 256>>>(Wv_b, vmw, vmb);

    dim3 gproj(NR / 128, NH);
    // K projection + fused phi -> Kf (fp16 2-pass)
    proj_f16<<<gproj, 256, PJ_SMEM>>>(pXfh, pXfl, pWkf, Wk_b, nsc, nullptr, pKf);
    // V projection -> Vf (fp16 2-pass, direct)
    proj_f16<<<gproj, 256, PJ_SMEM>>>(pXfh, pXfl, pWvf, Wv_b, nullptr, nullptr, pVf);
    // ktv + ksum (fp16 1-pass)
    ktv_mma<<<dim3(NH, KC2), 256, KTV_SMEM>>>();
    ktv_reduce_kernel<<<(NH * DD * DD + 255) / 256, 256>>>();
    // fused vss: xs @ WfuseT -> att (bf16 3-pass)
    mm_gemm_vss<<<dim3(NR / 128, 1), 256, MM_SMEM>>>(pXsh, pXsl, pWfh, pWfl, pcfuse, patt);
    // Q projection + phi + dinv*2^20 -> Qf (fp16 2-pass)
    proj_f16<<<gproj, 256, PJ_SMEM>>>(pXqfh, pXqfl, pWqf, Wq_b, nsc, pksum, pQf);
    // fused numerator + combine + time coordinate -> out [NR][129]
    attn_out<<<NR / 128, 256, AT_SMEM>>>(patt, out);
}

// round 10
// speedup vs baseline: 1.9931x; 1.1311x over previous
#include <cuda_runtime.h>
#include <cuda_bf16.h>
#include <cuda_fp16.h>
#include <cstdint>
#include <math.h>

#define NR 32768
#define NH 8
#define DD 128
#define HD 1024     // NH * DD
#define KC2 64      // split-K chunks for ktv (512 rows each)
#define QSCALE 1048576.f          // 2^20 pre-scale for Q*dinv (fp16 range guard)
#define OSCALE (0.125f / 1048576.f)

// ---------------- scratch (static device memory; no allocations) ----------------
__device__ __half g_Wqf[DD * HD], g_Wkf[DD * HD], g_Wvf[DD * HD];  // fp16 single, K-major
__device__ float g_Wvm[DD * DD];
__device__ __nv_bfloat16 g_WfTh[DD * DD], g_WfTl[DD * DD];         // fused vss weight
__device__ float g_cfuse[DD];
__device__ float g_att[(size_t)NR * DD];
__device__ __nv_bfloat16 g_Xsh[(size_t)NR * DD], g_Xsl[(size_t)NR * DD];  // xs bf16 pair (vss)
__device__ __half g_Xf[(size_t)NR * DD];                                  // xs fp16 single
__device__ __half g_Xqf[(size_t)NR * DD];                                 // xq fp16 single
__device__ __half g_Kf[(size_t)NR * HD];                                  // phi_ks fp16 single
__device__ __half g_Vf[(size_t)NR * HD];                                  // v fp16 single
__device__ __half g_Qf[(size_t)NR * HD];                                  // Q*dinv*2^20 single
__device__ __half g_ktvTf[NH * DD * DD];                                  // [h][d][m] fp16
__device__ float g_ksum[NH * DD];
__device__ float g_ktvp[(size_t)KC2 * NH * DD * DD];
__device__ float g_ksump[KC2 * NH * DD];

// ---------------- helpers ----------------
__device__ __forceinline__ uint32_t smem_u32(const void* p) {
    uint32_t a;
    asm("{ .reg .u64 t; cvta.to.shared.u64 t, %1; cvt.u32.u64 %0, t; }" : "=r"(a) : "l"(p));
    return a;
}
__device__ __forceinline__ uint32_t pack_bf2(__nv_bfloat16 a, __nv_bfloat16 b) {
    __nv_bfloat162 t; t.x = a; t.y = b;
    return *reinterpret_cast<uint32_t*>(&t);
}
__device__ __forceinline__ uint32_t pack_h2(__half a, __half b) {
    __half2 t; t.x = a; t.y = b;
    return *reinterpret_cast<uint32_t*>(&t);
}
__device__ __forceinline__ void split_bf(float x, __nv_bfloat16& h, __nv_bfloat16& l) {
    h = __float2bfloat16_rn(x);
    l = __float2bfloat16_rn(x - __bfloat162float(h));
}
#define SWZ(o)  ((o) ^ ((((o) >> 8) & 7) << 4))
#define SWZ1(o) ((o) ^ ((((o) >> 7) & 7) << 4))

__device__ __forceinline__ void ldsm_x4(uint32_t& r0, uint32_t& r1, uint32_t& r2,
                                        uint32_t& r3, uint32_t addr) {
    asm volatile("ldmatrix.sync.aligned.m8n8.x4.shared.b16 {%0,%1,%2,%3}, [%4];"
                 : "=r"(r0), "=r"(r1), "=r"(r2), "=r"(r3) : "r"(addr));
}
__device__ __forceinline__ void ldsm_x4_t(uint32_t& r0, uint32_t& r1, uint32_t& r2,
                                          uint32_t& r3, uint32_t addr) {
    asm volatile("ldmatrix.sync.aligned.m8n8.x4.trans.shared.b16 {%0,%1,%2,%3}, [%4];"
                 : "=r"(r0), "=r"(r1), "=r"(r2), "=r"(r3) : "r"(addr));
}
__device__ __forceinline__ void mma_bf16(float* c, uint32_t a0, uint32_t a1,
                                         uint32_t a2, uint32_t a3,
                                         uint32_t b0, uint32_t b1) {
    asm volatile("mma.sync.aligned.m16n8k16.row.col.f32.bf16.bf16.f32 "
                 "{%0,%1,%2,%3}, {%4,%5,%6,%7}, {%8,%9}, {%0,%1,%2,%3};"
                 : "+f"(c[0]), "+f"(c[1]), "+f"(c[2]), "+f"(c[3])
                 : "r"(a0), "r"(a1), "r"(a2), "r"(a3), "r"(b0), "r"(b1));
}
__device__ __forceinline__ void mma_f16(float* c, uint32_t a0, uint32_t a1,
                                        uint32_t a2, uint32_t a3,
                                        uint32_t b0, uint32_t b1) {
    asm volatile("mma.sync.aligned.m16n8k16.row.col.f32.f16.f16.f32 "
                 "{%0,%1,%2,%3}, {%4,%5,%6,%7}, {%8,%9}, {%0,%1,%2,%3};"
                 : "+f"(c[0]), "+f"(c[1]), "+f"(c[2]), "+f"(c[3])
                 : "r"(a0), "r"(a1), "r"(a2), "r"(a3), "r"(b0), "r"(b1));
}
__device__ __forceinline__ void cp16(uint32_t saddr, const void* g) {
    asm volatile("cp.async.cg.shared.global [%0], [%1], 16;" :: "r"(saddr), "l"(g));
}
#define CP_COMMIT() asm volatile("cp.async.commit_group;" ::: "memory")
#define CP_WAIT0()  asm volatile("cp.async.wait_group 0;" ::: "memory")

// ---------------- input split ----------------
__global__ void split_x_kernel(const float* __restrict__ xs, const float* __restrict__ xq) {
    int idx = blockIdx.x * blockDim.x + threadIdx.x;
    if (idx >= NR * DD / 4) return;
    float4 s = *(const float4*)(xs + (size_t)idx * 4);
    float4 q = *(const float4*)(xq + (size_t)idx * 4);
    {   // xs bf16 pair (vss)
        __nv_bfloat16 h0, h1, h2, h3, l0, l1, l2, l3;
        split_bf(s.x, h0, l0); split_bf(s.y, h1, l1);
        split_bf(s.z, h2, l2); split_bf(s.w, h3, l3);
        uint2 hv = { pack_bf2(h0, h1), pack_bf2(h2, h3) };
        uint2 lv = { pack_bf2(l0, l1), pack_bf2(l2, l3) };
        *(uint2*)(g_Xsh + (size_t)idx * 4) = hv;
        *(uint2*)(g_Xsl + (size_t)idx * 4) = lv;
    }
    {   // fp16 singles
        uint2 sv = { pack_h2(__float2half_rn(s.x), __float2half_rn(s.y)),
                     pack_h2(__float2half_rn(s.z), __float2half_rn(s.w)) };
        uint2 qv = { pack_h2(__float2half_rn(q.x), __float2half_rn(q.y)),
                     pack_h2(__float2half_rn(q.z), __float2half_rn(q.w)) };
        *(uint2*)(g_Xf + (size_t)idx * 4) = sv;
        *(uint2*)(g_Xqf + (size_t)idx * 4) = qv;
    }
}

// ---------------- weight prep ----------------
__global__ void prep_kernel(const float* __restrict__ Wq,
                            const float* __restrict__ Wk,
                            const float* __restrict__ Wv) {
    int idx = blockIdx.x * blockDim.x + threadIdx.x;
    if (idx < 3 * 131072) {
        int which = idx / 131072;
        int e = idx % 131072;
        if (which == 0)      g_Wqf[e] = __float2half_rn(Wq[e]);
        else if (which == 1) g_Wkf[e] = __float2half_rn(Wk[e]);
        else                 g_Wvf[e] = __float2half_rn(Wv[e]);
    } else if (idx < 3 * 131072 + DD * DD) {
        int e = idx - 3 * 131072;
        int i = e & 127, d = e >> 7;
        float s = 0.f;
        #pragma unroll
        for (int h = 0; h < NH; h++) s += Wv[((size_t)(h * DD + d)) * DD + i];
        g_Wvm[d * DD + i] = s * 0.125f;
    }
}

__global__ void wfuse_kernel(const float* __restrict__ Wv_b,
                             const float* __restrict__ vmw,
                             const float* __restrict__ vmb) {
    int idx = blockIdx.x * blockDim.x + threadIdx.x;
    if (idx >= DD * DD) return;
    int o = idx & 127, i = idx >> 7;
    float acc = 0.f;
    for (int d = 0; d < DD; d++) acc += g_Wvm[d * DD + i] * vmw[o * DD + d];
    __nv_bfloat16 h, l;
    split_bf(acc, h, l);
    g_WfTh[o * DD + i] = h;
    g_WfTl[o * DD + i] = l;
    if (idx < DD) {
        float c = 0.f;
        for (int d = 0; d < DD; d++) {
            float bm = 0.f;
            #pragma unroll
            for (int hh = 0; hh < NH; hh++) bm += Wv_b[hh * DD + d];
            c += 0.125f * bm * vmw[idx * DD + d];
        }
        g_cfuse[idx] = c + vmb[idx];
    }
}

// ---------------- fp16 1-pass projection (A single, B single) ----------------
#define F_A 0
#define F_B 16384
#define C_LD 132
#define PJ_SMEM (128 * C_LD * 4)   // 67584 (covers 32768 panels + C staging)

__global__ void __launch_bounds__(256, 2) proj_f16(
    const __half* __restrict__ Af, const __half* __restrict__ B_,
    const float* __restrict__ bias,
    const float* __restrict__ nsc, const float* __restrict__ ksum,
    __half* __restrict__ OutF) {
    extern __shared__ __align__(16) char smem[];
    const uint32_t sb = smem_u32(smem);
    float* Cs = (float*)smem;
    const int tid = threadIdx.x;
    const int lane = tid & 31, warp = tid >> 5;
    const int wm = warp >> 2, wn = warp & 3;
    const int row0 = blockIdx.x * 128;
    const int colb = blockIdx.y * 128;
    const __half* B = B_ + (size_t)colb * DD;

    float acc[4][4][4];
    #pragma unroll
    for (int i = 0; i < 4; i++)
        #pragma unroll
        for (int j = 0; j < 4; j++)
            #pragma unroll
            for (int e = 0; e < 4; e++) acc[i][j][e] = 0.f;

    const uint32_t a_row = wm * 64 + (lane & 15);
    const uint32_t a_cb  = (lane >> 4) * 16;
    const uint32_t b_row = wn * 32 + (lane & 7) + ((lane >> 4) & 1) * 8;
    const uint32_t b_cb  = ((lane >> 3) & 1) * 16;

    #pragma unroll
    for (int kc = 0; kc < 2; kc++) {
        #pragma unroll
        for (int it = 0; it < 4; it++) {
            int idx = it * 256 + tid;
            int r = idx >> 3, c8 = idx & 7;
            size_t ga = (size_t)(row0 + r) * DD + kc * 64 + c8 * 8;
            size_t gb = (size_t)r * DD + kc * 64 + c8 * 8;
            uint32_t off = SWZ1((uint32_t)(r * 128 + c8 * 16));
            cp16(sb + F_A + off, Af + ga);
            cp16(sb + F_B + off, B + gb);
        }
        CP_COMMIT();
        CP_WAIT0();
        __syncthreads();

        #pragma unroll
        for (int k = 0; k < 4; k++) {
            const uint32_t kb = k * 32;
            uint32_t a[4][4], b[2][4];
            #pragma unroll
            for (int nj = 0; nj < 2; nj++)
                ldsm_x4(b[nj][0], b[nj][1], b[nj][2], b[nj][3],
                        sb + F_B + SWZ1((b_row + nj * 16) * 128 + kb + b_cb));
            #pragma unroll
            for (int mi = 0; mi < 4; mi++)
                ldsm_x4(a[mi][0], a[mi][1], a[mi][2], a[mi][3],
                        sb + F_A + SWZ1((a_row + mi * 16) * 128 + kb + a_cb));
            #pragma unroll
            for (int mi = 0; mi < 4; mi++)
                #pragma unroll
                for (int nb = 0; nb < 4; nb++)
                    mma_f16(acc[mi][nb], a[mi][0], a[mi][1], a[mi][2], a[mi][3],
                            b[nb >> 1][(nb & 1) * 2], b[nb >> 1][(nb & 1) * 2 + 1]);
        }
        __syncthreads();
    }

    const int rr = wm * 64 + (lane >> 2);
    const int cc = wn * 32 + 2 * (lane & 3);

    if (nsc) {
        // phi (+ optional dinv*QSCALE) epilogue -> fp16 single
        #pragma unroll
        for (int mi = 0; mi < 4; mi++)
            #pragma unroll
            for (int nb = 0; nb < 4; nb++) {
                int r = rr + mi * 16;
                int c = cc + (nb >> 1) * 16 + (nb & 1) * 8;
                *(float2*)&Cs[r * C_LD + c]       = *(float2*)&acc[mi][nb][0];
                *(float2*)&Cs[(r + 8) * C_LD + c] = *(float2*)&acc[mi][nb][2];
            }
        __syncthreads();
        float inv = 1.f / (fabsf(*nsc) + 1e-6f);
        const float4 bv = *(const float4*)(bias + colb + lane * 4);
        float4 ks4 = { 0.f, 0.f, 0.f, 0.f };
        if (ksum) ks4 = *(const float4*)(ksum + colb + lane * 4);
        #pragma unroll 2
        for (int i = 0; i < 16; i++) {
            int r = warp * 16 + i;
            float4 x = *(float4*)&Cs[r * C_LD + lane * 4];
            float y0 = (fmaxf(x.x + bv.x, 0.f) + 1e-6f) * inv;
            float y1 = (fmaxf(x.y + bv.y, 0.f) + 1e-6f) * inv;
            float y2 = (fmaxf(x.z + bv.z, 0.f) + 1e-6f) * inv;
            float y3 = (fmaxf(x.w + bv.w, 0.f) + 1e-6f) * inv;
            float q0 = y0 * y0, q1 = y1 * y1, q2 = y2 * y2, q3 = y3 * y3;
            float s2 = q0 + q1 + q2 + q3;
            float s4 = q0 * q0 + q1 * q1 + q2 * q2 + q3 * q3;
            #pragma unroll
            for (int off = 16; off; off >>= 1) {
                s2 += __shfl_xor_sync(0xffffffffu, s2, off);
                s4 += __shfl_xor_sync(0xffffffffu, s4, off);
            }
            float rsc = sqrtf(s2) / (sqrtf(s4) + 1e-8f);
            float4 o;
            o.x = rsc * q0; o.y = rsc * q1; o.z = rsc * q2; o.w = rsc * q3;
            if (ksum) {
                float dd = o.x * ks4.x + o.y * ks4.y + o.z * ks4.z + o.w * ks4.w;
                #pragma unroll
                for (int off = 16; off; off >>= 1) dd += __shfl_xor_sync(0xffffffffu, dd, off);
                float sc = QSCALE / (dd + 1e-6f);
                o.x *= sc; o.y *= sc; o.z *= sc; o.w *= sc;
            }
            size_t base = (size_t)(row0 + r) * HD + colb + lane * 4;
            uint2 hv = { pack_h2(__float2half_rn(o.x), __float2half_rn(o.y)),
                         pack_h2(__float2half_rn(o.z), __float2half_rn(o.w)) };
            *(uint2*)(OutF + base) = hv;
        }
    } else {
        // direct epilogue (V projection)
        #pragma unroll
        for (int mi = 0; mi < 4; mi++)
            #pragma unroll
            for (int nb = 0; nb < 4; nb++) {
                int r = rr + mi * 16;
                int c = cc + (nb >> 1) * 16 + (nb & 1) * 8;
                float b0 = bias[colb + c];
                float b1 = bias[colb + c + 1];
                *(uint32_t*)(OutF + (size_t)(row0 + r) * HD + colb + c) =
                    pack_h2(__float2half_rn(acc[mi][nb][0] + b0),
                            __float2half_rn(acc[mi][nb][1] + b1));
                *(uint32_t*)(OutF + (size_t)(row0 + r + 8) * HD + colb + c) =
                    pack_h2(__float2half_rn(acc[mi][nb][2] + b0),
                            __float2half_rn(acc[mi][nb][3] + b1));
            }
    }
}

// ---------------- bf16 3-pass GEMM (vss only) ----------------
#define S_AH 0
#define S_AL 16384
#define S_BH 32768
#define S_BL 49152
#define MM_SMEM 65536

__global__ void __launch_bounds__(256, 2) mm_gemm_vss(
    const __nv_bfloat16* __restrict__ Ah, const __nv_bfloat16* __restrict__ Al,
    const __nv_bfloat16* __restrict__ Bh, const __nv_bfloat16* __restrict__ Bl,
    const float* __restrict__ bias, float* __restrict__ Cf) {
    extern __shared__ __align__(16) char smem[];
    const uint32_t sb = smem_u32(smem);
    const int tid = threadIdx.x;
    const int lane = tid & 31, warp = tid >> 5;
    const int wm = warp >> 2, wn = warp & 3;
    const int row0 = blockIdx.x * 128;

    float acc[4][4][4];
    #pragma unroll
    for (int i = 0; i < 4; i++)
        #pragma unroll
        for (int j = 0; j < 4; j++)
            #pragma unroll
            for (int e = 0; e < 4; e++) acc[i][j][e] = 0.f;

    const uint32_t a_row = wm * 64 + (lane & 15);
    const uint32_t a_cb  = (lane >> 4) * 16;
    const uint32_t b_row = wn * 32 + (lane & 7) + ((lane >> 4) & 1) * 8;
    const uint32_t b_cb  = ((lane >> 3) & 1) * 16;

    #pragma unroll
    for (int kc = 0; kc < 2; kc++) {
        #pragma unroll
        for (int it = 0; it < 4; it++) {
            int idx = it * 256 + tid;
            int r = idx >> 3, c8 = idx & 7;
            size_t ga = (size_t)(row0 + r) * DD + kc * 64 + c8 * 8;
            size_t gb = (size_t)r * DD + kc * 64 + c8 * 8;
            uint32_t off = SWZ1((uint32_t)(r * 128 + c8 * 16));
            cp16(sb + S_AH + off, Ah + ga);
            cp16(sb + S_AL + off, Al + ga);
            cp16(sb + S_BH + off, Bh + gb);
            cp16(sb + S_BL + off, Bl + gb);
        }
        CP_COMMIT();
        CP_WAIT0();
        __syncthreads();

        #pragma unroll
        for (int k = 0; k < 4; k++) {
            const uint32_t kb = k * 32;
            uint32_t ah[4][4], al[4][4], b[2][4];
            #pragma unroll
            for (int mi = 0; mi < 4; mi++) {
                uint32_t ra = SWZ1((a_row + mi * 16) * 128 + kb + a_cb);
                ldsm_x4(ah[mi][0], ah[mi][1], ah[mi][2], ah[mi][3], sb + S_AH + ra);
                ldsm_x4(al[mi][0], al[mi][1], al[mi][2], al[mi][3], sb + S_AL + ra);
            }
            #pragma unroll
            for (int nj = 0; nj < 2; nj++)
                ldsm_x4(b[nj][0], b[nj][1], b[nj][2], b[nj][3],
                        sb + S_BH + SWZ1((b_row + nj * 16) * 128 + kb + b_cb));
            #pragma unroll
            for (int mi = 0; mi < 4; mi++)
                #pragma unroll
                for (int nb = 0; nb < 4; nb++) {
                    mma_bf16(acc[mi][nb], ah[mi][0], ah[mi][1], ah[mi][2], ah[mi][3],
                             b[nb >> 1][(nb & 1) * 2], b[nb >> 1][(nb & 1) * 2 + 1]);
                    mma_bf16(acc[mi][nb], al[mi][0], al[mi][1], al[mi][2], al[mi][3],
                             b[nb >> 1][(nb & 1) * 2], b[nb >> 1][(nb & 1) * 2 + 1]);
                }
            #pragma unroll
            for (int nj = 0; nj < 2; nj++)
                ldsm_x4(b[nj][0], b[nj][1], b[nj][2], b[nj][3],
                        sb + S_BL + SWZ1((b_row + nj * 16) * 128 + kb + b_cb));
            #pragma unroll
            for (int mi = 0; mi < 4; mi++)
                #pragma unroll
                for (int nb = 0; nb < 4; nb++)
                    mma_bf16(acc[mi][nb], ah[mi][0], ah[mi][1], ah[mi][2], ah[mi][3],
                             b[nb >> 1][(nb & 1) * 2], b[nb >> 1][(nb & 1) * 2 + 1]);
        }
        __syncthreads();
    }

    const int rr = wm * 64 + (lane >> 2);
    const int cc = wn * 32 + 2 * (lane & 3);
    #pragma unroll
    for (int mi = 0; mi < 4; mi++)
        #pragma unroll
        for (int nb = 0; nb < 4; nb++) {
            int r = rr + mi * 16;
            int c = cc + (nb >> 1) * 16 + (nb & 1) * 8;
            float b0 = bias[c], b1 = bias[c + 1];
            float2 v0 = { acc[mi][nb][0] + b0, acc[mi][nb][1] + b1 };
            float2 v1 = { acc[mi][nb][2] + b0, acc[mi][nb][3] + b1 };
            *(float2*)(Cf + (size_t)(row0 + r) * DD + c) = v0;
            *(float2*)(Cf + (size_t)(row0 + r + 8) * DD + c) = v1;
        }
}

// ---------------- ktv via fp16 1-pass mma ----------------
#define T_P 0
#define T_V 16384
#define KTV_SMEM 32768

__global__ void __launch_bounds__(256, 2) ktv_mma() {
    extern __shared__ __align__(16) char smem[];
    const uint32_t sb = smem_u32(smem);
    const int h = blockIdx.x;
    const int chunk = blockIdx.y;
    const int tid = threadIdx.x;
    const int lane = tid & 31, warp = tid >> 5;
    const int wm = warp >> 2, wn = warp & 3;
    const int n0 = chunk * (NR / KC2);

    float acc[4][4][4];
    #pragma unroll
    for (int i = 0; i < 4; i++)
        #pragma unroll
        for (int j = 0; j < 4; j++)
            #pragma unroll
            for (int e = 0; e < 4; e++) acc[i][j][e] = 0.f;
    float ks = 0.f;

    const uint32_t a_kr = (lane & 7) + ((lane >> 4) & 1) * 8;
    const uint32_t a_cl = wm * 64 + ((lane >> 3) & 1) * 8;
    const uint32_t b_kr = (lane & 7) + ((lane >> 3) & 1) * 8;
    const uint32_t b_cl = wn * 32 + ((lane >> 4) & 1) * 8;

    for (int s = 0; s < (NR / KC2) / 64; s++) {
        const int nb = n0 + s * 64;
        #pragma unroll
        for (int it = 0; it < 4; it++) {
            int idx = it * 256 + tid;
            int r = idx >> 4, c16 = idx & 15;
            size_t gb = (size_t)(nb + r) * HD + h * DD + c16 * 8;
            uint32_t off = SWZ((uint32_t)(r * 256 + c16 * 16));
            cp16(sb + T_P + off, g_Kf + gb);
            cp16(sb + T_V + off, g_Vf + gb);
        }
        CP_COMMIT();
        CP_WAIT0();
        __syncthreads();

        #pragma unroll
        for (int kk = 0; kk < 4; kk++) {
            uint32_t a[4][4], b[2][4];
            #pragma unroll
            for (int nj = 0; nj < 2; nj++)
                ldsm_x4_t(b[nj][0], b[nj][1], b[nj][2], b[nj][3],
                          sb + T_V + SWZ((kk * 16 + b_kr) * 256 + (b_cl + nj * 16) * 2));
            #pragma unroll
            for (int mi = 0; mi < 4; mi++)
                ldsm_x4_t(a[mi][0], a[mi][1], a[mi][2], a[mi][3],
                          sb + T_P + SWZ((kk * 16 + a_kr) * 256 + (a_cl + mi * 16) * 2));
            #pragma unroll
            for (int mi = 0; mi < 4; mi++)
                #pragma unroll
                for (int nbt = 0; nbt < 4; nbt++)
                    mma_f16(acc[mi][nbt], a[mi][0], a[mi][1], a[mi][2], a[mi][3],
                            b[nbt >> 1][(nbt & 1) * 2], b[nbt >> 1][(nbt & 1) * 2 + 1]);
        }
        if (tid < 128) {
            #pragma unroll 4
            for (int r = 0; r < 64; r++) {
                uint32_t off = SWZ((uint32_t)(r * 256 + tid * 2));
                ks += __half2float(*(const __half*)(smem + T_P + off));
            }
        }
        __syncthreads();
    }

    float* outp = g_ktvp + ((size_t)chunk * NH + h) * (DD * DD);
    const int rr = wm * 64 + (lane >> 2);
    const int cc = wn * 32 + 2 * (lane & 3);
    #pragma unroll
    for (int mi = 0; mi < 4; mi++)
        #pragma unroll
        for (int nbt = 0; nbt < 4; nbt++) {
            int r = rr + mi * 16;
            int c = cc + (nbt >> 1) * 16 + (nbt & 1) * 8;
            *(float2*)&outp[r * DD + c]       = *(float2*)&acc[mi][nbt][0];
            *(float2*)&outp[(r + 8) * DD + c] = *(float2*)&acc[mi][nbt][2];
        }
    if (tid < 128) g_ksump[(chunk * NH + h) * DD + tid] = ks;
}

__global__ void ktv_reduce_kernel() {
    int idx = blockIdx.x * blockDim.x + threadIdx.x;
    if (idx < NH * DD * DD) {
        float s = 0.f;
        #pragma unroll 8
        for (int c = 0; c < KC2; c++) s += g_ktvp[(size_t)c * NH * DD * DD + idx];
        int h = idx >> 14, m = (idx >> 7) & 127, d = idx & 127;
        g_ktvTf[(h << 14) + (d << 7) + m] = __float2half_rn(s);
    }
    if (idx < NH * DD) {
        float s = 0.f;
        #pragma unroll 8
        for (int c = 0; c < KC2; c++) s += g_ksump[c * NH * DD + idx];
        g_ksum[idx] = s;
    }
}

// ---------------- fused numerator + combine (fp16 1-pass): out[n][129] ----------------
#define A_A 0
#define A_B 16384
#define AT_SMEM (128 * C_LD * 4)   // 67584

__global__ void __launch_bounds__(256, 2) attn_out(const float* __restrict__ att,
                                                   float* __restrict__ out) {
    extern __shared__ __align__(16) char smem[];
    const uint32_t sb = smem_u32(smem);
    float* Cs = (float*)smem;
    const int tid = threadIdx.x;
    const int lane = tid & 31, warp = tid >> 5;
    const int wm = warp >> 2, wn = warp & 3;
    const int row0 = blockIdx.x * 128;

    float acc[4][4][4];
    #pragma unroll
    for (int i = 0; i < 4; i++)
        #pragma unroll
        for (int j = 0; j < 4; j++)
            #pragma unroll
            for (int e = 0; e < 4; e++) acc[i][j][e] = 0.f;

    const uint32_t a_row = wm * 64 + (lane & 15);
    const uint32_t a_cb  = (lane >> 4) * 16;
    const uint32_t b_row = wn * 32 + (lane & 7) + ((lane >> 4) & 1) * 8;
    const uint32_t b_cb  = ((lane >> 3) & 1) * 16;

    for (int kc = 0; kc < 16; kc++) {
        const int h = kc >> 1;
        const __half* B = g_ktvTf + h * (DD * DD) + (kc & 1) * 64;
        #pragma unroll
        for (int it = 0; it < 4; it++) {
            int idx = it * 256 + tid;
            int r = idx >> 3, c8 = idx & 7;
            size_t ga = (size_t)(row0 + r) * HD + kc * 64 + c8 * 8;
            size_t gb = (size_t)r * DD + c8 * 8;
            uint32_t off = SWZ1((uint32_t)(r * 128 + c8 * 16));
            cp16(sb + A_A + off, g_Qf + ga);
            cp16(sb + A_B + off, B + gb);
        }
        CP_COMMIT();
        CP_WAIT0();
        __syncthreads();

        #pragma unroll
        for (int k = 0; k < 4; k++) {
            const uint32_t kb = k * 32;
            uint32_t a[4][4], b[2][4];
            #pragma unroll
            for (int nj = 0; nj < 2; nj++)
                ldsm_x4(b[nj][0], b[nj][1], b[nj][2], b[nj][3],
                        sb + A_B + SWZ1((b_row + nj * 16) * 128 + kb + b_cb));
            #pragma unroll
            for (int mi = 0; mi < 4; mi++)
                ldsm_x4(a[mi][0], a[mi][1], a[mi][2], a[mi][3],
                        sb + A_A + SWZ1((a_row + mi * 16) * 128 + kb + a_cb));
            #pragma unroll
            for (int mi = 0; mi < 4; mi++)
                #pragma unroll
                for (int nb = 0; nb < 4; nb++)
                    mma_f16(acc[mi][nb], a[mi][0], a[mi][1], a[mi][2], a[mi][3],
                            b[nb >> 1][(nb & 1) * 2], b[nb >> 1][(nb & 1) * 2 + 1]);
        }
        __syncthreads();
    }

    // dump acc, then final epilogue: mean + att + time coordinate
    {
        const int rr = wm * 64 + (lane >> 2);
        const int cc = wn * 32 + 2 * (lane & 3);
        #pragma unroll
        for (int mi = 0; mi < 4; mi++)
            #pragma unroll
            for (int nb = 0; nb < 4; nb++) {
                int r = rr + mi * 16;
                int c = cc + (nb >> 1) * 16 + (nb & 1) * 8;
                *(float2*)&Cs[r * C_LD + c]       = *(float2*)&acc[mi][nb][0];
                *(float2*)&Cs[(r + 8) * C_LD + c] = *(float2*)&acc[mi][nb][2];
            }
    }
    __syncthreads();
    #pragma unroll 2
    for (int i = 0; i < 16; i++) {
        int r = warp * 16 + i;
        int n = row0 + r;
        float4 x = *(float4*)&Cs[r * C_LD + lane * 4];
        float4 a4 = *(const float4*)(att + (size_t)n * DD + lane * 4);
        float v0 = x.x * OSCALE + a4.x;
        float v1 = x.y * OSCALE + a4.y;
        float v2 = x.z * OSCALE + a4.z;
        float v3 = x.w * OSCALE + a4.w;
        float ssum = v0 * v0 + v1 * v1 + v2 * v2 + v3 * v3;
        #pragma unroll
        for (int off = 16; off; off >>= 1) ssum += __shfl_xor_sync(0xffffffffu, ssum, off);
        float t = sqrtf(ssum + 1.0f);
        float* op = out + (size_t)n * 129;
        if (lane == 0) op[0] = t;
        op[1 + lane * 4 + 0] = v0;
        op[1 + lane * 4 + 1] = v1;
        op[1 + lane * 4 + 2] = v2;
        op[1 + lane * 4 + 3] = v3;
    }
}

// ---------------- launch ----------------
extern "C" void kernel_launch(void* const* d_in, const int* in_sizes, int n_in,
                              void* d_out, int out_size) {
    const float* xq   = (const float*)d_in[0];
    const float* xs   = (const float*)d_in[1];
    const float* Wq_w = (const float*)d_in[2];
    const float* Wq_b = (const float*)d_in[3];
    const float* Wk_w = (const float*)d_in[4];
    const float* Wk_b = (const float*)d_in[5];
    const float* Wv_w = (const float*)d_in[6];
    const float* Wv_b = (const float*)d_in[7];
    const float* vmw  = (const float*)d_in[8];
    const float* vmb  = (const float*)d_in[9];
    const float* nsc  = (const float*)d_in[10];
    float* out = (float*)d_out;

    float *pcfuse, *patt, *pksum;
    __nv_bfloat16 *pWfh, *pWfl, *pXsh, *pXsl;
    __half *pWqf, *pWkf, *pWvf, *pXf, *pXqf, *pKf, *pVf, *pQf;
    cudaGetSymbolAddress((void**)&pcfuse, g_cfuse);
    cudaGetSymbolAddress((void**)&patt, g_att);
    cudaGetSymbolAddress((void**)&pksum, g_ksum);
    cudaGetSymbolAddress((void**)&pWfh, g_WfTh);
    cudaGetSymbolAddress((void**)&pWfl, g_WfTl);
    cudaGetSymbolAddress((void**)&pXsh, g_Xsh);
    cudaGetSymbolAddress((void**)&pXsl, g_Xsl);
    cudaGetSymbolAddress((void**)&pWqf, g_Wqf);
    cudaGetSymbolAddress((void**)&pWkf, g_Wkf);
    cudaGetSymbolAddress((void**)&pWvf, g_Wvf);
    cudaGetSymbolAddress((void**)&pXf, g_Xf);
    cudaGetSymbolAddress((void**)&pXqf, g_Xqf);
    cudaGetSymbolAddress((void**)&pKf, g_Kf);
    cudaGetSymbolAddress((void**)&pVf, g_Vf);
    cudaGetSymbolAddress((void**)&pQf, g_Qf);

    cudaFuncSetAttribute(proj_f16, cudaFuncAttributeMaxDynamicSharedMemorySize, PJ_SMEM);
    cudaFuncSetAttribute(mm_gemm_vss, cudaFuncAttributeMaxDynamicSharedMemorySize, MM_SMEM);
    cudaFuncSetAttribute(ktv_mma, cudaFuncAttributeMaxDynamicSharedMemorySize, KTV_SMEM);
    cudaFuncSetAttribute(attn_out, cudaFuncAttributeMaxDynamicSharedMemorySize, AT_SMEM);

    split_x_kernel<<<(NR * DD / 4 + 255) / 256, 256>>>(xs, xq);
    prep_kernel<<<(3 * 131072 + DD * DD + 255) / 256, 256>>>(Wq_w, Wk_w, Wv_w);
    wfuse_kernel<<<(DD * DD + 255) / 256, 256>>>(Wv_b, vmw, vmb);

    dim3 gproj(NR / 128, NH);
    // K projection + fused phi -> Kf (fp16 1-pass)
    proj_f16<<<gproj, 256, PJ_SMEM>>>(pXf, pWkf, Wk_b, nsc, nullptr, pKf);
    // V projection -> Vf (fp16 1-pass, direct)
    proj_f16<<<gproj, 256, PJ_SMEM>>>(pXf, pWvf, Wv_b, nullptr, nullptr, pVf);
    // ktv + ksum (fp16 1-pass)
    ktv_mma<<<dim3(NH, KC2), 256, KTV_SMEM>>>();
    ktv_reduce_kernel<<<(NH * DD * DD + 255) / 256, 256>>>();
    // fused vss: xs @ WfuseT -> att (bf16 3-pass)
    mm_gemm_vss<<<dim3(NR / 128, 1), 256, MM_SMEM>>>(pXsh, pXsl, pWfh, pWfl, pcfuse, patt);
    // Q projection + phi + dinv*2^20 -> Qf (fp16 1-pass)
    proj_f16<<<gproj, 256, PJ_SMEM>>>(pXqf, pWqf, Wq_b, nsc, pksum, pQf);
    // fused numerator + combine + time coordinate -> out [NR][129]
    attn_out<<<NR / 128, 256, AT_SMEM>>>(patt, out);
}

// round 11
// speedup vs baseline: 2.1674x; 1.0874x over previous
#include <cuda_runtime.h>
#include <cuda_bf16.h>
#include <cuda_fp16.h>
#include <cstdint>
#include <math.h>

#define NR 32768
#define NH 8
#define DD 128
#define HD 1024     // NH * DD
#define KC2 64      // split-K chunks for ktv (512 rows each)
#define QSCALE 1048576.f          // 2^20 pre-scale for Q*dinv (fp16 range guard)
#define OSCALE (0.125f / 1048576.f)

// ---------------- scratch (static device memory; no allocations) ----------------
__device__ __half g_Wqf[DD * HD], g_Wkf[DD * HD], g_Wvf[DD * HD];  // fp16 single, K-major
__device__ float g_Wvm[DD * DD];
__device__ __nv_bfloat16 g_WfTh[DD * DD], g_WfTl[DD * DD];         // fused vss weight
__device__ float g_cfuse[DD];
__device__ float g_att[(size_t)NR * DD];
__device__ __nv_bfloat16 g_Xsh[(size_t)NR * DD], g_Xsl[(size_t)NR * DD];  // xs bf16 pair (vss)
__device__ __half g_Xf[(size_t)NR * DD];                                  // xs fp16 single
__device__ __half g_Xqf[(size_t)NR * DD];                                 // xq fp16 single
__device__ __half g_Kf[(size_t)NR * HD];                                  // phi_ks fp16 single
__device__ __half g_Vf[(size_t)NR * HD];                                  // v fp16 single
__device__ __half g_Qf[(size_t)NR * HD];                                  // Q*dinv*2^20 single
__device__ __half g_ktvTf[NH * DD * DD];                                  // [h][d][m] fp16
__device__ float g_ksum[NH * DD];
__device__ float g_ktvp[(size_t)KC2 * NH * DD * DD];
__device__ float g_ksump[KC2 * NH * DD];

// ---------------- helpers ----------------
__device__ __forceinline__ uint32_t smem_u32(const void* p) {
    uint32_t a;
    asm("{ .reg .u64 t; cvta.to.shared.u64 t, %1; cvt.u32.u64 %0, t; }" : "=r"(a) : "l"(p));
    return a;
}
__device__ __forceinline__ uint32_t pack_bf2(__nv_bfloat16 a, __nv_bfloat16 b) {
    __nv_bfloat162 t; t.x = a; t.y = b;
    return *reinterpret_cast<uint32_t*>(&t);
}
__device__ __forceinline__ uint32_t pack_h2(__half a, __half b) {
    __half2 t; t.x = a; t.y = b;
    return *reinterpret_cast<uint32_t*>(&t);
}
__device__ __forceinline__ void split_bf(float x, __nv_bfloat16& h, __nv_bfloat16& l) {
    h = __float2bfloat16_rn(x);
    l = __float2bfloat16_rn(x - __bfloat162float(h));
}
#define SWZ(o)  ((o) ^ ((((o) >> 8) & 7) << 4))
#define SWZ1(o) ((o) ^ ((((o) >> 7) & 7) << 4))

__device__ __forceinline__ void ldsm_x4(uint32_t& r0, uint32_t& r1, uint32_t& r2,
                                        uint32_t& r3, uint32_t addr) {
    asm volatile("ldmatrix.sync.aligned.m8n8.x4.shared.b16 {%0,%1,%2,%3}, [%4];"
                 : "=r"(r0), "=r"(r1), "=r"(r2), "=r"(r3) : "r"(addr));
}
__device__ __forceinline__ void ldsm_x4_t(uint32_t& r0, uint32_t& r1, uint32_t& r2,
                                          uint32_t& r3, uint32_t addr) {
    asm volatile("ldmatrix.sync.aligned.m8n8.x4.trans.shared.b16 {%0,%1,%2,%3}, [%4];"
                 : "=r"(r0), "=r"(r1), "=r"(r2), "=r"(r3) : "r"(addr));
}
__device__ __forceinline__ void mma_bf16(float* c, uint32_t a0, uint32_t a1,
                                         uint32_t a2, uint32_t a3,
                                         uint32_t b0, uint32_t b1) {
    asm volatile("mma.sync.aligned.m16n8k16.row.col.f32.bf16.bf16.f32 "
                 "{%0,%1,%2,%3}, {%4,%5,%6,%7}, {%8,%9}, {%0,%1,%2,%3};"
                 : "+f"(c[0]), "+f"(c[1]), "+f"(c[2]), "+f"(c[3])
                 : "r"(a0), "r"(a1), "r"(a2), "r"(a3), "r"(b0), "r"(b1));
}
__device__ __forceinline__ void mma_f16(float* c, uint32_t a0, uint32_t a1,
                                        uint32_t a2, uint32_t a3,
                                        uint32_t b0, uint32_t b1) {
    asm volatile("mma.sync.aligned.m16n8k16.row.col.f32.f16.f16.f32 "
                 "{%0,%1,%2,%3}, {%4,%5,%6,%7}, {%8,%9}, {%0,%1,%2,%3};"
                 : "+f"(c[0]), "+f"(c[1]), "+f"(c[2]), "+f"(c[3])
                 : "r"(a0), "r"(a1), "r"(a2), "r"(a3), "r"(b0), "r"(b1));
}
__device__ __forceinline__ void cp16(uint32_t saddr, const void* g) {
    asm volatile("cp.async.cg.shared.global [%0], [%1], 16;" :: "r"(saddr), "l"(g));
}
#define CP_COMMIT() asm volatile("cp.async.commit_group;" ::: "memory")
#define CP_WAIT0()  asm volatile("cp.async.wait_group 0;" ::: "memory")
#define CP_WAIT1()  asm volatile("cp.async.wait_group 1;" ::: "memory")

// ---------------- input split ----------------
__global__ void split_x_kernel(const float* __restrict__ xs, const float* __restrict__ xq) {
    int idx = blockIdx.x * blockDim.x + threadIdx.x;
    if (idx >= NR * DD / 4) return;
    float4 s = *(const float4*)(xs + (size_t)idx * 4);
    float4 q = *(const float4*)(xq + (size_t)idx * 4);
    {   // xs bf16 pair (vss)
        __nv_bfloat16 h0, h1, h2, h3, l0, l1, l2, l3;
        split_bf(s.x, h0, l0); split_bf(s.y, h1, l1);
        split_bf(s.z, h2, l2); split_bf(s.w, h3, l3);
        uint2 hv = { pack_bf2(h0, h1), pack_bf2(h2, h3) };
        uint2 lv = { pack_bf2(l0, l1), pack_bf2(l2, l3) };
        *(uint2*)(g_Xsh + (size_t)idx * 4) = hv;
        *(uint2*)(g_Xsl + (size_t)idx * 4) = lv;
    }
    {   // fp16 singles
        uint2 sv = { pack_h2(__float2half_rn(s.x), __float2half_rn(s.y)),
                     pack_h2(__float2half_rn(s.z), __float2half_rn(s.w)) };
        uint2 qv = { pack_h2(__float2half_rn(q.x), __float2half_rn(q.y)),
                     pack_h2(__float2half_rn(q.z), __float2half_rn(q.w)) };
        *(uint2*)(g_Xf + (size_t)idx * 4) = sv;
        *(uint2*)(g_Xqf + (size_t)idx * 4) = qv;
    }
}

// ---------------- weight prep ----------------
__global__ void prep_kernel(const float* __restrict__ Wq,
                            const float* __restrict__ Wk,
                            const float* __restrict__ Wv) {
    int idx = blockIdx.x * blockDim.x + threadIdx.x;
    if (idx < 3 * 131072) {
        int which = idx / 131072;
        int e = idx % 131072;
        if (which == 0)      g_Wqf[e] = __float2half_rn(Wq[e]);
        else if (which == 1) g_Wkf[e] = __float2half_rn(Wk[e]);
        else                 g_Wvf[e] = __float2half_rn(Wv[e]);
    } else if (idx < 3 * 131072 + DD * DD) {
        int e = idx - 3 * 131072;
        int i = e & 127, d = e >> 7;
        float s = 0.f;
        #pragma unroll
        for (int h = 0; h < NH; h++) s += Wv[((size_t)(h * DD + d)) * DD + i];
        g_Wvm[d * DD + i] = s * 0.125f;
    }
}

__global__ void wfuse_kernel(const float* __restrict__ Wv_b,
                             const float* __restrict__ vmw,
                             const float* __restrict__ vmb) {
    int idx = blockIdx.x * blockDim.x + threadIdx.x;
    if (idx >= DD * DD) return;
    int o = idx & 127, i = idx >> 7;
    float acc = 0.f;
    for (int d = 0; d < DD; d++) acc += g_Wvm[d * DD + i] * vmw[o * DD + d];
    __nv_bfloat16 h, l;
    split_bf(acc, h, l);
    g_WfTh[o * DD + i] = h;
    g_WfTl[o * DD + i] = l;
    if (idx < DD) {
        float c = 0.f;
        for (int d = 0; d < DD; d++) {
            float bm = 0.f;
            #pragma unroll
            for (int hh = 0; hh < NH; hh++) bm += Wv_b[hh * DD + d];
            c += 0.125f * bm * vmw[idx * DD + d];
        }
        g_cfuse[idx] = c + vmb[idx];
    }
}

// ---------------- head-looped projection kernels ----------------
// smem: A (2x16KB sub-panels) | B buf0 (32KB) | B buf1 (32KB) | red 128x12 f32
#define PA   0
#define PB0  32768
#define PB1  65536
#define PRED 98304
#define HP_SMEM (98304 + 128 * 12 * 4)   // 104448

// Inner GEMM: C(acc) = Atile @ Bpanel^T, K=128, from resident smem panels.
__device__ __forceinline__ void head_mma(float acc[4][4][4], uint32_t sb,
                                         uint32_t bbuf, uint32_t a_row, uint32_t a_cb,
                                         uint32_t b_row, uint32_t b_cb) {
    #pragma unroll
    for (int i = 0; i < 4; i++)
        #pragma unroll
        for (int j = 0; j < 4; j++)
            #pragma unroll
            for (int e = 0; e < 4; e++) acc[i][j][e] = 0.f;
    #pragma unroll
    for (int kc = 0; kc < 2; kc++) {
        #pragma unroll
        for (int k = 0; k < 4; k++) {
            const uint32_t kb = k * 32;
            uint32_t a[4][4], b[2][4];
            #pragma unroll
            for (int nj = 0; nj < 2; nj++)
                ldsm_x4(b[nj][0], b[nj][1], b[nj][2], b[nj][3],
                        bbuf + kc * 16384 + SWZ1((b_row + nj * 16) * 128 + kb + b_cb));
            #pragma unroll
            for (int mi = 0; mi < 4; mi++)
                ldsm_x4(a[mi][0], a[mi][1], a[mi][2], a[mi][3],
                        sb + PA + kc * 16384 + SWZ1((a_row + mi * 16) * 128 + kb + a_cb));
            #pragma unroll
            for (int mi = 0; mi < 4; mi++)
                #pragma unroll
                for (int nb = 0; nb < 4; nb++)
                    mma_f16(acc[mi][nb], a[mi][0], a[mi][1], a[mi][2], a[mi][3],
                            b[nb >> 1][(nb & 1) * 2], b[nb >> 1][(nb & 1) * 2 + 1]);
        }
    }
}

__device__ __forceinline__ void stage_b(uint32_t dst, const __half* src, int tid) {
    #pragma unroll
    for (int it = 0; it < 8; it++) {
        int idx = it * 256 + tid;
        int r = idx >> 4, kc = (idx >> 3) & 1, c8 = idx & 7;
        uint32_t off = kc * 16384 + SWZ1((uint32_t)(r * 128 + c8 * 16));
        cp16(dst + off, src + (size_t)r * DD + kc * 64 + c8 * 8);
    }
}

// KV: j=0..15 alternating Wk (phi epilogue) / Wv (direct epilogue)
__global__ void __launch_bounds__(256, 2) kv_proj(
    const float* __restrict__ Wk_b, const float* __restrict__ Wv_b,
    const float* __restrict__ nsc) {
    extern __shared__ __align__(16) char smem[];
    const uint32_t sb = smem_u32(smem);
    float* red = (float*)(smem + PRED);
    const int tid = threadIdx.x;
    const int lane = tid & 31, warp = tid >> 5;
    const int wm = warp >> 2, wn = warp & 3;
    const int row0 = blockIdx.x * 128;

    const uint32_t a_row = wm * 64 + (lane & 15);
    const uint32_t a_cb  = (lane >> 4) * 16;
    const uint32_t b_row = wn * 32 + (lane & 7) + ((lane >> 4) & 1) * 8;
    const uint32_t b_cb  = ((lane >> 3) & 1) * 16;
    const float inv = 1.f / (fabsf(*nsc) + 1e-6f);

    // stage A (once) + B for j=0
    #pragma unroll
    for (int it = 0; it < 8; it++) {
        int idx = it * 256 + tid;
        int r = idx >> 4, kc = (idx >> 3) & 1, c8 = idx & 7;
        uint32_t off = kc * 16384 + SWZ1((uint32_t)(r * 128 + c8 * 16));
        cp16(sb + PA + off, g_Xf + (size_t)(row0 + r) * DD + kc * 64 + c8 * 8);
        cp16(sb + PB0 + off, g_Wkf + (size_t)r * DD + kc * 64 + c8 * 8);
    }
    CP_COMMIT();

    float acc[4][4][4];
    for (int j = 0; j < 16; j++) {
        const int h = j >> 1;
        if (j < 15) {
            int jn = j + 1;
            const __half* src = (jn & 1) ? g_Wvf + (jn >> 1) * (DD * DD)
                                         : g_Wkf + (jn >> 1) * (DD * DD);
            stage_b(sb + ((jn & 1) ? PB1 : PB0), src, tid);
            CP_COMMIT();
            CP_WAIT1();
        } else {
            CP_WAIT0();
        }
        __syncthreads();

        head_mma(acc, sb, sb + ((j & 1) ? PB1 : PB0), a_row, a_cb, b_row, b_cb);

        if ((j & 1) == 0) {
            // ---- phi epilogue (K head h), register-resident ----
            const float* bias = Wk_b + h * DD;
            float bc[8];
            #pragma unroll
            for (int nb = 0; nb < 4; nb++) {
                int c = wn * 32 + (nb >> 1) * 16 + (nb & 1) * 8 + 2 * (lane & 3);
                bc[nb * 2] = bias[c]; bc[nb * 2 + 1] = bias[c + 1];
            }
            #pragma unroll
            for (int rh = 0; rh < 8; rh++) {
                int mi = rh >> 1, half = rh & 1;
                int r = wm * 64 + mi * 16 + half * 8 + (lane >> 2);
                float s2 = 0.f, s4 = 0.f;
                #pragma unroll
                for (int nb = 0; nb < 4; nb++)
                    #pragma unroll
                    for (int e = 0; e < 2; e++) {
                        float x = acc[mi][nb][half * 2 + e] + bc[nb * 2 + e];
                        float y = (fmaxf(x, 0.f) + 1e-6f) * inv;
                        float q = y * y;
                        s2 += q; s4 += q * q;
                    }
                s2 += __shfl_xor_sync(0xffffffffu, s2, 1);
                s2 += __shfl_xor_sync(0xffffffffu, s2, 2);
                s4 += __shfl_xor_sync(0xffffffffu, s4, 1);
                s4 += __shfl_xor_sync(0xffffffffu, s4, 2);
                if ((lane & 3) == 0) {
                    red[r * 12 + wn * 2] = s2;
                    red[r * 12 + wn * 2 + 1] = s4;
                }
            }
            __syncthreads();
            #pragma unroll
            for (int rh = 0; rh < 8; rh++) {
                int mi = rh >> 1, half = rh & 1;
                int r = wm * 64 + mi * 16 + half * 8 + (lane >> 2);
                float s2 = red[r * 12] + red[r * 12 + 2] + red[r * 12 + 4] + red[r * 12 + 6];
                float s4 = red[r * 12 + 1] + red[r * 12 + 3] + red[r * 12 + 5] + red[r * 12 + 7];
                float rsc = sqrtf(s2) / (sqrtf(s4) + 1e-8f);
                #pragma unroll
                for (int nb = 0; nb < 4; nb++) {
                    int c = wn * 32 + (nb >> 1) * 16 + (nb & 1) * 8 + 2 * (lane & 3);
                    float x0 = acc[mi][nb][half * 2] + bc[nb * 2];
                    float x1 = acc[mi][nb][half * 2 + 1] + bc[nb * 2 + 1];
                    float y0 = (fmaxf(x0, 0.f) + 1e-6f) * inv;
                    float y1 = (fmaxf(x1, 0.f) + 1e-6f) * inv;
                    *(uint32_t*)(g_Kf + (size_t)(row0 + r) * HD + h * DD + c) =
                        pack_h2(__float2half_rn(rsc * y0 * y0),
                                __float2half_rn(rsc * y1 * y1));
                }
            }
        } else {
            // ---- direct epilogue (V head h) ----
            const float* bias = Wv_b + h * DD;
            #pragma unroll
            for (int nb = 0; nb < 4; nb++) {
                int c = wn * 32 + (nb >> 1) * 16 + (nb & 1) * 8 + 2 * (lane & 3);
                float b0 = bias[c], b1 = bias[c + 1];
                #pragma unroll
                for (int mi = 0; mi < 4; mi++) {
                    int r = wm * 64 + mi * 16 + (lane >> 2);
                    *(uint32_t*)(g_Vf + (size_t)(row0 + r) * HD + h * DD + c) =
                        pack_h2(__float2half_rn(acc[mi][nb][0] + b0),
                                __float2half_rn(acc[mi][nb][1] + b1));
                    *(uint32_t*)(g_Vf + (size_t)(row0 + r + 8) * HD + h * DD + c) =
                        pack_h2(__float2half_rn(acc[mi][nb][2] + b0),
                                __float2half_rn(acc[mi][nb][3] + b1));
                }
            }
        }
        __syncthreads();
    }
}

// Q: j=0..7 heads, phi + dinv*QSCALE epilogue
__global__ void __launch_bounds__(256, 2) q_proj(
    const float* __restrict__ Wq_b, const float* __restrict__ nsc) {
    extern __shared__ __align__(16) char smem[];
    const uint32_t sb = smem_u32(smem);
    float* red = (float*)(smem + PRED);
    const int tid = threadIdx.x;
    const int lane = tid & 31, warp = tid >> 5;
    const int wm = warp >> 2, wn = warp & 3;
    const int row0 = blockIdx.x * 128;

    const uint32_t a_row = wm * 64 + (lane & 15);
    const uint32_t a_cb  = (lane >> 4) * 16;
    const uint32_t b_row = wn * 32 + (lane & 7) + ((lane >> 4) & 1) * 8;
    const uint32_t b_cb  = ((lane >> 3) & 1) * 16;
    const float inv = 1.f / (fabsf(*nsc) + 1e-6f);

    #pragma unroll
    for (int it = 0; it < 8; it++) {
        int idx = it * 256 + tid;
        int r = idx >> 4, kc = (idx >> 3) & 1, c8 = idx & 7;
        uint32_t off = kc * 16384 + SWZ1((uint32_t)(r * 128 + c8 * 16));
        cp16(sb + PA + off, g_Xqf + (size_t)(row0 + r) * DD + kc * 64 + c8 * 8);
        cp16(sb + PB0 + off, g_Wqf + (size_t)r * DD + kc * 64 + c8 * 8);
    }
    CP_COMMIT();

    float acc[4][4][4];
    for (int h = 0; h < 8; h++) {
        if (h < 7) {
            stage_b(sb + (((h + 1) & 1) ? PB1 : PB0), g_Wqf + (h + 1) * (DD * DD), tid);
            CP_COMMIT();
            CP_WAIT1();
        } else {
            CP_WAIT0();
        }
        __syncthreads();

        head_mma(acc, sb, sb + ((h & 1) ? PB1 : PB0), a_row, a_cb, b_row, b_cb);

        const float* bias = Wq_b + h * DD;
        float bc[8], ks[8];
        #pragma unroll
        for (int nb = 0; nb < 4; nb++) {
            int c = wn * 32 + (nb >> 1) * 16 + (nb & 1) * 8 + 2 * (lane & 3);
            bc[nb * 2] = bias[c]; bc[nb * 2 + 1] = bias[c + 1];
            ks[nb * 2] = g_ksum[h * DD + c]; ks[nb * 2 + 1] = g_ksum[h * DD + c + 1];
        }
        // pass 1: s2/s4 partials
        #pragma unroll
        for (int rh = 0; rh < 8; rh++) {
            int mi = rh >> 1, half = rh & 1;
            int r = wm * 64 + mi * 16 + half * 8 + (lane >> 2);
            float s2 = 0.f, s4 = 0.f;
            #pragma unroll
            for (int nb = 0; nb < 4; nb++)
                #pragma unroll
                for (int e = 0; e < 2; e++) {
                    float x = acc[mi][nb][half * 2 + e] + bc[nb * 2 + e];
                    float y = (fmaxf(x, 0.f) + 1e-6f) * inv;
                    float q = y * y;
                    s2 += q; s4 += q * q;
                }
            s2 += __shfl_xor_sync(0xffffffffu, s2, 1);
            s2 += __shfl_xor_sync(0xffffffffu, s2, 2);
            s4 += __shfl_xor_sync(0xffffffffu, s4, 1);
            s4 += __shfl_xor_sync(0xffffffffu, s4, 2);
            if ((lane & 3) == 0) {
                red[r * 12 + wn * 2] = s2;
                red[r * 12 + wn * 2 + 1] = s4;
            }
        }
        __syncthreads();
        // pass 2: rsc, dot(phi, ksum) partials
        #pragma unroll
        for (int rh = 0; rh < 8; rh++) {
            int mi = rh >> 1, half = rh & 1;
            int r = wm * 64 + mi * 16 + half * 8 + (lane >> 2);
            float s2 = red[r * 12] + red[r * 12 + 2] + red[r * 12 + 4] + red[r * 12 + 6];
            float s4 = red[r * 12 + 1] + red[r * 12 + 3] + red[r * 12 + 5] + red[r * 12 + 7];
            float rsc = sqrtf(s2) / (sqrtf(s4) + 1e-8f);
            float dot = 0.f;
            #pragma unroll
            for (int nb = 0; nb < 4; nb++)
                #pragma unroll
                for (int e = 0; e < 2; e++) {
                    float x = acc[mi][nb][half * 2 + e] + bc[nb * 2 + e];
                    float y = (fmaxf(x, 0.f) + 1e-6f) * inv;
                    dot += rsc * y * y * ks[nb * 2 + e];
                }
            dot += __shfl_xor_sync(0xffffffffu, dot, 1);
            dot += __shfl_xor_sync(0xffffffffu, dot, 2);
            if ((lane & 3) == 0) red[r * 12 + 8 + wn] = dot;
        }
        __syncthreads();
        // pass 3: scale + store
        #pragma unroll
        for (int rh = 0; rh < 8; rh++) {
            int mi = rh >> 1, half = rh & 1;
            int r = wm * 64 + mi * 16 + half * 8 + (lane >> 2);
            float s2 = red[r * 12] + red[r * 12 + 2] + red[r * 12 + 4] + red[r * 12 + 6];
            float s4 = red[r * 12 + 1] + red[r * 12 + 3] + red[r * 12 + 5] + red[r * 12 + 7];
            float rsc = sqrtf(s2) / (sqrtf(s4) + 1e-8f);
            float dd = red[r * 12 + 8] + red[r * 12 + 9] + red[r * 12 + 10] + red[r * 12 + 11];
            float sc = rsc * QSCALE / (dd + 1e-6f);
            #pragma unroll
            for (int nb = 0; nb < 4; nb++) {
                int c = wn * 32 + (nb >> 1) * 16 + (nb & 1) * 8 + 2 * (lane & 3);
                float x0 = acc[mi][nb][half * 2] + bc[nb * 2];
                float x1 = acc[mi][nb][half * 2 + 1] + bc[nb * 2 + 1];
                float y0 = (fmaxf(x0, 0.f) + 1e-6f) * inv;
                float y1 = (fmaxf(x1, 0.f) + 1e-6f) * inv;
                *(uint32_t*)(g_Qf + (size_t)(row0 + r) * HD + h * DD + c) =
                    pack_h2(__float2half_rn(sc * y0 * y0),
                            __float2half_rn(sc * y1 * y1));
            }
        }
        __syncthreads();
    }
}

// ---------------- bf16 3-pass GEMM (vss only) ----------------
#define S_AH 0
#define S_AL 16384
#define S_BH 32768
#define S_BL 49152
#define MM_SMEM 65536

__global__ void __launch_bounds__(256, 2) mm_gemm_vss(
    const __nv_bfloat16* __restrict__ Ah, const __nv_bfloat16* __restrict__ Al,
    const __nv_bfloat16* __restrict__ Bh, const __nv_bfloat16* __restrict__ Bl,
    const float* __restrict__ bias, float* __restrict__ Cf) {
    extern __shared__ __align__(16) char smem[];
    const uint32_t sb = smem_u32(smem);
    const int tid = threadIdx.x;
    const int lane = tid & 31, warp = tid >> 5;
    const int wm = warp >> 2, wn = warp & 3;
    const int row0 = blockIdx.x * 128;

    float acc[4][4][4];
    #pragma unroll
    for (int i = 0; i < 4; i++)
        #pragma unroll
        for (int j = 0; j < 4; j++)
            #pragma unroll
            for (int e = 0; e < 4; e++) acc[i][j][e] = 0.f;

    const uint32_t a_row = wm * 64 + (lane & 15);
    const uint32_t a_cb  = (lane >> 4) * 16;
    const uint32_t b_row = wn * 32 + (lane & 7) + ((lane >> 4) & 1) * 8;
    const uint32_t b_cb  = ((lane >> 3) & 1) * 16;

    #pragma unroll
    for (int kc = 0; kc < 2; kc++) {
        #pragma unroll
        for (int it = 0; it < 4; it++) {
            int idx = it * 256 + tid;
            int r = idx >> 3, c8 = idx & 7;
            size_t ga = (size_t)(row0 + r) * DD + kc * 64 + c8 * 8;
            size_t gb = (size_t)r * DD + kc * 64 + c8 * 8;
            uint32_t off = SWZ1((uint32_t)(r * 128 + c8 * 16));
            cp16(sb + S_AH + off, Ah + ga);
            cp16(sb + S_AL + off, Al + ga);
            cp16(sb + S_BH + off, Bh + gb);
            cp16(sb + S_BL + off, Bl + gb);
        }
        CP_COMMIT();
        CP_WAIT0();
        __syncthreads();

        #pragma unroll
        for (int k = 0; k < 4; k++) {
            const uint32_t kb = k * 32;
            uint32_t ah[4][4], al[4][4], b[2][4];
            #pragma unroll
            for (int mi = 0; mi < 4; mi++) {
                uint32_t ra = SWZ1((a_row + mi * 16) * 128 + kb + a_cb);
                ldsm_x4(ah[mi][0], ah[mi][1], ah[mi][2], ah[mi][3], sb + S_AH + ra);
                ldsm_x4(al[mi][0], al[mi][1], al[mi][2], al[mi][3], sb + S_AL + ra);
            }
            #pragma unroll
            for (int nj = 0; nj < 2; nj++)
                ldsm_x4(b[nj][0], b[nj][1], b[nj][2], b[nj][3],
                        sb + S_BH + SWZ1((b_row + nj * 16) * 128 + kb + b_cb));
            #pragma unroll
            for (int mi = 0; mi < 4; mi++)
                #pragma unroll
                for (int nb = 0; nb < 4; nb++) {
                    mma_bf16(acc[mi][nb], ah[mi][0], ah[mi][1], ah[mi][2], ah[mi][3],
                             b[nb >> 1][(nb & 1) * 2], b[nb >> 1][(nb & 1) * 2 + 1]);
                    mma_bf16(acc[mi][nb], al[mi][0], al[mi][1], al[mi][2], al[mi][3],
                             b[nb >> 1][(nb & 1) * 2], b[nb >> 1][(nb & 1) * 2 + 1]);
                }
            #pragma unroll
            for (int nj = 0; nj < 2; nj++)
                ldsm_x4(b[nj][0], b[nj][1], b[nj][2], b[nj][3],
                        sb + S_BL + SWZ1((b_row + nj * 16) * 128 + kb + b_cb));
            #pragma unroll
            for (int mi = 0; mi < 4; mi++)
                #pragma unroll
                for (int nb = 0; nb < 4; nb++)
                    mma_bf16(acc[mi][nb], ah[mi][0], ah[mi][1], ah[mi][2], ah[mi][3],
                             b[nb >> 1][(nb & 1) * 2], b[nb >> 1][(nb & 1) * 2 + 1]);
        }
        __syncthreads();
    }

    const int rr = wm * 64 + (lane >> 2);
    const int cc = wn * 32 + 2 * (lane & 3);
    #pragma unroll
    for (int mi = 0; mi < 4; mi++)
        #pragma unroll
        for (int nb = 0; nb < 4; nb++) {
            int r = rr + mi * 16;
            int c = cc + (nb >> 1) * 16 + (nb & 1) * 8;
            float b0 = bias[c], b1 = bias[c + 1];
            float2 v0 = { acc[mi][nb][0] + b0, acc[mi][nb][1] + b1 };
            float2 v1 = { acc[mi][nb][2] + b0, acc[mi][nb][3] + b1 };
            *(float2*)(Cf + (size_t)(row0 + r) * DD + c) = v0;
            *(float2*)(Cf + (size_t)(row0 + r + 8) * DD + c) = v1;
        }
}

// ---------------- ktv via fp16 1-pass mma ----------------
#define T_P 0
#define T_V 16384
#define KTV_SMEM 32768

__global__ void __launch_bounds__(256, 2) ktv_mma() {
    extern __shared__ __align__(16) char smem[];
    const uint32_t sb = smem_u32(smem);
    const int h = blockIdx.x;
    const int chunk = blockIdx.y;
    const int tid = threadIdx.x;
    const int lane = tid & 31, warp = tid >> 5;
    const int wm = warp >> 2, wn = warp & 3;
    const int n0 = chunk * (NR / KC2);

    float acc[4][4][4];
    #pragma unroll
    for (int i = 0; i < 4; i++)
        #pragma unroll
        for (int j = 0; j < 4; j++)
            #pragma unroll
            for (int e = 0; e < 4; e++) acc[i][j][e] = 0.f;
    float ks = 0.f;

    const uint32_t a_kr = (lane & 7) + ((lane >> 4) & 1) * 8;
    const uint32_t a_cl = wm * 64 + ((lane >> 3) & 1) * 8;
    const uint32_t b_kr = (lane & 7) + ((lane >> 3) & 1) * 8;
    const uint32_t b_cl = wn * 32 + ((lane >> 4) & 1) * 8;

    for (int s = 0; s < (NR / KC2) / 64; s++) {
        const int nb = n0 + s * 64;
        #pragma unroll
        for (int it = 0; it < 4; it++) {
            int idx = it * 256 + tid;
            int r = idx >> 4, c16 = idx & 15;
            size_t gb = (size_t)(nb + r) * HD + h * DD + c16 * 8;
            uint32_t off = SWZ((uint32_t)(r * 256 + c16 * 16));
            cp16(sb + T_P + off, g_Kf + gb);
            cp16(sb + T_V + off, g_Vf + gb);
        }
        CP_COMMIT();
        CP_WAIT0();
        __syncthreads();

        #pragma unroll
        for (int kk = 0; kk < 4; kk++) {
            uint32_t a[4][4], b[2][4];
            #pragma unroll
            for (int nj = 0; nj < 2; nj++)
                ldsm_x4_t(b[nj][0], b[nj][1], b[nj][2], b[nj][3],
                          sb + T_V + SWZ((kk * 16 + b_kr) * 256 + (b_cl + nj * 16) * 2));
            #pragma unroll
            for (int mi = 0; mi < 4; mi++)
                ldsm_x4_t(a[mi][0], a[mi][1], a[mi][2], a[mi][3],
                          sb + T_P + SWZ((kk * 16 + a_kr) * 256 + (a_cl + mi * 16) * 2));
            #pragma unroll
            for (int mi = 0; mi < 4; mi++)
                #pragma unroll
                for (int nbt = 0; nbt < 4; nbt++)
                    mma_f16(acc[mi][nbt], a[mi][0], a[mi][1], a[mi][2], a[mi][3],
                            b[nbt >> 1][(nbt & 1) * 2], b[nbt >> 1][(nbt & 1) * 2 + 1]);
        }
        if (tid < 128) {
            #pragma unroll 4
            for (int r = 0; r < 64; r++) {
                uint32_t off = SWZ((uint32_t)(r * 256 + tid * 2));
                ks += __half2float(*(const __half*)(smem + T_P + off));
            }
        }
        __syncthreads();
    }

    float* outp = g_ktvp + ((size_t)chunk * NH + h) * (DD * DD);
    const int rr = wm * 64 + (lane >> 2);
    const int cc = wn * 32 + 2 * (lane & 3);
    #pragma unroll
    for (int mi = 0; mi < 4; mi++)
        #pragma unroll
        for (int nbt = 0; nbt < 4; nbt++) {
            int r = rr + mi * 16;
            int c = cc + (nbt >> 1) * 16 + (nbt & 1) * 8;
            *(float2*)&outp[r * DD + c]       = *(float2*)&acc[mi][nbt][0];
            *(float2*)&outp[(r + 8) * DD + c] = *(float2*)&acc[mi][nbt][2];
        }
    if (tid < 128) g_ksump[(chunk * NH + h) * DD + tid] = ks;
}

__global__ void ktv_reduce_kernel() {
    int idx = blockIdx.x * blockDim.x + threadIdx.x;
    if (idx < NH * DD * DD) {
        float s = 0.f;
        #pragma unroll 8
        for (int c = 0; c < KC2; c++) s += g_ktvp[(size_t)c * NH * DD * DD + idx];
        int h = idx >> 14, m = (idx >> 7) & 127, d = idx & 127;
        g_ktvTf[(h << 14) + (d << 7) + m] = __float2half_rn(s);
    }
    if (idx < NH * DD) {
        float s = 0.f;
        #pragma unroll 8
        for (int c = 0; c < KC2; c++) s += g_ksump[c * NH * DD + idx];
        g_ksum[idx] = s;
    }
}

// ---------------- fused numerator + combine (fp16 1-pass): out[n][129] ----------------
#define A_A 0
#define A_B 16384
#define C_LD 132
#define AT_SMEM (128 * C_LD * 4)   // 67584

__global__ void __launch_bounds__(256, 2) attn_out(const float* __restrict__ att,
                                                   float* __restrict__ out) {
    extern __shared__ __align__(16) char smem[];
    const uint32_t sb = smem_u32(smem);
    float* Cs = (float*)smem;
    const int tid = threadIdx.x;
    const int lane = tid & 31, warp = tid >> 5;
    const int wm = warp >> 2, wn = warp & 3;
    const int row0 = blockIdx.x * 128;

    float acc[4][4][4];
    #pragma unroll
    for (int i = 0; i < 4; i++)
        #pragma unroll
        for (int j = 0; j < 4; j++)
            #pragma unroll
            for (int e = 0; e < 4; e++) acc[i][j][e] = 0.f;

    const uint32_t a_row = wm * 64 + (lane & 15);
    const uint32_t a_cb  = (lane >> 4) * 16;
    const uint32_t b_row = wn * 32 + (lane & 7) + ((lane >> 4) & 1) * 8;
    const uint32_t b_cb  = ((lane >> 3) & 1) * 16;

    for (int kc = 0; kc < 16; kc++) {
        const int h = kc >> 1;
        const __half* B = g_ktvTf + h * (DD * DD) + (kc & 1) * 64;
        #pragma unroll
        for (int it = 0; it < 4; it++) {
            int idx = it * 256 + tid;
            int r = idx >> 3, c8 = idx & 7;
            size_t ga = (size_t)(row0 + r) * HD + kc * 64 + c8 * 8;
            size_t gb = (size_t)r * DD + c8 * 8;
            uint32_t off = SWZ1((uint32_t)(r * 128 + c8 * 16));
            cp16(sb + A_A + off, g_Qf + ga);
            cp16(sb + A_B + off, B + gb);
        }
        CP_COMMIT();
        CP_WAIT0();
        __syncthreads();

        #pragma unroll
        for (int k = 0; k < 4; k++) {
            const uint32_t kb = k * 32;
            uint32_t a[4][4], b[2][4];
            #pragma unroll
            for (int nj = 0; nj < 2; nj++)
                ldsm_x4(b[nj][0], b[nj][1], b[nj][2], b[nj][3],
                        sb + A_B + SWZ1((b_row + nj * 16) * 128 + kb + b_cb));
            #pragma unroll
            for (int mi = 0; mi < 4; mi++)
                ldsm_x4(a[mi][0], a[mi][1], a[mi][2], a[mi][3],
                        sb + A_A + SWZ1((a_row + mi * 16) * 128 + kb + a_cb));
            #pragma unroll
            for (int mi = 0; mi < 4; mi++)
                #pragma unroll
                for (int nb = 0; nb < 4; nb++)
                    mma_f16(acc[mi][nb], a[mi][0], a[mi][1], a[mi][2], a[mi][3],
                            b[nb >> 1][(nb & 1) * 2], b[nb >> 1][(nb & 1) * 2 + 1]);
        }
        __syncthreads();
    }

    {
        const int rr = wm * 64 + (lane >> 2);
        const int cc = wn * 32 + 2 * (lane & 3);
        #pragma unroll
        for (int mi = 0; mi < 4; mi++)
            #pragma unroll
            for (int nb = 0; nb < 4; nb++) {
                int r = rr + mi * 16;
                int c = cc + (nb >> 1) * 16 + (nb & 1) * 8;
                *(float2*)&Cs[r * C_LD + c]       = *(float2*)&acc[mi][nb][0];
                *(float2*)&Cs[(r + 8) * C_LD + c] = *(float2*)&acc[mi][nb][2];
            }
    }
    __syncthreads();
    #pragma unroll 2
    for (int i = 0; i < 16; i++) {
        int r = warp * 16 + i;
        int n = row0 + r;
        float4 x = *(float4*)&Cs[r * C_LD + lane * 4];
        float4 a4 = *(const float4*)(att + (size_t)n * DD + lane * 4);
        float v0 = x.x * OSCALE + a4.x;
        float v1 = x.y * OSCALE + a4.y;
        float v2 = x.z * OSCALE + a4.z;
        float v3 = x.w * OSCALE + a4.w;
        float ssum = v0 * v0 + v1 * v1 + v2 * v2 + v3 * v3;
        #pragma unroll
        for (int off = 16; off; off >>= 1) ssum += __shfl_xor_sync(0xffffffffu, ssum, off);
        float t = sqrtf(ssum + 1.0f);
        float* op = out + (size_t)n * 129;
        if (lane == 0) op[0] = t;
        op[1 + lane * 4 + 0] = v0;
        op[1 + lane * 4 + 1] = v1;
        op[1 + lane * 4 + 2] = v2;
        op[1 + lane * 4 + 3] = v3;
    }
}

// ---------------- launch ----------------
extern "C" void kernel_launch(void* const* d_in, const int* in_sizes, int n_in,
                              void* d_out, int out_size) {
    const float* xq   = (const float*)d_in[0];
    const float* xs   = (const float*)d_in[1];
    const float* Wq_w = (const float*)d_in[2];
    const float* Wq_b = (const float*)d_in[3];
    const float* Wk_w = (const float*)d_in[4];
    const float* Wk_b = (const float*)d_in[5];
    const float* Wv_w = (const float*)d_in[6];
    const float* Wv_b = (const float*)d_in[7];
    const float* vmw  = (const float*)d_in[8];
    const float* vmb  = (const float*)d_in[9];
    const float* nsc  = (const float*)d_in[10];
    float* out = (float*)d_out;

    float *pcfuse, *patt;
    __nv_bfloat16 *pWfh, *pWfl, *pXsh, *pXsl;
    cudaGetSymbolAddress((void**)&pcfuse, g_cfuse);
    cudaGetSymbolAddress((void**)&patt, g_att);
    cudaGetSymbolAddress((void**)&pWfh, g_WfTh);
    cudaGetSymbolAddress((void**)&pWfl, g_WfTl);
    cudaGetSymbolAddress((void**)&pXsh, g_Xsh);
    cudaGetSymbolAddress((void**)&pXsl, g_Xsl);

    cudaFuncSetAttribute(kv_proj, cudaFuncAttributeMaxDynamicSharedMemorySize, HP_SMEM);
    cudaFuncSetAttribute(q_proj, cudaFuncAttributeMaxDynamicSharedMemorySize, HP_SMEM);
    cudaFuncSetAttribute(mm_gemm_vss, cudaFuncAttributeMaxDynamicSharedMemorySize, MM_SMEM);
    cudaFuncSetAttribute(ktv_mma, cudaFuncAttributeMaxDynamicSharedMemorySize, KTV_SMEM);
    cudaFuncSetAttribute(attn_out, cudaFuncAttributeMaxDynamicSharedMemorySize, AT_SMEM);

    split_x_kernel<<<(NR * DD / 4 + 255) / 256, 256>>>(xs, xq);
    prep_kernel<<<(3 * 131072 + DD * DD + 255) / 256, 256>>>(Wq_w, Wk_w, Wv_w);
    wfuse_kernel<<<(DD * DD + 255) / 256, 256>>>(Wv_b, vmw, vmb);

    // K + V projections, head-looped, fused phi for K
    kv_proj<<<NR / 128, 256, HP_SMEM>>>(Wk_b, Wv_b, nsc);
    // ktv + ksum (fp16 1-pass)
    ktv_mma<<<dim3(NH, KC2), 256, KTV_SMEM>>>();
    ktv_reduce_kernel<<<(NH * DD * DD + 255) / 256, 256>>>();
    // fused vss: xs @ WfuseT -> att (bf16 3-pass)
    mm_gemm_vss<<<dim3(NR / 128, 1), 256, MM_SMEM>>>(pXsh, pXsl, pWfh, pWfl, pcfuse, patt);
    // Q projection + phi + dinv*2^20, head-looped
    q_proj<<<NR / 128, 256, HP_SMEM>>>(Wq_b, nsc);
    // fused numerator + combine + time coordinate -> out [NR][129]
    attn_out<<<NR / 128, 256, AT_SMEM>>>(patt, out);
}

// round 12
// speedup vs baseline: 2.3313x; 1.0756x over previous
#include <cuda_runtime.h>
#include <cuda_fp16.h>
#include <cstdint>
#include <math.h>

#define NR 32768
#define NH 8
#define DD 128
#define HD 1024     // NH * DD
#define KC2 64      // split-K chunks for ktv (512 rows each)
#define QSCALE 1048576.f          // 2^20 pre-scale for Q*dinv (fp16 range guard)
#define OSCALE (0.125f / 1048576.f)

// ---------------- scratch (static device memory; no allocations) ----------------
__device__ __half g_Wqf[DD * HD], g_Wkf[DD * HD], g_Wvf[DD * HD];  // fp16 single, K-major
__device__ float g_Wvm[DD * DD];
__device__ __half g_WfTf[DD * DD];                                 // fused vss weight fp16 [o][i]
__device__ float g_cfuse[DD];
__device__ __half g_Xf[(size_t)NR * DD];                           // xs fp16 single
__device__ __half g_Xqf[(size_t)NR * DD];                          // xq fp16 single
__device__ __half g_Kf[(size_t)NR * HD];                           // phi_ks fp16 single
__device__ __half g_Vf[(size_t)NR * HD];                           // v fp16 single
__device__ __half g_Qf[(size_t)NR * HD];                           // Q*dinv*2^20 single
__device__ __half g_ktvTf[NH * DD * DD];                           // [h][d][m] fp16
__device__ float g_ksum[NH * DD];
__device__ float g_ktvp[(size_t)KC2 * NH * DD * DD];
__device__ float g_ksump[KC2 * NH * DD];

// ---------------- helpers ----------------
__device__ __forceinline__ uint32_t smem_u32(const void* p) {
    uint32_t a;
    asm("{ .reg .u64 t; cvta.to.shared.u64 t, %1; cvt.u32.u64 %0, t; }" : "=r"(a) : "l"(p));
    return a;
}
__device__ __forceinline__ uint32_t pack_h2(__half a, __half b) {
    __half2 t; t.x = a; t.y = b;
    return *reinterpret_cast<uint32_t*>(&t);
}
#define SWZ(o)  ((o) ^ ((((o) >> 8) & 7) << 4))
#define SWZ1(o) ((o) ^ ((((o) >> 7) & 7) << 4))

__device__ __forceinline__ void ldsm_x4(uint32_t& r0, uint32_t& r1, uint32_t& r2,
                                        uint32_t& r3, uint32_t addr) {
    asm volatile("ldmatrix.sync.aligned.m8n8.x4.shared.b16 {%0,%1,%2,%3}, [%4];"
                 : "=r"(r0), "=r"(r1), "=r"(r2), "=r"(r3) : "r"(addr));
}
__device__ __forceinline__ void ldsm_x4_t(uint32_t& r0, uint32_t& r1, uint32_t& r2,
                                          uint32_t& r3, uint32_t addr) {
    asm volatile("ldmatrix.sync.aligned.m8n8.x4.trans.shared.b16 {%0,%1,%2,%3}, [%4];"
                 : "=r"(r0), "=r"(r1), "=r"(r2), "=r"(r3) : "r"(addr));
}
__device__ __forceinline__ void mma_f16(float* c, uint32_t a0, uint32_t a1,
                                        uint32_t a2, uint32_t a3,
                                        uint32_t b0, uint32_t b1) {
    asm volatile("mma.sync.aligned.m16n8k16.row.col.f32.f16.f16.f32 "
                 "{%0,%1,%2,%3}, {%4,%5,%6,%7}, {%8,%9}, {%0,%1,%2,%3};"
                 : "+f"(c[0]), "+f"(c[1]), "+f"(c[2]), "+f"(c[3])
                 : "r"(a0), "r"(a1), "r"(a2), "r"(a3), "r"(b0), "r"(b1));
}
__device__ __forceinline__ void cp16(uint32_t saddr, const void* g) {
    asm volatile("cp.async.cg.shared.global [%0], [%1], 16;" :: "r"(saddr), "l"(g));
}
#define CP_COMMIT() asm volatile("cp.async.commit_group;" ::: "memory")
#define CP_WAIT0()  asm volatile("cp.async.wait_group 0;" ::: "memory")
#define CP_WAIT1()  asm volatile("cp.async.wait_group 1;" ::: "memory")

// ---------------- input convert: fp32 -> fp16 singles ----------------
__global__ void split_x_kernel(const float* __restrict__ xs, const float* __restrict__ xq) {
    int idx = blockIdx.x * blockDim.x + threadIdx.x;
    if (idx >= NR * DD / 4) return;
    float4 s = *(const float4*)(xs + (size_t)idx * 4);
    float4 q = *(const float4*)(xq + (size_t)idx * 4);
    uint2 sv = { pack_h2(__float2half_rn(s.x), __float2half_rn(s.y)),
                 pack_h2(__float2half_rn(s.z), __float2half_rn(s.w)) };
    uint2 qv = { pack_h2(__float2half_rn(q.x), __float2half_rn(q.y)),
                 pack_h2(__float2half_rn(q.z), __float2half_rn(q.w)) };
    *(uint2*)(g_Xf + (size_t)idx * 4) = sv;
    *(uint2*)(g_Xqf + (size_t)idx * 4) = qv;
}

// ---------------- weight prep ----------------
__global__ void prep_kernel(const float* __restrict__ Wq,
                            const float* __restrict__ Wk,
                            const float* __restrict__ Wv) {
    int idx = blockIdx.x * blockDim.x + threadIdx.x;
    if (idx < 3 * 131072) {
        int which = idx / 131072;
        int e = idx % 131072;
        if (which == 0)      g_Wqf[e] = __float2half_rn(Wq[e]);
        else if (which == 1) g_Wkf[e] = __float2half_rn(Wk[e]);
        else                 g_Wvf[e] = __float2half_rn(Wv[e]);
    } else if (idx < 3 * 131072 + DD * DD) {
        int e = idx - 3 * 131072;
        int i = e & 127, d = e >> 7;
        float s = 0.f;
        #pragma unroll
        for (int h = 0; h < NH; h++) s += Wv[((size_t)(h * DD + d)) * DD + i];
        g_Wvm[d * DD + i] = s * 0.125f;
    }
}

__global__ void wfuse_kernel(const float* __restrict__ Wv_b,
                             const float* __restrict__ vmw,
                             const float* __restrict__ vmb) {
    int idx = blockIdx.x * blockDim.x + threadIdx.x;
    if (idx >= DD * DD) return;
    int o = idx & 127, i = idx >> 7;
    float acc = 0.f;
    for (int d = 0; d < DD; d++) acc += g_Wvm[d * DD + i] * vmw[o * DD + d];
    g_WfTf[o * DD + i] = __float2half_rn(acc);
    if (idx < DD) {
        float c = 0.f;
        for (int d = 0; d < DD; d++) {
            float bm = 0.f;
            #pragma unroll
            for (int hh = 0; hh < NH; hh++) bm += Wv_b[hh * DD + d];
            c += 0.125f * bm * vmw[idx * DD + d];
        }
        g_cfuse[idx] = c + vmb[idx];
    }
}

// ---------------- head-looped projection kernels ----------------
#define PA   0
#define PB0  32768
#define PB1  65536
#define PRED 98304
#define HP_SMEM (98304 + 128 * 12 * 4)   // 104448

__device__ __forceinline__ void head_mma(float acc[4][4][4], uint32_t sb,
                                         uint32_t bbuf, uint32_t a_row, uint32_t a_cb,
                                         uint32_t b_row, uint32_t b_cb) {
    #pragma unroll
    for (int i = 0; i < 4; i++)
        #pragma unroll
        for (int j = 0; j < 4; j++)
            #pragma unroll
            for (int e = 0; e < 4; e++) acc[i][j][e] = 0.f;
    #pragma unroll
    for (int kc = 0; kc < 2; kc++) {
        #pragma unroll
        for (int k = 0; k < 4; k++) {
            const uint32_t kb = k * 32;
            uint32_t a[4][4], b[2][4];
            #pragma unroll
            for (int nj = 0; nj < 2; nj++)
                ldsm_x4(b[nj][0], b[nj][1], b[nj][2], b[nj][3],
                        bbuf + kc * 16384 + SWZ1((b_row + nj * 16) * 128 + kb + b_cb));
            #pragma unroll
            for (int mi = 0; mi < 4; mi++)
                ldsm_x4(a[mi][0], a[mi][1], a[mi][2], a[mi][3],
                        sb + PA + kc * 16384 + SWZ1((a_row + mi * 16) * 128 + kb + a_cb));
            #pragma unroll
            for (int mi = 0; mi < 4; mi++)
                #pragma unroll
                for (int nb = 0; nb < 4; nb++)
                    mma_f16(acc[mi][nb], a[mi][0], a[mi][1], a[mi][2], a[mi][3],
                            b[nb >> 1][(nb & 1) * 2], b[nb >> 1][(nb & 1) * 2 + 1]);
        }
    }
}

__device__ __forceinline__ void stage_b(uint32_t dst, const __half* src, int tid) {
    #pragma unroll
    for (int it = 0; it < 8; it++) {
        int idx = it * 256 + tid;
        int r = idx >> 4, kc = (idx >> 3) & 1, c8 = idx & 7;
        uint32_t off = kc * 16384 + SWZ1((uint32_t)(r * 128 + c8 * 16));
        cp16(dst + off, src + (size_t)r * DD + kc * 64 + c8 * 8);
    }
}

// KV: j=0..15 alternating Wk (phi epilogue) / Wv (direct epilogue)
__global__ void __launch_bounds__(256, 2) kv_proj(
    const float* __restrict__ Wk_b, const float* __restrict__ Wv_b,
    const float* __restrict__ nsc) {
    extern __shared__ __align__(16) char smem[];
    const uint32_t sb = smem_u32(smem);
    float* red = (float*)(smem + PRED);
    const int tid = threadIdx.x;
    const int lane = tid & 31, warp = tid >> 5;
    const int wm = warp >> 2, wn = warp & 3;
    const int row0 = blockIdx.x * 128;

    const uint32_t a_row = wm * 64 + (lane & 15);
    const uint32_t a_cb  = (lane >> 4) * 16;
    const uint32_t b_row = wn * 32 + (lane & 7) + ((lane >> 4) & 1) * 8;
    const uint32_t b_cb  = ((lane >> 3) & 1) * 16;
    const float inv = 1.f / (fabsf(*nsc) + 1e-6f);

    #pragma unroll
    for (int it = 0; it < 8; it++) {
        int idx = it * 256 + tid;
        int r = idx >> 4, kc = (idx >> 3) & 1, c8 = idx & 7;
        uint32_t off = kc * 16384 + SWZ1((uint32_t)(r * 128 + c8 * 16));
        cp16(sb + PA + off, g_Xf + (size_t)(row0 + r) * DD + kc * 64 + c8 * 8);
        cp16(sb + PB0 + off, g_Wkf + (size_t)r * DD + kc * 64 + c8 * 8);
    }
    CP_COMMIT();

    float acc[4][4][4];
    for (int j = 0; j < 16; j++) {
        const int h = j >> 1;
        if (j < 15) {
            int jn = j + 1;
            const __half* src = (jn & 1) ? g_Wvf + (jn >> 1) * (DD * DD)
                                         : g_Wkf + (jn >> 1) * (DD * DD);
            stage_b(sb + ((jn & 1) ? PB1 : PB0), src, tid);
            CP_COMMIT();
            CP_WAIT1();
        } else {
            CP_WAIT0();
        }
        __syncthreads();

        head_mma(acc, sb, sb + ((j & 1) ? PB1 : PB0), a_row, a_cb, b_row, b_cb);

        if ((j & 1) == 0) {
            // phi epilogue (K head h)
            const float* bias = Wk_b + h * DD;
            float bc[8];
            #pragma unroll
            for (int nb = 0; nb < 4; nb++) {
                int c = wn * 32 + (nb >> 1) * 16 + (nb & 1) * 8 + 2 * (lane & 3);
                bc[nb * 2] = bias[c]; bc[nb * 2 + 1] = bias[c + 1];
            }
            #pragma unroll
            for (int rh = 0; rh < 8; rh++) {
                int mi = rh >> 1, half = rh & 1;
                int r = wm * 64 + mi * 16 + half * 8 + (lane >> 2);
                float s2 = 0.f, s4 = 0.f;
                #pragma unroll
                for (int nb = 0; nb < 4; nb++)
                    #pragma unroll
                    for (int e = 0; e < 2; e++) {
                        float x = acc[mi][nb][half * 2 + e] + bc[nb * 2 + e];
                        float y = (fmaxf(x, 0.f) + 1e-6f) * inv;
                        float q = y * y;
                        s2 += q; s4 += q * q;
                    }
                s2 += __shfl_xor_sync(0xffffffffu, s2, 1);
                s2 += __shfl_xor_sync(0xffffffffu, s2, 2);
                s4 += __shfl_xor_sync(0xffffffffu, s4, 1);
                s4 += __shfl_xor_sync(0xffffffffu, s4, 2);
                if ((lane & 3) == 0) {
                    red[r * 12 + wn * 2] = s2;
                    red[r * 12 + wn * 2 + 1] = s4;
                }
            }
            __syncthreads();
            #pragma unroll
            for (int rh = 0; rh < 8; rh++) {
                int mi = rh >> 1, half = rh & 1;
                int r = wm * 64 + mi * 16 + half * 8 + (lane >> 2);
                float s2 = red[r * 12] + red[r * 12 + 2] + red[r * 12 + 4] + red[r * 12 + 6];
                float s4 = red[r * 12 + 1] + red[r * 12 + 3] + red[r * 12 + 5] + red[r * 12 + 7];
                float rsc = sqrtf(s2) / (sqrtf(s4) + 1e-8f);
                #pragma unroll
                for (int nb = 0; nb < 4; nb++) {
                    int c = wn * 32 + (nb >> 1) * 16 + (nb & 1) * 8 + 2 * (lane & 3);
                    float x0 = acc[mi][nb][half * 2] + bc[nb * 2];
                    float x1 = acc[mi][nb][half * 2 + 1] + bc[nb * 2 + 1];
                    float y0 = (fmaxf(x0, 0.f) + 1e-6f) * inv;
                    float y1 = (fmaxf(x1, 0.f) + 1e-6f) * inv;
                    *(uint32_t*)(g_Kf + (size_t)(row0 + r) * HD + h * DD + c) =
                        pack_h2(__float2half_rn(rsc * y0 * y0),
                                __float2half_rn(rsc * y1 * y1));
                }
            }
        } else {
            // direct epilogue (V head h)
            const float* bias = Wv_b + h * DD;
            #pragma unroll
            for (int nb = 0; nb < 4; nb++) {
                int c = wn * 32 + (nb >> 1) * 16 + (nb & 1) * 8 + 2 * (lane & 3);
                float b0 = bias[c], b1 = bias[c + 1];
                #pragma unroll
                for (int mi = 0; mi < 4; mi++) {
                    int r = wm * 64 + mi * 16 + (lane >> 2);
                    *(uint32_t*)(g_Vf + (size_t)(row0 + r) * HD + h * DD + c) =
                        pack_h2(__float2half_rn(acc[mi][nb][0] + b0),
                                __float2half_rn(acc[mi][nb][1] + b1));
                    *(uint32_t*)(g_Vf + (size_t)(row0 + r + 8) * HD + h * DD + c) =
                        pack_h2(__float2half_rn(acc[mi][nb][2] + b0),
                                __float2half_rn(acc[mi][nb][3] + b1));
                }
            }
        }
        __syncthreads();
    }
}

// Q: heads 0..7, phi + dinv*QSCALE epilogue
__global__ void __launch_bounds__(256, 2) q_proj(
    const float* __restrict__ Wq_b, const float* __restrict__ nsc) {
    extern __shared__ __align__(16) char smem[];
    const uint32_t sb = smem_u32(smem);
    float* red = (float*)(smem + PRED);
    const int tid = threadIdx.x;
    const int lane = tid & 31, warp = tid >> 5;
    const int wm = warp >> 2, wn = warp & 3;
    const int row0 = blockIdx.x * 128;

    const uint32_t a_row = wm * 64 + (lane & 15);
    const uint32_t a_cb  = (lane >> 4) * 16;
    const uint32_t b_row = wn * 32 + (lane & 7) + ((lane >> 4) & 1) * 8;
    const uint32_t b_cb  = ((lane >> 3) & 1) * 16;
    const float inv = 1.f / (fabsf(*nsc) + 1e-6f);

    #pragma unroll
    for (int it = 0; it < 8; it++) {
        int idx = it * 256 + tid;
        int r = idx >> 4, kc = (idx >> 3) & 1, c8 = idx & 7;
        uint32_t off = kc * 16384 + SWZ1((uint32_t)(r * 128 + c8 * 16));
        cp16(sb + PA + off, g_Xqf + (size_t)(row0 + r) * DD + kc * 64 + c8 * 8);
        cp16(sb + PB0 + off, g_Wqf + (size_t)r * DD + kc * 64 + c8 * 8);
    }
    CP_COMMIT();

    float acc[4][4][4];
    for (int h = 0; h < 8; h++) {
        if (h < 7) {
            stage_b(sb + (((h + 1) & 1) ? PB1 : PB0), g_Wqf + (h + 1) * (DD * DD), tid);
            CP_COMMIT();
            CP_WAIT1();
        } else {
            CP_WAIT0();
        }
        __syncthreads();

        head_mma(acc, sb, sb + ((h & 1) ? PB1 : PB0), a_row, a_cb, b_row, b_cb);

        const float* bias = Wq_b + h * DD;
        float bc[8], ks[8];
        #pragma unroll
        for (int nb = 0; nb < 4; nb++) {
            int c = wn * 32 + (nb >> 1) * 16 + (nb & 1) * 8 + 2 * (lane & 3);
            bc[nb * 2] = bias[c]; bc[nb * 2 + 1] = bias[c + 1];
            ks[nb * 2] = g_ksum[h * DD + c]; ks[nb * 2 + 1] = g_ksum[h * DD + c + 1];
        }
        #pragma unroll
        for (int rh = 0; rh < 8; rh++) {
            int mi = rh >> 1, half = rh & 1;
            int r = wm * 64 + mi * 16 + half * 8 + (lane >> 2);
            float s2 = 0.f, s4 = 0.f;
            #pragma unroll
            for (int nb = 0; nb < 4; nb++)
                #pragma unroll
                for (int e = 0; e < 2; e++) {
                    float x = acc[mi][nb][half * 2 + e] + bc[nb * 2 + e];
                    float y = (fmaxf(x, 0.f) + 1e-6f) * inv;
                    float q = y * y;
                    s2 += q; s4 += q * q;
                }
            s2 += __shfl_xor_sync(0xffffffffu, s2, 1);
            s2 += __shfl_xor_sync(0xffffffffu, s2, 2);
            s4 += __shfl_xor_sync(0xffffffffu, s4, 1);
            s4 += __shfl_xor_sync(0xffffffffu, s4, 2);
            if ((lane & 3) == 0) {
                red[r * 12 + wn * 2] = s2;
                red[r * 12 + wn * 2 + 1] = s4;
            }
        }
        __syncthreads();
        #pragma unroll
        for (int rh = 0; rh < 8; rh++) {
            int mi = rh >> 1, half = rh & 1;
            int r = wm * 64 + mi * 16 + half * 8 + (lane >> 2);
            float s2 = red[r * 12] + red[r * 12 + 2] + red[r * 12 + 4] + red[r * 12 + 6];
            float s4 = red[r * 12 + 1] + red[r * 12 + 3] + red[r * 12 + 5] + red[r * 12 + 7];
            float rsc = sqrtf(s2) / (sqrtf(s4) + 1e-8f);
            float dot = 0.f;
            #pragma unroll
            for (int nb = 0; nb < 4; nb++)
                #pragma unroll
                for (int e = 0; e < 2; e++) {
                    float x = acc[mi][nb][half * 2 + e] + bc[nb * 2 + e];
                    float y = (fmaxf(x, 0.f) + 1e-6f) * inv;
                    dot += rsc * y * y * ks[nb * 2 + e];
                }
            dot += __shfl_xor_sync(0xffffffffu, dot, 1);
            dot += __shfl_xor_sync(0xffffffffu, dot, 2);
            if ((lane & 3) == 0) red[r * 12 + 8 + wn] = dot;
        }
        __syncthreads();
        #pragma unroll
        for (int rh = 0; rh < 8; rh++) {
            int mi = rh >> 1, half = rh & 1;
            int r = wm * 64 + mi * 16 + half * 8 + (lane >> 2);
            float s2 = red[r * 12] + red[r * 12 + 2] + red[r * 12 + 4] + red[r * 12 + 6];
            float s4 = red[r * 12 + 1] + red[r * 12 + 3] + red[r * 12 + 5] + red[r * 12 + 7];
            float rsc = sqrtf(s2) / (sqrtf(s4) + 1e-8f);
            float dd = red[r * 12 + 8] + red[r * 12 + 9] + red[r * 12 + 10] + red[r * 12 + 11];
            float sc = rsc * QSCALE / (dd + 1e-6f);
            #pragma unroll
            for (int nb = 0; nb < 4; nb++) {
                int c = wn * 32 + (nb >> 1) * 16 + (nb & 1) * 8 + 2 * (lane & 3);
                float x0 = acc[mi][nb][half * 2] + bc[nb * 2];
                float x1 = acc[mi][nb][half * 2 + 1] + bc[nb * 2 + 1];
                float y0 = (fmaxf(x0, 0.f) + 1e-6f) * inv;
                float y1 = (fmaxf(x1, 0.f) + 1e-6f) * inv;
                *(uint32_t*)(g_Qf + (size_t)(row0 + r) * HD + h * DD + c) =
                    pack_h2(__float2half_rn(sc * y0 * y0),
                            __float2half_rn(sc * y1 * y1));
            }
        }
        __syncthreads();
    }
}

// ---------------- ktv via fp16 1-pass mma ----------------
#define T_P 0
#define T_V 16384
#define KTV_SMEM 32768

__global__ void __launch_bounds__(256, 2) ktv_mma() {
    extern __shared__ __align__(16) char smem[];
    const uint32_t sb = smem_u32(smem);
    const int h = blockIdx.x;
    const int chunk = blockIdx.y;
    const int tid = threadIdx.x;
    const int lane = tid & 31, warp = tid >> 5;
    const int wm = warp >> 2, wn = warp & 3;
    const int n0 = chunk * (NR / KC2);

    float acc[4][4][4];
    #pragma unroll
    for (int i = 0; i < 4; i++)
        #pragma unroll
        for (int j = 0; j < 4; j++)
            #pragma unroll
            for (int e = 0; e < 4; e++) acc[i][j][e] = 0.f;
    float ks = 0.f;

    const uint32_t a_kr = (lane & 7) + ((lane >> 4) & 1) * 8;
    const uint32_t a_cl = wm * 64 + ((lane >> 3) & 1) * 8;
    const uint32_t b_kr = (lane & 7) + ((lane >> 3) & 1) * 8;
    const uint32_t b_cl = wn * 32 + ((lane >> 4) & 1) * 8;

    for (int s = 0; s < (NR / KC2) / 64; s++) {
        const int nb = n0 + s * 64;
        #pragma unroll
        for (int it = 0; it < 4; it++) {
            int idx = it * 256 + tid;
            int r = idx >> 4, c16 = idx & 15;
            size_t gb = (size_t)(nb + r) * HD + h * DD + c16 * 8;
            uint32_t off = SWZ((uint32_t)(r * 256 + c16 * 16));
            cp16(sb + T_P + off, g_Kf + gb);
            cp16(sb + T_V + off, g_Vf + gb);
        }
        CP_COMMIT();
        CP_WAIT0();
        __syncthreads();

        #pragma unroll
        for (int kk = 0; kk < 4; kk++) {
            uint32_t a[4][4], b[2][4];
            #pragma unroll
            for (int nj = 0; nj < 2; nj++)
                ldsm_x4_t(b[nj][0], b[nj][1], b[nj][2], b[nj][3],
                          sb + T_V + SWZ((kk * 16 + b_kr) * 256 + (b_cl + nj * 16) * 2));
            #pragma unroll
            for (int mi = 0; mi < 4; mi++)
                ldsm_x4_t(a[mi][0], a[mi][1], a[mi][2], a[mi][3],
                          sb + T_P + SWZ((kk * 16 + a_kr) * 256 + (a_cl + mi * 16) * 2));
            #pragma unroll
            for (int mi = 0; mi < 4; mi++)
                #pragma unroll
                for (int nbt = 0; nbt < 4; nbt++)
                    mma_f16(acc[mi][nbt], a[mi][0], a[mi][1], a[mi][2], a[mi][3],
                            b[nbt >> 1][(nbt & 1) * 2], b[nbt >> 1][(nbt & 1) * 2 + 1]);
        }
        if (tid < 128) {
            #pragma unroll 4
            for (int r = 0; r < 64; r++) {
                uint32_t off = SWZ((uint32_t)(r * 256 + tid * 2));
                ks += __half2float(*(const __half*)(smem + T_P + off));
            }
        }
        __syncthreads();
    }

    float* outp = g_ktvp + ((size_t)chunk * NH + h) * (DD * DD);
    const int rr = wm * 64 + (lane >> 2);
    const int cc = wn * 32 + 2 * (lane & 3);
    #pragma unroll
    for (int mi = 0; mi < 4; mi++)
        #pragma unroll
        for (int nbt = 0; nbt < 4; nbt++) {
            int r = rr + mi * 16;
            int c = cc + (nbt >> 1) * 16 + (nbt & 1) * 8;
            *(float2*)&outp[r * DD + c]       = *(float2*)&acc[mi][nbt][0];
            *(float2*)&outp[(r + 8) * DD + c] = *(float2*)&acc[mi][nbt][2];
        }
    if (tid < 128) g_ksump[(chunk * NH + h) * DD + tid] = ks;
}

__global__ void ktv_reduce_kernel() {
    int idx = blockIdx.x * blockDim.x + threadIdx.x;
    if (idx < NH * DD * DD) {
        float s = 0.f;
        #pragma unroll 8
        for (int c = 0; c < KC2; c++) s += g_ktvp[(size_t)c * NH * DD * DD + idx];
        int h = idx >> 14, m = (idx >> 7) & 127, d = idx & 127;
        g_ktvTf[(h << 14) + (d << 7) + m] = __float2half_rn(s);
    }
    if (idx < NH * DD) {
        float s = 0.f;
        #pragma unroll 8
        for (int c = 0; c < KC2; c++) s += g_ksump[c * NH * DD + idx];
        g_ksum[idx] = s;
    }
}

// ---------------- fused numerator + vss + combine: out[n][129] ----------------
#define A_A 0
#define A_B 16384
#define C_LD 132
#define AT_SMEM (128 * C_LD * 4)   // 67584

__global__ void __launch_bounds__(256, 2) attn_out(float* __restrict__ out) {
    extern __shared__ __align__(16) char smem[];
    const uint32_t sb = smem_u32(smem);
    float* Cs = (float*)smem;
    const int tid = threadIdx.x;
    const int lane = tid & 31, warp = tid >> 5;
    const int wm = warp >> 2, wn = warp & 3;
    const int row0 = blockIdx.x * 128;

    float acc[4][4][4];
    #pragma unroll
    for (int i = 0; i < 4; i++)
        #pragma unroll
        for (int j = 0; j < 4; j++)
            #pragma unroll
            for (int e = 0; e < 4; e++) acc[i][j][e] = 0.f;

    const uint32_t a_row = wm * 64 + (lane & 15);
    const uint32_t a_cb  = (lane >> 4) * 16;
    const uint32_t b_row = wn * 32 + (lane & 7) + ((lane >> 4) & 1) * 8;
    const uint32_t b_cb  = ((lane >> 3) & 1) * 16;

    // 18 k-chunks: 0..15 = Q @ ktvT (per-head), 16..17 = xs @ WfuseT (vss)
    for (int kc = 0; kc < 18; kc++) {
        const __half *Asrc, *Bsrc;
        int a_ld;
        if (kc < 16) {
            Asrc = g_Qf + (size_t)row0 * HD + kc * 64;
            a_ld = HD;
            Bsrc = g_ktvTf + (kc >> 1) * (DD * DD) + (kc & 1) * 64;
        } else {
            Asrc = g_Xf + (size_t)row0 * DD + (kc - 16) * 64;
            a_ld = DD;
            Bsrc = g_WfTf + (kc - 16) * 64;
        }
        #pragma unroll
        for (int it = 0; it < 4; it++) {
            int idx = it * 256 + tid;
            int r = idx >> 3, c8 = idx & 7;
            uint32_t off = SWZ1((uint32_t)(r * 128 + c8 * 16));
            cp16(sb + A_A + off, Asrc + (size_t)r * a_ld + c8 * 8);
            cp16(sb + A_B + off, Bsrc + (size_t)r * DD + c8 * 8);
        }
        CP_COMMIT();
        CP_WAIT0();
        __syncthreads();

        if (kc == 16) {
            // transition from numerator to vss: fold OSCALE into accumulators
            #pragma unroll
            for (int mi = 0; mi < 4; mi++)
                #pragma unroll
                for (int nb = 0; nb < 4; nb++)
                    #pragma unroll
                    for (int e = 0; e < 4; e++) acc[mi][nb][e] *= OSCALE;
        }

        #pragma unroll
        for (int k = 0; k < 4; k++) {
            const uint32_t kb = k * 32;
            uint32_t a[4][4], b[2][4];
            #pragma unroll
            for (int nj = 0; nj < 2; nj++)
                ldsm_x4(b[nj][0], b[nj][1], b[nj][2], b[nj][3],
                        sb + A_B + SWZ1((b_row + nj * 16) * 128 + kb + b_cb));
            #pragma unroll
            for (int mi = 0; mi < 4; mi++)
                ldsm_x4(a[mi][0], a[mi][1], a[mi][2], a[mi][3],
                        sb + A_A + SWZ1((a_row + mi * 16) * 128 + kb + a_cb));
            #pragma unroll
            for (int mi = 0; mi < 4; mi++)
                #pragma unroll
                for (int nb = 0; nb < 4; nb++)
                    mma_f16(acc[mi][nb], a[mi][0], a[mi][1], a[mi][2], a[mi][3],
                            b[nb >> 1][(nb & 1) * 2], b[nb >> 1][(nb & 1) * 2 + 1]);
        }
        __syncthreads();
    }

    // dump acc, final epilogue: + cfuse, time coordinate
    {
        const int rr = wm * 64 + (lane >> 2);
        const int cc = wn * 32 + 2 * (lane & 3);
        #pragma unroll
        for (int mi = 0; mi < 4; mi++)
            #pragma unroll
            for (int nb = 0; nb < 4; nb++) {
                int r = rr + mi * 16;
                int c = cc + (nb >> 1) * 16 + (nb & 1) * 8;
                *(float2*)&Cs[r * C_LD + c]       = *(float2*)&acc[mi][nb][0];
                *(float2*)&Cs[(r + 8) * C_LD + c] = *(float2*)&acc[mi][nb][2];
            }
    }
    __syncthreads();
    const float4 cf = *(const float4*)(g_cfuse + lane * 4);
    #pragma unroll 2
    for (int i = 0; i < 16; i++) {
        int r = warp * 16 + i;
        int n = row0 + r;
        float4 x = *(float4*)&Cs[r * C_LD + lane * 4];
        float v0 = x.x + cf.x;
        float v1 = x.y + cf.y;
        float v2 = x.z + cf.z;
        float v3 = x.w + cf.w;
        float ssum = v0 * v0 + v1 * v1 + v2 * v2 + v3 * v3;
        #pragma unroll
        for (int off = 16; off; off >>= 1) ssum += __shfl_xor_sync(0xffffffffu, ssum, off);
        float t = sqrtf(ssum + 1.0f);
        float* op = out + (size_t)n * 129;
        if (lane == 0) op[0] = t;
        op[1 + lane * 4 + 0] = v0;
        op[1 + lane * 4 + 1] = v1;
        op[1 + lane * 4 + 2] = v2;
        op[1 + lane * 4 + 3] = v3;
    }
}

// ---------------- launch ----------------
extern "C" void kernel_launch(void* const* d_in, const int* in_sizes, int n_in,
                              void* d_out, int out_size) {
    const float* xq   = (const float*)d_in[0];
    const float* xs   = (const float*)d_in[1];
    const float* Wq_w = (const float*)d_in[2];
    const float* Wq_b = (const float*)d_in[3];
    const float* Wk_w = (const float*)d_in[4];
    const float* Wk_b = (const float*)d_in[5];
    const float* Wv_w = (const float*)d_in[6];
    const float* Wv_b = (const float*)d_in[7];
    const float* vmw  = (const float*)d_in[8];
    const float* vmb  = (const float*)d_in[9];
    const float* nsc  = (const float*)d_in[10];
    float* out = (float*)d_out;

    cudaFuncSetAttribute(kv_proj, cudaFuncAttributeMaxDynamicSharedMemorySize, HP_SMEM);
    cudaFuncSetAttribute(q_proj, cudaFuncAttributeMaxDynamicSharedMemorySize, HP_SMEM);
    cudaFuncSetAttribute(ktv_mma, cudaFuncAttributeMaxDynamicSharedMemorySize, KTV_SMEM);
    cudaFuncSetAttribute(attn_out, cudaFuncAttributeMaxDynamicSharedMemorySize, AT_SMEM);

    split_x_kernel<<<(NR * DD / 4 + 255) / 256, 256>>>(xs, xq);
    prep_kernel<<<(3 * 131072 + DD * DD + 255) / 256, 256>>>(Wq_w, Wk_w, Wv_w);
    wfuse_kernel<<<(DD * DD + 255) / 256, 256>>>(Wv_b, vmw, vmb);

    // K + V projections, head-looped, fused phi for K
    kv_proj<<<NR / 128, 256, HP_SMEM>>>(Wk_b, Wv_b, nsc);
    // ktv + ksum (fp16 1-pass)
    ktv_mma<<<dim3(NH, KC2), 256, KTV_SMEM>>>();
    ktv_reduce_kernel<<<(NH * DD * DD + 255) / 256, 256>>>();
    // Q projection + phi + dinv*2^20, head-looped
    q_proj<<<NR / 128, 256, HP_SMEM>>>(Wq_b, nsc);
    // fused numerator + vss + combine + time coordinate -> out [NR][129]
    attn_out<<<NR / 128, 256, AT_SMEM>>>(out);
}